// round 9
// baseline (speedup 1.0000x reference)
#include <cuda_runtime.h>
#include <cuda_bf16.h>
#include <math.h>
#include <stdint.h>

#define BB   64
#define LL   4096
#define RC   64
#define SC   128
#define NBLK 30
#define P    132    // post_kernel fp32 staging pitch
#define PX   68     // pitch (words) for 64-pair split arrays (68 mod 32 == 4)
#define PG   36     // pitch (words) for 32-pair split arrays (36 mod 32 == 4)

// Static device scratch (allocation-free contract)
__device__ float g_h0[(size_t)BB * LL * RC];
__device__ float g_h1[(size_t)BB * LL * RC];
__device__ float g_skip[(size_t)BB * LL * SC];
__device__ float g_partial[(size_t)BB * 32 * SC];
// pre-split weights (bf16x2 hi/lo pair-words)
__device__ uint32_t g_wdh[NBLK * 8192], g_wdl[NBLK * 8192];   // conv  [o][64 pairs]
__device__ uint32_t g_wrh[NBLK * 2048], g_wrl[NBLK * 2048];   // res   [o][32 pairs]
__device__ uint32_t g_wsh[NBLK * 4096], g_wsl[NBLK * 4096];   // skip  [o][32 pairs]

// ---------------------------------------------------------------------------
__device__ __forceinline__ void bfsplit2(float v0, float v1, uint32_t& hi, uint32_t& lo) {
    __nv_bfloat16 h0 = __float2bfloat16_rn(v0);
    __nv_bfloat16 h1 = __float2bfloat16_rn(v1);
    float r0 = v0 - __bfloat162float(h0);
    float r1 = v1 - __bfloat162float(h1);
    __nv_bfloat16 l0 = __float2bfloat16_rn(r0);
    __nv_bfloat16 l1 = __float2bfloat16_rn(r1);
    hi = (uint32_t)__bfloat16_as_ushort(h0) | ((uint32_t)__bfloat16_as_ushort(h1) << 16);
    lo = (uint32_t)__bfloat16_as_ushort(l0) | ((uint32_t)__bfloat16_as_ushort(l1) << 16);
}
__device__ __forceinline__ void bfsplit1(float v, uint16_t& hi, uint16_t& lo) {
    __nv_bfloat16 h = __float2bfloat16_rn(v);
    float r = v - __bfloat162float(h);
    hi = __bfloat16_as_ushort(h);
    lo = __bfloat16_as_ushort(__float2bfloat16_rn(r));
}

__device__ __forceinline__ void mma_bf16(float* d, const uint32_t* a, const uint32_t* b) {
    asm volatile(
        "mma.sync.aligned.m16n8k16.row.col.f32.bf16.bf16.f32 "
        "{%0,%1,%2,%3}, {%4,%5,%6,%7}, {%8,%9}, {%0,%1,%2,%3};"
        : "+f"(d[0]), "+f"(d[1]), "+f"(d[2]), "+f"(d[3])
        : "r"(a[0]), "r"(a[1]), "r"(a[2]), "r"(a[3]), "r"(b[0]), "r"(b[1]));
}

__device__ __forceinline__ float fast_gate(float t, float s) {
    float th = 2.f * __fdividef(1.f, 1.f + __expf(-2.f * t)) - 1.f;
    float sg = __fdividef(1.f, 1.f + __expf(-s));
    return th * sg;
}

// ---------------------------------------------------------------------------
__global__ __launch_bounds__(256) void split_kernel(
    const float* __restrict__ wd, const float* __restrict__ wr,
    const float* __restrict__ ws)
{
    int id = blockIdx.x * 256 + threadIdx.x;
    if (id >= NBLK * 14336) return;
    int i = id / 14336, r = id % 14336;
    const float* src; uint32_t *dh, *dl; int off;
    if (r < 8192)       { src = wd + (size_t)i * 16384; off = r;        dh = g_wdh + i * 8192; dl = g_wdl + i * 8192; }
    else if (r < 10240) { src = wr + (size_t)i * 4096;  off = r - 8192; dh = g_wrh + i * 2048; dl = g_wrl + i * 2048; }
    else                { src = ws + (size_t)i * 8192;  off = r - 10240;dh = g_wsh + i * 4096; dl = g_wsl + i * 4096; }
    float2 v = *(const float2*)(src + 2 * off);
    uint32_t hi, lo; bfsplit2(v.x, v.y, hi, lo);
    dh[off] = hi; dl[off] = lo;
}

// ---------------------------------------------------------------------------
__global__ __launch_bounds__(256) void proj_kernel(
    const float* __restrict__ x, const float* __restrict__ w_in,
    const float* __restrict__ b_in, float* __restrict__ h)
{
    int idx = blockIdx.x * 256 + threadIdx.x;
    int oc = idx & 63;
    int l  = (idx >> 6) & (LL - 1);
    int b  = idx >> 18;
    float acc = b_in[oc];
#pragma unroll
    for (int c = 0; c < 8; ++c)
        acc += w_in[oc * 8 + c] * x[((size_t)(b * 8 + c)) * LL + l];
    h[(size_t)idx] = acc;
}

// ---------------------------------------------------------------------------
// One WaveNet block. 512 threads, 128 pos/CTA, 3 barriers.
// Conv warps own matching t/s rows -> register gate -> G in smem.
// Res/skip epilogues store fragments directly to global (sector-perfect).
// ---------------------------------------------------------------------------
__global__ __launch_bounds__(512, 1) void block_kernel(
    const float* __restrict__ h_in, float* __restrict__ h_out,
    float* __restrict__ skip,
    const uint32_t* __restrict__ wdh, const uint32_t* __restrict__ wdl,
    const float* __restrict__ bd,
    const uint32_t* __restrict__ wrh, const uint32_t* __restrict__ wrl,
    const float* __restrict__ br,
    const uint32_t* __restrict__ wsh, const uint32_t* __restrict__ wsl,
    const float* __restrict__ bs,
    int d, int first)
{
    extern __shared__ uint32_t smw[];
    uint32_t* s_xh = smw;                  // [128 pos][PX] X hi pairs (region A)
    uint32_t* s_xl = s_xh + 128 * PX;
    uint32_t* s_wh = s_xl + 128 * PX;      // [128 o][PX] conv W hi (region B)
    uint32_t* s_wl = s_wh + 128 * PX;
    // overlays after conv barrier:
    uint32_t* s_gh  = s_xh;                // [128 pos][PG] gated G hi (region A)
    uint32_t* s_gl  = s_xl;
    uint32_t* s_wrh = s_wh;                // region B: wr/ws splits
    uint32_t* s_wrl = s_wh + 2304;
    uint32_t* s_wsh = s_wh + 4608;
    uint32_t* s_wsl = s_wh + 9216;

    const int tid  = threadIdx.x;
    const int lane = tid & 31;
    const int w    = tid >> 5;      // warp 0..15
    const int lr   = lane >> 2;     // 0..7
    const int lc   = lane & 3;      // 0..3
    const int b    = blockIdx.y;
    const int l0   = blockIdx.x * 128;

    // ---- prefetch res/skip weights into registers (overlaps everything) ----
    uint4 p_wrh = ((const uint4*)wrh)[tid];
    uint4 p_wrl = ((const uint4*)wrl)[tid];
    uint4 p_wsh0 = ((const uint4*)wsh)[tid];
    uint4 p_wsh1 = ((const uint4*)wsh)[tid + 512];
    uint4 p_wsl0 = ((const uint4*)wsl)[tid];
    uint4 p_wsl1 = ((const uint4*)wsl)[tid + 512];

    // ---- stage X split: pair (k=2c: delayed, k=2c+1: current) ----
    {
        int c = tid & 63, p0 = tid >> 6;
        const float* hb = h_in + (size_t)b * LL * 64;
#pragma unroll
        for (int p = p0; p < 128; p += 8) {
            int l = l0 + p, ld = l - d;
            float cur = hb[(size_t)l * 64 + c];
            float del = (ld >= 0) ? hb[(size_t)ld * 64 + c] : 0.f;
            uint32_t hi, lo; bfsplit2(del, cur, hi, lo);
            s_xh[p * PX + c] = hi; s_xl[p * PX + c] = lo;
        }
    }
    // ---- stage conv W ----
    for (int e = tid; e < 2048; e += 512) {
        int o = e >> 4, q = e & 15;
        *(uint4*)&s_wh[o * PX + q * 4] = ((const uint4*)wdh)[e];
        *(uint4*)&s_wl[o * PX + q * 4] = ((const uint4*)wdl)[e];
    }
    __syncthreads();   // [1]

    // ================= conv GEMM =================
    // warp tile: rows {o0..o0+16} (t) and {64+o0..} (s), cols pos0..pos0+32
    const int o0   = (w & 3) * 16;
    const int pos0 = (w >> 2) * 32;
    float acc[2][4][4];
#pragma unroll
    for (int mt = 0; mt < 2; mt++)
#pragma unroll
        for (int nt = 0; nt < 4; nt++)
#pragma unroll
            for (int r = 0; r < 4; r++) acc[mt][nt][r] = 0.f;

#pragma unroll 1
    for (int ks = 0; ks < 8; ks++) {
        const int kp = ks * 8 + lc;
        uint32_t ah[2][4], al[2][4], bh[4][2], bl[4][2];
#pragma unroll
        for (int mt = 0; mt < 2; mt++) {
            int r0 = (mt * 64 + o0 + lr) * PX + kp;
            int r8 = r0 + 8 * PX;
            ah[mt][0] = s_wh[r0]; ah[mt][1] = s_wh[r8];
            ah[mt][2] = s_wh[r0 + 4]; ah[mt][3] = s_wh[r8 + 4];
            al[mt][0] = s_wl[r0]; al[mt][1] = s_wl[r8];
            al[mt][2] = s_wl[r0 + 4]; al[mt][3] = s_wl[r8 + 4];
        }
#pragma unroll
        for (int nt = 0; nt < 4; nt++) {
            int q = (pos0 + nt * 8 + lr) * PX + kp;
            bh[nt][0] = s_xh[q]; bh[nt][1] = s_xh[q + 4];
            bl[nt][0] = s_xl[q]; bl[nt][1] = s_xl[q + 4];
        }
#pragma unroll
        for (int mt = 0; mt < 2; mt++)
#pragma unroll
            for (int nt = 0; nt < 4; nt++) {
                mma_bf16(acc[mt][nt], ah[mt], bh[nt]);
                mma_bf16(acc[mt][nt], ah[mt], bl[nt]);
                mma_bf16(acc[mt][nt], al[mt], bh[nt]);
            }
    }
    __syncthreads();   // [2] X + conv W dead

    // ---- register gate -> G (u16 hi/lo into region A) ----
    {
        uint16_t* gh16 = (uint16_t*)s_gh;
        uint16_t* gl16 = (uint16_t*)s_gl;
        float bt[2] = {bd[o0 + lr], bd[o0 + lr + 8]};
        float bg[2] = {bd[64 + o0 + lr], bd[64 + o0 + lr + 8]};
#pragma unroll
        for (int nt = 0; nt < 4; nt++)
#pragma unroll
            for (int half = 0; half < 2; half++)
#pragma unroll
                for (int co = 0; co < 2; co++) {
                    int ri = half * 2 + co;
                    float t = acc[0][nt][ri] + bt[half];
                    float s = acc[1][nt][ri] + bg[half];
                    float g = fast_gate(t, s);
                    int c   = o0 + lr + half * 8;
                    int pos = pos0 + nt * 8 + 2 * lc + co;
                    uint16_t hi, lo; bfsplit1(g, hi, lo);
                    int wi = (pos * PG + (c >> 1)) * 2 + (c & 1);
                    gh16[wi] = hi; gl16[wi] = lo;
                }
    }
    // ---- store prefetched wr/ws into region B ----
    {
        int ow = tid >> 3, cw = (4 * tid) & 31;
        *(uint4*)&s_wrh[ow * PG + cw] = p_wrh;
        *(uint4*)&s_wrl[ow * PG + cw] = p_wrl;
        *(uint4*)&s_wsh[ow * PG + cw] = p_wsh0;
        *(uint4*)&s_wsh[(ow + 64) * PG + cw] = p_wsh1;
        *(uint4*)&s_wsl[ow * PG + cw] = p_wsl0;
        *(uint4*)&s_wsl[(ow + 64) * PG + cw] = p_wsl1;
    }
    __syncthreads();   // [3]

    // ================= res GEMM: D[64][128], direct h_out =================
    {
        float racc[4][4];
#pragma unroll
        for (int nt = 0; nt < 4; nt++)
#pragma unroll
            for (int r = 0; r < 4; r++) racc[nt][r] = 0.f;
#pragma unroll 1
        for (int ks = 0; ks < 4; ks++) {
            const int kp = ks * 8 + lc;
            uint32_t ah[4], al[4], bh[4][2], bl[4][2];
            int r0 = (o0 + lr) * PG + kp, r8 = r0 + 8 * PG;
            ah[0] = s_wrh[r0]; ah[1] = s_wrh[r8]; ah[2] = s_wrh[r0 + 4]; ah[3] = s_wrh[r8 + 4];
            al[0] = s_wrl[r0]; al[1] = s_wrl[r8]; al[2] = s_wrl[r0 + 4]; al[3] = s_wrl[r8 + 4];
#pragma unroll
            for (int nt = 0; nt < 4; nt++) {
                int q = (pos0 + nt * 8 + lr) * PG + kp;
                bh[nt][0] = s_gh[q]; bh[nt][1] = s_gh[q + 4];
                bl[nt][0] = s_gl[q]; bl[nt][1] = s_gl[q + 4];
            }
#pragma unroll
            for (int nt = 0; nt < 4; nt++) {
                mma_bf16(racc[nt], ah, bh[nt]);
                mma_bf16(racc[nt], ah, bl[nt]);
                mma_bf16(racc[nt], al, bh[nt]);
            }
        }
        float brv[2] = {br[o0 + lr], br[o0 + lr + 8]};
        const float* hb = h_in + (size_t)b * LL * 64;
        float* ho = h_out + (size_t)b * LL * 64;
#pragma unroll
        for (int nt = 0; nt < 4; nt++)
#pragma unroll
            for (int half = 0; half < 2; half++)
#pragma unroll
                for (int co = 0; co < 2; co++) {
                    int c   = o0 + lr + half * 8;
                    int pos = pos0 + nt * 8 + 2 * lc + co;
                    size_t gi = (size_t)(l0 + pos) * 64 + c;
                    ho[gi] = racc[nt][half * 2 + co] + brv[half] + hb[gi];
                }
    }

    // ================= skip GEMM: D[128][128], direct RMW =================
    {
        const int s0 = (w & 3) * 32;
        float sacc[2][4][4];
#pragma unroll
        for (int mt = 0; mt < 2; mt++)
#pragma unroll
            for (int nt = 0; nt < 4; nt++)
#pragma unroll
                for (int r = 0; r < 4; r++) sacc[mt][nt][r] = 0.f;
#pragma unroll 1
        for (int ks = 0; ks < 4; ks++) {
            const int kp = ks * 8 + lc;
            uint32_t ah[2][4], al[2][4], bh[4][2], bl[4][2];
#pragma unroll
            for (int mt = 0; mt < 2; mt++) {
                int r0 = (s0 + mt * 16 + lr) * PG + kp, r8 = r0 + 8 * PG;
                ah[mt][0] = s_wsh[r0]; ah[mt][1] = s_wsh[r8];
                ah[mt][2] = s_wsh[r0 + 4]; ah[mt][3] = s_wsh[r8 + 4];
                al[mt][0] = s_wsl[r0]; al[mt][1] = s_wsl[r8];
                al[mt][2] = s_wsl[r0 + 4]; al[mt][3] = s_wsl[r8 + 4];
            }
#pragma unroll
            for (int nt = 0; nt < 4; nt++) {
                int q = (pos0 + nt * 8 + lr) * PG + kp;
                bh[nt][0] = s_gh[q]; bh[nt][1] = s_gh[q + 4];
                bl[nt][0] = s_gl[q]; bl[nt][1] = s_gl[q + 4];
            }
#pragma unroll
            for (int mt = 0; mt < 2; mt++)
#pragma unroll
                for (int nt = 0; nt < 4; nt++) {
                    mma_bf16(sacc[mt][nt], ah[mt], bh[nt]);
                    mma_bf16(sacc[mt][nt], ah[mt], bl[nt]);
                    mma_bf16(sacc[mt][nt], al[mt], bh[nt]);
                }
        }
        float* sk = skip + (size_t)b * LL * 128;
#pragma unroll
        for (int mt = 0; mt < 2; mt++) {
            float bsv[2] = {bs[s0 + mt * 16 + lr], bs[s0 + mt * 16 + lr + 8]};
#pragma unroll
            for (int nt = 0; nt < 4; nt++)
#pragma unroll
                for (int half = 0; half < 2; half++)
#pragma unroll
                    for (int co = 0; co < 2; co++) {
                        int sc  = s0 + mt * 16 + lr + half * 8;
                        int pos = pos0 + nt * 8 + 2 * lc + co;
                        size_t gi = (size_t)(l0 + pos) * 128 + sc;
                        float v = sacc[mt][nt][half * 2 + co] + bsv[half];
                        if (!first) v += sk[gi];
                        sk[gi] = v;
                    }
        }
    }
}

// ---------------------------------------------------------------------------
// Post: relu(skip) -> out1 -> relu -> out2 -> per-tile column sums (bf16 mma)
// ---------------------------------------------------------------------------
__global__ __launch_bounds__(256) void post_kernel(
    const float* __restrict__ skip,
    const float* __restrict__ w1g, const float* __restrict__ b1,
    const float* __restrict__ w2g, const float* __restrict__ b2,
    float* __restrict__ partial)
{
    extern __shared__ float sm[];
    float*    s_ts = sm;
    uint32_t* s_rh = (uint32_t*)(sm + 128 * P);
    uint32_t* s_rl = s_rh + 128 * PX;
    uint32_t* s_wh = s_rl + 128 * PX;
    uint32_t* s_wl = s_wh + 128 * PX;

    const int tid  = threadIdx.x;
    const int lane = tid & 31;
    const int w    = tid >> 5;
    const int lr   = lane >> 2;
    const int lc   = lane & 3;
    const int b    = blockIdx.y;
    const int l0   = blockIdx.x * 128;

    const int out0 = (w >> 2) * 64;
    const int pos0 = (w & 3) * 32;

    {
        int cp = tid & 63, p0 = tid >> 6;
#pragma unroll
        for (int p = p0; p < 128; p += 4) {
            float2 v = *(const float2*)(skip + ((size_t)b * LL + l0 + p) * 128 + 2 * cp);
            v.x = fmaxf(v.x, 0.f); v.y = fmaxf(v.y, 0.f);
            uint32_t hi, lo; bfsplit2(v.x, v.y, hi, lo);
            s_rh[p * PX + cp] = hi; s_rl[p * PX + cp] = lo;
        }
    }
    for (int e = tid; e < 8192; e += 256) {
        int o = e >> 6, j = e & 63;
        float2 v = *(const float2*)(w1g + o * 128 + 2 * j);
        uint32_t hi, lo; bfsplit2(v.x, v.y, hi, lo);
        s_wh[o * PX + j] = hi; s_wl[o * PX + j] = lo;
    }
    __syncthreads();

    {
        float acc[4][4][4];
#pragma unroll
        for (int mt = 0; mt < 4; mt++)
#pragma unroll
            for (int nt = 0; nt < 4; nt++)
#pragma unroll
                for (int r = 0; r < 4; r++) acc[mt][nt][r] = 0.f;
#pragma unroll 1
        for (int ks = 0; ks < 8; ks++) {
            const int kp = ks * 8 + lc;
            uint32_t ah[4][4], al[4][4], bh[4][2], bl[4][2];
#pragma unroll
            for (int mt = 0; mt < 4; mt++) {
                int r0 = (out0 + mt * 16 + lr) * PX + kp, r8 = r0 + 8 * PX;
                ah[mt][0] = s_wh[r0]; ah[mt][1] = s_wh[r8];
                ah[mt][2] = s_wh[r0 + 4]; ah[mt][3] = s_wh[r8 + 4];
                al[mt][0] = s_wl[r0]; al[mt][1] = s_wl[r8];
                al[mt][2] = s_wl[r0 + 4]; al[mt][3] = s_wl[r8 + 4];
            }
#pragma unroll
            for (int nt = 0; nt < 4; nt++) {
                int q = (pos0 + nt * 8 + lr) * PX + kp;
                bh[nt][0] = s_rh[q]; bh[nt][1] = s_rh[q + 4];
                bl[nt][0] = s_rl[q]; bl[nt][1] = s_rl[q + 4];
            }
#pragma unroll
            for (int mt = 0; mt < 4; mt++)
#pragma unroll
                for (int nt = 0; nt < 4; nt++) {
                    mma_bf16(acc[mt][nt], ah[mt], bh[nt]);
                    mma_bf16(acc[mt][nt], ah[mt], bl[nt]);
                    mma_bf16(acc[mt][nt], al[mt], bh[nt]);
                }
        }
#pragma unroll
        for (int mt = 0; mt < 4; mt++) {
            int row = out0 + mt * 16 + lr;
            float bv0 = b1[row], bv8 = b1[row + 8];
#pragma unroll
            for (int nt = 0; nt < 4; nt++) {
                int col = pos0 + nt * 8 + 2 * lc;
                *(float2*)&s_ts[row * P + col] =
                    make_float2(fmaxf(acc[mt][nt][0] + bv0, 0.f), fmaxf(acc[mt][nt][1] + bv0, 0.f));
                *(float2*)&s_ts[(row + 8) * P + col] =
                    make_float2(fmaxf(acc[mt][nt][2] + bv8, 0.f), fmaxf(acc[mt][nt][3] + bv8, 0.f));
            }
        }
    }
    __syncthreads();

    for (int e = tid; e < 8192; e += 256) {
        int o = e >> 6, j = e & 63;
        float2 v = *(const float2*)(w2g + o * 128 + 2 * j);
        uint32_t hi, lo; bfsplit2(v.x, v.y, hi, lo);
        s_wh[o * PX + j] = hi; s_wl[o * PX + j] = lo;
    }
    for (int it = w; it < 256; it += 8) {
        int cp = it >> 2, pos = (it & 3) * 32 + lane;
        float v0 = s_ts[(2 * cp) * P + pos];
        float v1 = s_ts[(2 * cp + 1) * P + pos];
        uint32_t hi, lo; bfsplit2(v0, v1, hi, lo);
        s_rh[pos * PX + cp] = hi; s_rl[pos * PX + cp] = lo;
    }
    __syncthreads();

    {
        float acc[4][4][4];
#pragma unroll
        for (int mt = 0; mt < 4; mt++)
#pragma unroll
            for (int nt = 0; nt < 4; nt++)
#pragma unroll
                for (int r = 0; r < 4; r++) acc[mt][nt][r] = 0.f;
#pragma unroll 1
        for (int ks = 0; ks < 8; ks++) {
            const int kp = ks * 8 + lc;
            uint32_t ah[4][4], al[4][4], bh[4][2], bl[4][2];
#pragma unroll
            for (int mt = 0; mt < 4; mt++) {
                int r0 = (out0 + mt * 16 + lr) * PX + kp, r8 = r0 + 8 * PX;
                ah[mt][0] = s_wh[r0]; ah[mt][1] = s_wh[r8];
                ah[mt][2] = s_wh[r0 + 4]; ah[mt][3] = s_wh[r8 + 4];
                al[mt][0] = s_wl[r0]; al[mt][1] = s_wl[r8];
                al[mt][2] = s_wl[r0 + 4]; al[mt][3] = s_wl[r8 + 4];
            }
#pragma unroll
            for (int nt = 0; nt < 4; nt++) {
                int q = (pos0 + nt * 8 + lr) * PX + kp;
                bh[nt][0] = s_rh[q]; bh[nt][1] = s_rh[q + 4];
                bl[nt][0] = s_rl[q]; bl[nt][1] = s_rl[q + 4];
            }
#pragma unroll
            for (int mt = 0; mt < 4; mt++)
#pragma unroll
                for (int nt = 0; nt < 4; nt++) {
                    mma_bf16(acc[mt][nt], ah[mt], bh[nt]);
                    mma_bf16(acc[mt][nt], ah[mt], bl[nt]);
                    mma_bf16(acc[mt][nt], al[mt], bh[nt]);
                }
        }
#pragma unroll
        for (int mt = 0; mt < 4; mt++)
#pragma unroll
            for (int nt = 0; nt < 4; nt++) {
                int row = out0 + mt * 16 + lr;
                int col = pos0 + nt * 8 + 2 * lc;
                *(float2*)&s_ts[row * P + col] = make_float2(acc[mt][nt][0], acc[mt][nt][1]);
                *(float2*)&s_ts[(row + 8) * P + col] = make_float2(acc[mt][nt][2], acc[mt][nt][3]);
            }
    }
    __syncthreads();

    {
        float* sred = (float*)s_rh;
        int c = tid & 127, half = tid >> 7;
        float sum = 0.f;
        for (int p = half * 64; p < half * 64 + 64; p++) sum += s_ts[c * P + p];
        sred[half * 128 + c] = sum;
        __syncthreads();
        if (tid < 128)
            partial[((size_t)b * 32 + blockIdx.x) * 128 + tid] =
                sred[tid] + sred[128 + tid] + 128.f * b2[tid];
    }
}

// ---------------------------------------------------------------------------
__global__ __launch_bounds__(256) void final_kernel(
    const float* __restrict__ partial,
    const float* __restrict__ wf1, const float* __restrict__ bf1,
    const float* __restrict__ wf2, const float* __restrict__ bf2,
    const float* __restrict__ wf3, const float* __restrict__ bf3,
    float* __restrict__ out)
{
    __shared__ float pooled[128];
    __shared__ float z1[256];
    __shared__ float z2[128];
    int b = blockIdx.x, tid = threadIdx.x;
    if (tid < 128) {
        float s = 0.f;
        for (int t = 0; t < 32; t++) s += partial[((size_t)b * 32 + t) * 128 + tid];
        pooled[tid] = s * (1.f / (float)LL);
    }
    __syncthreads();
    {
        float a = bf1[tid];
        for (int c = 0; c < 128; c++) a += wf1[tid * 128 + c] * pooled[c];
        z1[tid] = fmaxf(a, 0.f);
    }
    __syncthreads();
    if (tid < 128) {
        float a = bf2[tid];
        for (int c = 0; c < 256; c++) a += wf2[tid * 256 + c] * z1[c];
        z2[tid] = fmaxf(a, 0.f);
    }
    __syncthreads();
    if (tid < 6) {
        float a = bf3[tid];
        for (int c = 0; c < 128; c++) a += wf3[tid * 128 + c] * z2[c];
        out[b * 6 + tid] = a;
    }
}

// ---------------------------------------------------------------------------
extern "C" void kernel_launch(void* const* d_in, const int* in_sizes, int n_in,
                              void* d_out, int out_size)
{
    const float* x      = (const float*)d_in[0];
    const float* w_in   = (const float*)d_in[1];
    const float* b_in   = (const float*)d_in[2];
    const float* w_dil  = (const float*)d_in[3];
    const float* b_dil  = (const float*)d_in[4];
    const float* w_res  = (const float*)d_in[5];
    const float* b_res  = (const float*)d_in[6];
    const float* w_skip = (const float*)d_in[7];
    const float* b_skip = (const float*)d_in[8];
    const float* w_out1 = (const float*)d_in[9];
    const float* b_out1 = (const float*)d_in[10];
    const float* w_out2 = (const float*)d_in[11];
    const float* b_out2 = (const float*)d_in[12];
    const float* w_fc1  = (const float*)d_in[13];
    const float* b_fc1  = (const float*)d_in[14];
    const float* w_fc2  = (const float*)d_in[15];
    const float* b_fc2  = (const float*)d_in[16];
    const float* w_fc3  = (const float*)d_in[17];
    const float* b_fc3  = (const float*)d_in[18];
    float* out = (float*)d_out;

    float *h0, *h1, *skipb, *partial;
    uint32_t *wdh, *wdl, *wrh, *wrl, *wsh, *wsl;
    cudaGetSymbolAddress((void**)&h0,      g_h0);
    cudaGetSymbolAddress((void**)&h1,      g_h1);
    cudaGetSymbolAddress((void**)&skipb,   g_skip);
    cudaGetSymbolAddress((void**)&partial, g_partial);
    cudaGetSymbolAddress((void**)&wdh,     g_wdh);
    cudaGetSymbolAddress((void**)&wdl,     g_wdl);
    cudaGetSymbolAddress((void**)&wrh,     g_wrh);
    cudaGetSymbolAddress((void**)&wrl,     g_wrl);
    cudaGetSymbolAddress((void**)&wsh,     g_wsh);
    cudaGetSymbolAddress((void**)&wsl,     g_wsl);

    const int BLOCK_SMEM = 4 * 128 * PX * 4;                     // 139,264 B
    const int POST_SMEM  = (128 * P + 4 * 128 * PX) * 4;         // 206,848 B
    cudaFuncSetAttribute(block_kernel, cudaFuncAttributeMaxDynamicSharedMemorySize, BLOCK_SMEM);
    cudaFuncSetAttribute(post_kernel,  cudaFuncAttributeMaxDynamicSharedMemorySize, POST_SMEM);

    split_kernel<<<(NBLK * 14336 + 255) / 256, 256>>>(w_dil, w_res, w_skip);
    proj_kernel<<<(BB * LL * 64) / 256, 256>>>(x, w_in, b_in, h0);

    dim3 grid(LL / 128, BB);
    const float* hin = h0;
    float* hout = h1;
    for (int i = 0; i < NBLK; ++i) {
        int d = 1 << (i % 10);
        block_kernel<<<grid, 512, BLOCK_SMEM>>>(
            hin, hout, skipb,
            wdh + i * 8192, wdl + i * 8192, b_dil + i * 128,
            wrh + i * 2048, wrl + i * 2048, b_res + i * 64,
            wsh + i * 4096, wsl + i * 4096, b_skip + i * 128,
            d, (i == 0) ? 1 : 0);
        const float* t = hout;
        hout = (float*)hin;
        hin = t;
    }

    post_kernel<<<grid, 256, POST_SMEM>>>(skipb, w_out1, b_out1, w_out2, b_out2, partial);
    final_kernel<<<BB, 256>>>(partial, w_fc1, b_fc1, w_fc2, b_fc2, w_fc3, b_fc3, out);
}

// round 10
// speedup vs baseline: 1.2135x; 1.2135x over previous
#include <cuda_runtime.h>
#include <cuda_bf16.h>
#include <math.h>
#include <stdint.h>

#define BB   64
#define LL   4096
#define RC   64
#define SC   128
#define NBLK 30
#define P    132    // fp32 staging pitch (floats)
#define PX   68     // pitch (words) for 64-pair split arrays (68 mod 32 == 4)
#define PG   36     // pitch (words) for 32-pair split arrays (36 mod 32 == 4)

// Static device scratch (allocation-free contract)
__device__ float g_h0[(size_t)BB * LL * RC];
__device__ float g_h1[(size_t)BB * LL * RC];
__device__ float g_skip[(size_t)BB * LL * SC];
__device__ float g_partial[(size_t)BB * 32 * SC];
// pre-split weights (bf16x2 hi/lo pair-words)
__device__ uint32_t g_wdh[NBLK * 8192], g_wdl[NBLK * 8192];   // conv  [o][64 pairs]
__device__ uint32_t g_wrh[NBLK * 2048], g_wrl[NBLK * 2048];   // res   [o][32 pairs]
__device__ uint32_t g_wsh[NBLK * 4096], g_wsl[NBLK * 4096];   // skip  [o][32 pairs]

// ---------------------------------------------------------------------------
__device__ __forceinline__ void bfsplit2(float v0, float v1, uint32_t& hi, uint32_t& lo) {
    __nv_bfloat16 h0 = __float2bfloat16_rn(v0);
    __nv_bfloat16 h1 = __float2bfloat16_rn(v1);
    float r0 = v0 - __bfloat162float(h0);
    float r1 = v1 - __bfloat162float(h1);
    __nv_bfloat16 l0 = __float2bfloat16_rn(r0);
    __nv_bfloat16 l1 = __float2bfloat16_rn(r1);
    hi = (uint32_t)__bfloat16_as_ushort(h0) | ((uint32_t)__bfloat16_as_ushort(h1) << 16);
    lo = (uint32_t)__bfloat16_as_ushort(l0) | ((uint32_t)__bfloat16_as_ushort(l1) << 16);
}
__device__ __forceinline__ void bfsplit1(float v, uint16_t& hi, uint16_t& lo) {
    __nv_bfloat16 h = __float2bfloat16_rn(v);
    float r = v - __bfloat162float(h);
    hi = __bfloat16_as_ushort(h);
    lo = __bfloat16_as_ushort(__float2bfloat16_rn(r));
}

__device__ __forceinline__ void mma_bf16(float* d, const uint32_t* a, const uint32_t* b) {
    asm volatile(
        "mma.sync.aligned.m16n8k16.row.col.f32.bf16.bf16.f32 "
        "{%0,%1,%2,%3}, {%4,%5,%6,%7}, {%8,%9}, {%0,%1,%2,%3};"
        : "+f"(d[0]), "+f"(d[1]), "+f"(d[2]), "+f"(d[3])
        : "r"(a[0]), "r"(a[1]), "r"(a[2]), "r"(a[3]), "r"(b[0]), "r"(b[1]));
}

__device__ __forceinline__ float fast_gate(float t, float s) {
    float th = 2.f * __fdividef(1.f, 1.f + __expf(-2.f * t)) - 1.f;
    float sg = __fdividef(1.f, 1.f + __expf(-s));
    return th * sg;
}

// ---------------------------------------------------------------------------
__global__ __launch_bounds__(256) void split_kernel(
    const float* __restrict__ wd, const float* __restrict__ wr,
    const float* __restrict__ ws)
{
    int id = blockIdx.x * 256 + threadIdx.x;
    if (id >= NBLK * 14336) return;
    int i = id / 14336, r = id % 14336;
    const float* src; uint32_t *dh, *dl; int off;
    if (r < 8192)       { src = wd + (size_t)i * 16384; off = r;        dh = g_wdh + i * 8192; dl = g_wdl + i * 8192; }
    else if (r < 10240) { src = wr + (size_t)i * 4096;  off = r - 8192; dh = g_wrh + i * 2048; dl = g_wrl + i * 2048; }
    else                { src = ws + (size_t)i * 8192;  off = r - 10240;dh = g_wsh + i * 4096; dl = g_wsl + i * 4096; }
    float2 v = *(const float2*)(src + 2 * off);
    uint32_t hi, lo; bfsplit2(v.x, v.y, hi, lo);
    dh[off] = hi; dl[off] = lo;
}

// ---------------------------------------------------------------------------
__global__ __launch_bounds__(256) void proj_kernel(
    const float* __restrict__ x, const float* __restrict__ w_in,
    const float* __restrict__ b_in, float* __restrict__ h)
{
    int idx = blockIdx.x * 256 + threadIdx.x;
    int oc = idx & 63;
    int l  = (idx >> 6) & (LL - 1);
    int b  = idx >> 18;
    float acc = b_in[oc];
#pragma unroll
    for (int c = 0; c < 8; ++c)
        acc += w_in[oc * 8 + c] * x[((size_t)(b * 8 + c)) * LL + l];
    h[(size_t)idx] = acc;
}

// ---------------------------------------------------------------------------
// One WaveNet block. 512 threads, 128 pos/CTA.
// Register gate (conv warps own matching t/s rows); smem-staged COALESCED
// epilogues for h_out and skip (the R8 pattern that benchmarked fastest).
// ---------------------------------------------------------------------------
__global__ __launch_bounds__(512, 1) void block_kernel(
    const float* __restrict__ h_in, float* __restrict__ h_out,
    float* __restrict__ skip,
    const uint32_t* __restrict__ wdh, const uint32_t* __restrict__ wdl,
    const float* __restrict__ bd,
    const uint32_t* __restrict__ wrh, const uint32_t* __restrict__ wrl,
    const float* __restrict__ br,
    const uint32_t* __restrict__ wsh, const uint32_t* __restrict__ wsl,
    const float* __restrict__ bs,
    int d, int first)
{
    extern __shared__ uint32_t smw[];
    uint32_t* s_xh = smw;                  // [128 pos][PX] X hi pairs (region A)
    uint32_t* s_xl = s_xh + 128 * PX;
    uint32_t* s_wh = s_xl + 128 * PX;      // [128 o][PX] conv W hi (region B)
    uint32_t* s_wl = s_wh + 128 * PX;
    float*    s_ts = (float*)(s_wl + 128 * PX);   // [128][P] fp32 staging
    // overlays after conv barrier:
    uint32_t* s_gh  = s_xh;                // [128 pos][PG] gated G hi
    uint32_t* s_gl  = s_xl;
    uint32_t* s_wrh = s_wh;                // region B: wr/ws splits
    uint32_t* s_wrl = s_wh + 2304;
    uint32_t* s_wsh = s_wh + 4608;
    uint32_t* s_wsl = s_wh + 9216;

    const int tid  = threadIdx.x;
    const int lane = tid & 31;
    const int w    = tid >> 5;      // warp 0..15
    const int lr   = lane >> 2;     // 0..7
    const int lc   = lane & 3;      // 0..3
    const int b    = blockIdx.y;
    const int l0   = blockIdx.x * 128;

    // ---- prefetch res/skip weights into registers (overlaps everything) ----
    uint4 p_wrh  = ((const uint4*)wrh)[tid];
    uint4 p_wrl  = ((const uint4*)wrl)[tid];
    uint4 p_wsh0 = ((const uint4*)wsh)[tid];
    uint4 p_wsh1 = ((const uint4*)wsh)[tid + 512];
    uint4 p_wsl0 = ((const uint4*)wsl)[tid];
    uint4 p_wsl1 = ((const uint4*)wsl)[tid + 512];

    // ---- stage X: batch all loads first (MLP=32), then split+store ----
    {
        int c = tid & 63, p0 = tid >> 6;
        const float* hb = h_in + (size_t)b * LL * 64;
        float curv[16], delv[16];
#pragma unroll
        for (int i = 0; i < 16; i++) {
            int p = p0 + i * 8;
            int l = l0 + p, ld = l - d;
            curv[i] = hb[(size_t)l * 64 + c];
            delv[i] = (ld >= 0) ? hb[(size_t)ld * 64 + c] : 0.f;
        }
#pragma unroll
        for (int i = 0; i < 16; i++) {
            int p = p0 + i * 8;
            uint32_t hi, lo; bfsplit2(delv[i], curv[i], hi, lo);
            s_xh[p * PX + c] = hi; s_xl[p * PX + c] = lo;
        }
    }
    // ---- stage conv W ----
    for (int e = tid; e < 2048; e += 512) {
        int o = e >> 4, q = e & 15;
        *(uint4*)&s_wh[o * PX + q * 4] = ((const uint4*)wdh)[e];
        *(uint4*)&s_wl[o * PX + q * 4] = ((const uint4*)wdl)[e];
    }
    __syncthreads();   // [1]

    // ================= conv GEMM =================
    // warp tile: rows {o0..o0+16} (t) and {64+o0..} (s), cols pos0..pos0+32
    const int o0   = (w & 3) * 16;
    const int pos0 = (w >> 2) * 32;
    float acc[2][4][4];
#pragma unroll
    for (int mt = 0; mt < 2; mt++)
#pragma unroll
        for (int nt = 0; nt < 4; nt++)
#pragma unroll
            for (int r = 0; r < 4; r++) acc[mt][nt][r] = 0.f;

#pragma unroll 1
    for (int ks = 0; ks < 8; ks++) {
        const int kp = ks * 8 + lc;
        uint32_t ah[2][4], al[2][4], bh[4][2], bl[4][2];
#pragma unroll
        for (int mt = 0; mt < 2; mt++) {
            int r0 = (mt * 64 + o0 + lr) * PX + kp;
            int r8 = r0 + 8 * PX;
            ah[mt][0] = s_wh[r0]; ah[mt][1] = s_wh[r8];
            ah[mt][2] = s_wh[r0 + 4]; ah[mt][3] = s_wh[r8 + 4];
            al[mt][0] = s_wl[r0]; al[mt][1] = s_wl[r8];
            al[mt][2] = s_wl[r0 + 4]; al[mt][3] = s_wl[r8 + 4];
        }
#pragma unroll
        for (int nt = 0; nt < 4; nt++) {
            int q = (pos0 + nt * 8 + lr) * PX + kp;
            bh[nt][0] = s_xh[q]; bh[nt][1] = s_xh[q + 4];
            bl[nt][0] = s_xl[q]; bl[nt][1] = s_xl[q + 4];
        }
#pragma unroll
        for (int mt = 0; mt < 2; mt++)
#pragma unroll
            for (int nt = 0; nt < 4; nt++) {
                mma_bf16(acc[mt][nt], ah[mt], bh[nt]);
                mma_bf16(acc[mt][nt], ah[mt], bl[nt]);
                mma_bf16(acc[mt][nt], al[mt], bh[nt]);
            }
    }
    __syncthreads();   // [2] X + conv W dead

    // ---- register gate -> G (u16 hi/lo into region A) ----
    {
        uint16_t* gh16 = (uint16_t*)s_gh;
        uint16_t* gl16 = (uint16_t*)s_gl;
        float bt[2] = {bd[o0 + lr], bd[o0 + lr + 8]};
        float bg[2] = {bd[64 + o0 + lr], bd[64 + o0 + lr + 8]};
#pragma unroll
        for (int nt = 0; nt < 4; nt++)
#pragma unroll
            for (int half = 0; half < 2; half++)
#pragma unroll
                for (int co = 0; co < 2; co++) {
                    int ri = half * 2 + co;
                    float t = acc[0][nt][ri] + bt[half];
                    float s = acc[1][nt][ri] + bg[half];
                    float g = fast_gate(t, s);
                    int c   = o0 + lr + half * 8;
                    int pos = pos0 + nt * 8 + 2 * lc + co;
                    uint16_t hi, lo; bfsplit1(g, hi, lo);
                    int wi = (pos * PG + (c >> 1)) * 2 + (c & 1);
                    gh16[wi] = hi; gl16[wi] = lo;
                }
    }
    // ---- store prefetched wr/ws into region B ----
    {
        int ow = tid >> 3, cw = 4 * (tid & 7);
        *(uint4*)&s_wrh[ow * PG + cw] = p_wrh;
        *(uint4*)&s_wrl[ow * PG + cw] = p_wrl;
        *(uint4*)&s_wsh[ow * PG + cw] = p_wsh0;
        *(uint4*)&s_wsh[(ow + 64) * PG + cw] = p_wsh1;
        *(uint4*)&s_wsl[ow * PG + cw] = p_wsl0;
        *(uint4*)&s_wsl[(ow + 64) * PG + cw] = p_wsl1;
    }
    __syncthreads();   // [3]

    // ================= res GEMM: D[64][128] -> s_ts =================
    {
        float racc[4][4];
#pragma unroll
        for (int nt = 0; nt < 4; nt++)
#pragma unroll
            for (int r = 0; r < 4; r++) racc[nt][r] = 0.f;
#pragma unroll 1
        for (int ks = 0; ks < 4; ks++) {
            const int kp = ks * 8 + lc;
            uint32_t ah[4], al[4], bh[4][2], bl[4][2];
            int r0 = (o0 + lr) * PG + kp, r8 = r0 + 8 * PG;
            ah[0] = s_wrh[r0]; ah[1] = s_wrh[r8]; ah[2] = s_wrh[r0 + 4]; ah[3] = s_wrh[r8 + 4];
            al[0] = s_wrl[r0]; al[1] = s_wrl[r8]; al[2] = s_wrl[r0 + 4]; al[3] = s_wrl[r8 + 4];
#pragma unroll
            for (int nt = 0; nt < 4; nt++) {
                int q = (pos0 + nt * 8 + lr) * PG + kp;
                bh[nt][0] = s_gh[q]; bh[nt][1] = s_gh[q + 4];
                bl[nt][0] = s_gl[q]; bl[nt][1] = s_gl[q + 4];
            }
#pragma unroll
            for (int nt = 0; nt < 4; nt++) {
                mma_bf16(racc[nt], ah, bh[nt]);
                mma_bf16(racc[nt], ah, bl[nt]);
                mma_bf16(racc[nt], al, bh[nt]);
            }
        }
        float b0v = br[o0 + lr], b8v = br[o0 + lr + 8];
#pragma unroll
        for (int nt = 0; nt < 4; nt++) {
            int row = o0 + lr;
            int col = pos0 + nt * 8 + 2 * lc;
            *(float2*)&s_ts[row * P + col] = make_float2(racc[nt][0] + b0v, racc[nt][1] + b0v);
            *(float2*)&s_ts[(row + 8) * P + col] = make_float2(racc[nt][2] + b8v, racc[nt][3] + b8v);
        }
    }
    __syncthreads();   // [4]

    // ---- h_out = res + residual(h_in), coalesced ----
    {
        int c = tid & 63, p0 = tid >> 6;
#pragma unroll
        for (int p = p0; p < 128; p += 8) {
            size_t gi = ((size_t)b * LL + l0 + p) * 64 + c;
            h_out[gi] = s_ts[c * P + p] + h_in[gi];
        }
    }
    __syncthreads();   // [5] s_ts free

    // ================= skip GEMM: D[128][128] -> s_ts =================
    {
        const int s0 = (w & 3) * 32;
        float sacc[2][4][4];
#pragma unroll
        for (int mt = 0; mt < 2; mt++)
#pragma unroll
            for (int nt = 0; nt < 4; nt++)
#pragma unroll
                for (int r = 0; r < 4; r++) sacc[mt][nt][r] = 0.f;
#pragma unroll 1
        for (int ks = 0; ks < 4; ks++) {
            const int kp = ks * 8 + lc;
            uint32_t ah[2][4], al[2][4], bh[4][2], bl[4][2];
#pragma unroll
            for (int mt = 0; mt < 2; mt++) {
                int r0 = (s0 + mt * 16 + lr) * PG + kp, r8 = r0 + 8 * PG;
                ah[mt][0] = s_wsh[r0]; ah[mt][1] = s_wsh[r8];
                ah[mt][2] = s_wsh[r0 + 4]; ah[mt][3] = s_wsh[r8 + 4];
                al[mt][0] = s_wsl[r0]; al[mt][1] = s_wsl[r8];
                al[mt][2] = s_wsl[r0 + 4]; al[mt][3] = s_wsl[r8 + 4];
            }
#pragma unroll
            for (int nt = 0; nt < 4; nt++) {
                int q = (pos0 + nt * 8 + lr) * PG + kp;
                bh[nt][0] = s_gh[q]; bh[nt][1] = s_gh[q + 4];
                bl[nt][0] = s_gl[q]; bl[nt][1] = s_gl[q + 4];
            }
#pragma unroll
            for (int mt = 0; mt < 2; mt++)
#pragma unroll
                for (int nt = 0; nt < 4; nt++) {
                    mma_bf16(sacc[mt][nt], ah[mt], bh[nt]);
                    mma_bf16(sacc[mt][nt], ah[mt], bl[nt]);
                    mma_bf16(sacc[mt][nt], al[mt], bh[nt]);
                }
        }
#pragma unroll
        for (int mt = 0; mt < 2; mt++)
#pragma unroll
            for (int nt = 0; nt < 4; nt++) {
                int row = s0 + mt * 16 + lr;
                int col = pos0 + nt * 8 + 2 * lc;
                *(float2*)&s_ts[row * P + col] = make_float2(sacc[mt][nt][0], sacc[mt][nt][1]);
                *(float2*)&s_ts[(row + 8) * P + col] = make_float2(sacc[mt][nt][2], sacc[mt][nt][3]);
            }
    }
    __syncthreads();   // [6]

    // ---- coalesced skip RMW ----
    {
        int s = tid & 127, pr = tid >> 7;
        float bsv = bs[s];
#pragma unroll
        for (int p = pr; p < 128; p += 4) {
            size_t gi = ((size_t)b * LL + l0 + p) * 128 + s;
            float v = s_ts[s * P + p] + bsv;
            if (!first) v += skip[gi];
            skip[gi] = v;
        }
    }
}

// ---------------------------------------------------------------------------
// Post: relu(skip) -> out1 -> relu -> out2 -> per-tile column sums (bf16 mma)
// ---------------------------------------------------------------------------
__global__ __launch_bounds__(256) void post_kernel(
    const float* __restrict__ skip,
    const float* __restrict__ w1g, const float* __restrict__ b1,
    const float* __restrict__ w2g, const float* __restrict__ b2,
    float* __restrict__ partial)
{
    extern __shared__ float sm[];
    float*    s_ts = sm;
    uint32_t* s_rh = (uint32_t*)(sm + 128 * P);
    uint32_t* s_rl = s_rh + 128 * PX;
    uint32_t* s_wh = s_rl + 128 * PX;
    uint32_t* s_wl = s_wh + 128 * PX;

    const int tid  = threadIdx.x;
    const int lane = tid & 31;
    const int w    = tid >> 5;
    const int lr   = lane >> 2;
    const int lc   = lane & 3;
    const int b    = blockIdx.y;
    const int l0   = blockIdx.x * 128;

    const int out0 = (w >> 2) * 64;
    const int pos0 = (w & 3) * 32;

    {
        int cp = tid & 63, p0 = tid >> 6;
#pragma unroll
        for (int p = p0; p < 128; p += 4) {
            float2 v = *(const float2*)(skip + ((size_t)b * LL + l0 + p) * 128 + 2 * cp);
            v.x = fmaxf(v.x, 0.f); v.y = fmaxf(v.y, 0.f);
            uint32_t hi, lo; bfsplit2(v.x, v.y, hi, lo);
            s_rh[p * PX + cp] = hi; s_rl[p * PX + cp] = lo;
        }
    }
    for (int e = tid; e < 8192; e += 256) {
        int o = e >> 6, j = e & 63;
        float2 v = *(const float2*)(w1g + o * 128 + 2 * j);
        uint32_t hi, lo; bfsplit2(v.x, v.y, hi, lo);
        s_wh[o * PX + j] = hi; s_wl[o * PX + j] = lo;
    }
    __syncthreads();

    {
        float acc[4][4][4];
#pragma unroll
        for (int mt = 0; mt < 4; mt++)
#pragma unroll
            for (int nt = 0; nt < 4; nt++)
#pragma unroll
                for (int r = 0; r < 4; r++) acc[mt][nt][r] = 0.f;
#pragma unroll 1
        for (int ks = 0; ks < 8; ks++) {
            const int kp = ks * 8 + lc;
            uint32_t ah[4][4], al[4][4], bh[4][2], bl[4][2];
#pragma unroll
            for (int mt = 0; mt < 4; mt++) {
                int r0 = (out0 + mt * 16 + lr) * PX + kp, r8 = r0 + 8 * PX;
                ah[mt][0] = s_wh[r0]; ah[mt][1] = s_wh[r8];
                ah[mt][2] = s_wh[r0 + 4]; ah[mt][3] = s_wh[r8 + 4];
                al[mt][0] = s_wl[r0]; al[mt][1] = s_wl[r8];
                al[mt][2] = s_wl[r0 + 4]; al[mt][3] = s_wl[r8 + 4];
            }
#pragma unroll
            for (int nt = 0; nt < 4; nt++) {
                int q = (pos0 + nt * 8 + lr) * PX + kp;
                bh[nt][0] = s_rh[q]; bh[nt][1] = s_rh[q + 4];
                bl[nt][0] = s_rl[q]; bl[nt][1] = s_rl[q + 4];
            }
#pragma unroll
            for (int mt = 0; mt < 4; mt++)
#pragma unroll
                for (int nt = 0; nt < 4; nt++) {
                    mma_bf16(acc[mt][nt], ah[mt], bh[nt]);
                    mma_bf16(acc[mt][nt], ah[mt], bl[nt]);
                    mma_bf16(acc[mt][nt], al[mt], bh[nt]);
                }
        }
#pragma unroll
        for (int mt = 0; mt < 4; mt++) {
            int row = out0 + mt * 16 + lr;
            float bv0 = b1[row], bv8 = b1[row + 8];
#pragma unroll
            for (int nt = 0; nt < 4; nt++) {
                int col = pos0 + nt * 8 + 2 * lc;
                *(float2*)&s_ts[row * P + col] =
                    make_float2(fmaxf(acc[mt][nt][0] + bv0, 0.f), fmaxf(acc[mt][nt][1] + bv0, 0.f));
                *(float2*)&s_ts[(row + 8) * P + col] =
                    make_float2(fmaxf(acc[mt][nt][2] + bv8, 0.f), fmaxf(acc[mt][nt][3] + bv8, 0.f));
            }
        }
    }
    __syncthreads();

    for (int e = tid; e < 8192; e += 256) {
        int o = e >> 6, j = e & 63;
        float2 v = *(const float2*)(w2g + o * 128 + 2 * j);
        uint32_t hi, lo; bfsplit2(v.x, v.y, hi, lo);
        s_wh[o * PX + j] = hi; s_wl[o * PX + j] = lo;
    }
    for (int it = w; it < 256; it += 8) {
        int cp = it >> 2, pos = (it & 3) * 32 + lane;
        float v0 = s_ts[(2 * cp) * P + pos];
        float v1 = s_ts[(2 * cp + 1) * P + pos];
        uint32_t hi, lo; bfsplit2(v0, v1, hi, lo);
        s_rh[pos * PX + cp] = hi; s_rl[pos * PX + cp] = lo;
    }
    __syncthreads();

    {
        float acc[4][4][4];
#pragma unroll
        for (int mt = 0; mt < 4; mt++)
#pragma unroll
            for (int nt = 0; nt < 4; nt++)
#pragma unroll
                for (int r = 0; r < 4; r++) acc[mt][nt][r] = 0.f;
#pragma unroll 1
        for (int ks = 0; ks < 8; ks++) {
            const int kp = ks * 8 + lc;
            uint32_t ah[4][4], al[4][4], bh[4][2], bl[4][2];
#pragma unroll
            for (int mt = 0; mt < 4; mt++) {
                int r0 = (out0 + mt * 16 + lr) * PX + kp, r8 = r0 + 8 * PX;
                ah[mt][0] = s_wh[r0]; ah[mt][1] = s_wh[r8];
                ah[mt][2] = s_wh[r0 + 4]; ah[mt][3] = s_wh[r8 + 4];
                al[mt][0] = s_wl[r0]; al[mt][1] = s_wl[r8];
                al[mt][2] = s_wl[r0 + 4]; al[mt][3] = s_wl[r8 + 4];
            }
#pragma unroll
            for (int nt = 0; nt < 4; nt++) {
                int q = (pos0 + nt * 8 + lr) * PX + kp;
                bh[nt][0] = s_rh[q]; bh[nt][1] = s_rh[q + 4];
                bl[nt][0] = s_rl[q]; bl[nt][1] = s_rl[q + 4];
            }
#pragma unroll
            for (int mt = 0; mt < 4; mt++)
#pragma unroll
                for (int nt = 0; nt < 4; nt++) {
                    mma_bf16(acc[mt][nt], ah[mt], bh[nt]);
                    mma_bf16(acc[mt][nt], ah[mt], bl[nt]);
                    mma_bf16(acc[mt][nt], al[mt], bh[nt]);
                }
        }
#pragma unroll
        for (int mt = 0; mt < 4; mt++)
#pragma unroll
            for (int nt = 0; nt < 4; nt++) {
                int row = out0 + mt * 16 + lr;
                int col = pos0 + nt * 8 + 2 * lc;
                *(float2*)&s_ts[row * P + col] = make_float2(acc[mt][nt][0], acc[mt][nt][1]);
                *(float2*)&s_ts[(row + 8) * P + col] = make_float2(acc[mt][nt][2], acc[mt][nt][3]);
            }
    }
    __syncthreads();

    {
        float* sred = (float*)s_rh;
        int c = tid & 127, half = tid >> 7;
        float sum = 0.f;
        for (int p = half * 64; p < half * 64 + 64; p++) sum += s_ts[c * P + p];
        sred[half * 128 + c] = sum;
        __syncthreads();
        if (tid < 128)
            partial[((size_t)b * 32 + blockIdx.x) * 128 + tid] =
                sred[tid] + sred[128 + tid] + 128.f * b2[tid];
    }
}

// ---------------------------------------------------------------------------
__global__ __launch_bounds__(256) void final_kernel(
    const float* __restrict__ partial,
    const float* __restrict__ wf1, const float* __restrict__ bf1,
    const float* __restrict__ wf2, const float* __restrict__ bf2,
    const float* __restrict__ wf3, const float* __restrict__ bf3,
    float* __restrict__ out)
{
    __shared__ float pooled[128];
    __shared__ float z1[256];
    __shared__ float z2[128];
    int b = blockIdx.x, tid = threadIdx.x;
    if (tid < 128) {
        float s = 0.f;
        for (int t = 0; t < 32; t++) s += partial[((size_t)b * 32 + t) * 128 + tid];
        pooled[tid] = s * (1.f / (float)LL);
    }
    __syncthreads();
    {
        float a = bf1[tid];
        for (int c = 0; c < 128; c++) a += wf1[tid * 128 + c] * pooled[c];
        z1[tid] = fmaxf(a, 0.f);
    }
    __syncthreads();
    if (tid < 128) {
        float a = bf2[tid];
        for (int c = 0; c < 256; c++) a += wf2[tid * 256 + c] * z1[c];
        z2[tid] = fmaxf(a, 0.f);
    }
    __syncthreads();
    if (tid < 6) {
        float a = bf3[tid];
        for (int c = 0; c < 128; c++) a += wf3[tid * 128 + c] * z2[c];
        out[b * 6 + tid] = a;
    }
}

// ---------------------------------------------------------------------------
extern "C" void kernel_launch(void* const* d_in, const int* in_sizes, int n_in,
                              void* d_out, int out_size)
{
    const float* x      = (const float*)d_in[0];
    const float* w_in   = (const float*)d_in[1];
    const float* b_in   = (const float*)d_in[2];
    const float* w_dil  = (const float*)d_in[3];
    const float* b_dil  = (const float*)d_in[4];
    const float* w_res  = (const float*)d_in[5];
    const float* b_res  = (const float*)d_in[6];
    const float* w_skip = (const float*)d_in[7];
    const float* b_skip = (const float*)d_in[8];
    const float* w_out1 = (const float*)d_in[9];
    const float* b_out1 = (const float*)d_in[10];
    const float* w_out2 = (const float*)d_in[11];
    const float* b_out2 = (const float*)d_in[12];
    const float* w_fc1  = (const float*)d_in[13];
    const float* b_fc1  = (const float*)d_in[14];
    const float* w_fc2  = (const float*)d_in[15];
    const float* b_fc2  = (const float*)d_in[16];
    const float* w_fc3  = (const float*)d_in[17];
    const float* b_fc3  = (const float*)d_in[18];
    float* out = (float*)d_out;

    float *h0, *h1, *skipb, *partial;
    uint32_t *wdh, *wdl, *wrh, *wrl, *wsh, *wsl;
    cudaGetSymbolAddress((void**)&h0,      g_h0);
    cudaGetSymbolAddress((void**)&h1,      g_h1);
    cudaGetSymbolAddress((void**)&skipb,   g_skip);
    cudaGetSymbolAddress((void**)&partial, g_partial);
    cudaGetSymbolAddress((void**)&wdh,     g_wdh);
    cudaGetSymbolAddress((void**)&wdl,     g_wdl);
    cudaGetSymbolAddress((void**)&wrh,     g_wrh);
    cudaGetSymbolAddress((void**)&wrl,     g_wrl);
    cudaGetSymbolAddress((void**)&wsh,     g_wsh);
    cudaGetSymbolAddress((void**)&wsl,     g_wsl);

    const int SMEM = (4 * 128 * PX + 128 * P) * 4;   // 206,848 B
    cudaFuncSetAttribute(block_kernel, cudaFuncAttributeMaxDynamicSharedMemorySize, SMEM);
    cudaFuncSetAttribute(post_kernel,  cudaFuncAttributeMaxDynamicSharedMemorySize, SMEM);

    split_kernel<<<(NBLK * 14336 + 255) / 256, 256>>>(w_dil, w_res, w_skip);
    proj_kernel<<<(BB * LL * 64) / 256, 256>>>(x, w_in, b_in, h0);

    dim3 grid(LL / 128, BB);
    const float* hin = h0;
    float* hout = h1;
    for (int i = 0; i < NBLK; ++i) {
        int d = 1 << (i % 10);
        block_kernel<<<grid, 512, SMEM>>>(
            hin, hout, skipb,
            wdh + i * 8192, wdl + i * 8192, b_dil + i * 128,
            wrh + i * 2048, wrl + i * 2048, b_res + i * 64,
            wsh + i * 4096, wsl + i * 4096, b_skip + i * 128,
            d, (i == 0) ? 1 : 0);
        const float* t = hout;
        hout = (float*)hin;
        hin = t;
    }

    post_kernel<<<grid, 256, SMEM>>>(skipb, w_out1, b_out1, w_out2, b_out2, partial);
    final_kernel<<<BB, 256>>>(partial, w_fc1, b_fc1, w_fc2, b_fc2, w_fc3, b_fc3, out);
}

// round 11
// speedup vs baseline: 1.3811x; 1.1381x over previous
#include <cuda_runtime.h>
#include <cuda_bf16.h>
#include <math.h>
#include <stdint.h>

#define BB   64
#define LL   4096
#define RC   64
#define SC   128
#define NBLK 30
#define P    132    // post_kernel fp32 staging pitch
#define PX   68     // X pitch (words), 68 mod 32 == 4 -> conflict-free
#define PW   36     // weight/G pitch (words), 36 mod 32 == 4

// Static device scratch (allocation-free contract)
__device__ float g_h0[(size_t)BB * LL * RC];
__device__ float g_h1[(size_t)BB * LL * RC];
__device__ float g_skip[(size_t)BB * LL * SC];
__device__ float g_partial[(size_t)BB * 32 * SC];
// pre-split weights (bf16x2 hi/lo pair-words)
// conv: PERMUTED rows o' (even=t[j], odd=s[j]), [i][o'][64 pairs]
__device__ uint32_t g_wdch[NBLK * 8192], g_wdcl[NBLK * 8192];
__device__ uint32_t g_wrh[NBLK * 2048], g_wrl[NBLK * 2048];   // res  [o][32 pairs]
__device__ uint32_t g_wsh[NBLK * 4096], g_wsl[NBLK * 4096];   // skip [o][32 pairs]

// ---------------------------------------------------------------------------
__device__ __forceinline__ void bfsplit2(float v0, float v1, uint32_t& hi, uint32_t& lo) {
    __nv_bfloat16 h0 = __float2bfloat16_rn(v0);
    __nv_bfloat16 h1 = __float2bfloat16_rn(v1);
    float r0 = v0 - __bfloat162float(h0);
    float r1 = v1 - __bfloat162float(h1);
    __nv_bfloat16 l0 = __float2bfloat16_rn(r0);
    __nv_bfloat16 l1 = __float2bfloat16_rn(r1);
    hi = (uint32_t)__bfloat16_as_ushort(h0) | ((uint32_t)__bfloat16_as_ushort(h1) << 16);
    lo = (uint32_t)__bfloat16_as_ushort(l0) | ((uint32_t)__bfloat16_as_ushort(l1) << 16);
}
__device__ __forceinline__ void bfsplit1(float v, uint16_t& hi, uint16_t& lo) {
    __nv_bfloat16 h = __float2bfloat16_rn(v);
    float r = v - __bfloat162float(h);
    hi = __bfloat16_as_ushort(h);
    lo = __bfloat16_as_ushort(__float2bfloat16_rn(r));
}

__device__ __forceinline__ void mma_bf16(float* d, const uint32_t* a, const uint32_t* b) {
    asm volatile(
        "mma.sync.aligned.m16n8k16.row.col.f32.bf16.bf16.f32 "
        "{%0,%1,%2,%3}, {%4,%5,%6,%7}, {%8,%9}, {%0,%1,%2,%3};"
        : "+f"(d[0]), "+f"(d[1]), "+f"(d[2]), "+f"(d[3])
        : "r"(a[0]), "r"(a[1]), "r"(a[2]), "r"(a[3]), "r"(b[0]), "r"(b[1]));
}

__device__ __forceinline__ float fast_gate(float t, float s) {
    float th = 2.f * __fdividef(1.f, 1.f + __expf(-2.f * t)) - 1.f;
    float sg = __fdividef(1.f, 1.f + __expf(-s));
    return th * sg;
}

// ---------------------------------------------------------------------------
// Pre-split weights. Conv rows permuted: o' even -> t[o'/2], odd -> s[o'/2].
// ---------------------------------------------------------------------------
__global__ __launch_bounds__(256) void split_kernel(
    const float* __restrict__ wd, const float* __restrict__ wr,
    const float* __restrict__ ws)
{
    int id = blockIdx.x * 256 + threadIdx.x;
    if (id >= NBLK * 14336) return;
    int i = id / 14336, r = id % 14336;
    if (r < 8192) {
        int op = r >> 6, j = r & 63;
        int o = ((op & 1) << 6) + (op >> 1);          // permuted source row
        float2 v = *(const float2*)(wd + (size_t)i * 16384 + o * 128 + 2 * j);
        uint32_t hi, lo; bfsplit2(v.x, v.y, hi, lo);
        g_wdch[i * 8192 + r] = hi; g_wdcl[i * 8192 + r] = lo;
    } else if (r < 10240) {
        int off = r - 8192;
        float2 v = *(const float2*)(wr + (size_t)i * 4096 + 2 * off);
        uint32_t hi, lo; bfsplit2(v.x, v.y, hi, lo);
        g_wrh[i * 2048 + off] = hi; g_wrl[i * 2048 + off] = lo;
    } else {
        int off = r - 10240;
        float2 v = *(const float2*)(ws + (size_t)i * 8192 + 2 * off);
        uint32_t hi, lo; bfsplit2(v.x, v.y, hi, lo);
        g_wsh[i * 4096 + off] = hi; g_wsl[i * 4096 + off] = lo;
    }
}

// ---------------------------------------------------------------------------
__global__ __launch_bounds__(256) void proj_kernel(
    const float* __restrict__ x, const float* __restrict__ w_in,
    const float* __restrict__ b_in, float* __restrict__ h)
{
    int idx = blockIdx.x * 256 + threadIdx.x;
    int oc = idx & 63;
    int l  = (idx >> 6) & (LL - 1);
    int b  = idx >> 18;
    float acc = b_in[oc];
#pragma unroll
    for (int c = 0; c < 8; ++c)
        acc += w_in[oc * 8 + c] * x[((size_t)(b * 8 + c)) * LL + l];
    h[(size_t)idx] = acc;
}

// ---------------------------------------------------------------------------
// One WaveNet block. 256 threads, 2 CTAs/SM (smem 106,496 B, <=128 regs).
// D[pos][out] orientation (A=X, B=W); conv channels permuted so each thread's
// (c0,c1) D-pair is (t,s) of the same channel -> register gate. Direct float2
// epilogues (no fp32 staging). Conv W streamed in two K-halves.
// ---------------------------------------------------------------------------
__global__ __launch_bounds__(256, 2) void block_kernel(
    const float* __restrict__ h_in, float* __restrict__ h_out,
    float* __restrict__ skip,
    const uint32_t* __restrict__ wdch, const uint32_t* __restrict__ wdcl,
    const float* __restrict__ bd,
    const uint32_t* __restrict__ wrh, const uint32_t* __restrict__ wrl,
    const float* __restrict__ br,
    const uint32_t* __restrict__ wsh, const uint32_t* __restrict__ wsl,
    const float* __restrict__ bs,
    int d, int first)
{
    extern __shared__ uint32_t smw[];
    // region A: X during conv; G + ws-lo after
    uint32_t* s_xh = smw;                         // [128 pos][PX]
    uint32_t* s_xl = smw + 128 * PX;
    uint32_t* s_gh  = smw;                        // [128 pos][PW] (overlay)
    uint32_t* s_gl  = smw + 128 * PW;
    uint32_t* s_wsl = smw + 2 * 128 * PW;         // [128][PW]    (overlay)
    // region B: conv-W half during conv; wr + ws-hi after
    uint32_t* s_cwh = smw + 2 * 128 * PX;         // [128 o'][PW]
    uint32_t* s_cwl = s_cwh + 128 * PW;
    uint32_t* s_wrh = s_cwh;                      // [64][PW]     (overlay)
    uint32_t* s_wrl = s_cwh + 64 * PW;
    uint32_t* s_wsh = s_cwh + 128 * PW;           // [128][PW]    (overlay)

    const int tid  = threadIdx.x;
    const int lane = tid & 31;
    const int w    = tid >> 5;      // warp 0..7
    const int lr   = lane >> 2;     // 0..7
    const int lc   = lane & 3;      // 0..3
    const int b    = blockIdx.y;
    const int l0   = blockIdx.x * 128;

    // ---- stage X split: pair (k even: delayed, k odd: current) ----
    {
        int c = tid & 63, p0 = tid >> 6;   // p0 in 0..3
        const float* hb = h_in + (size_t)b * LL * 64;
#pragma unroll
        for (int g = 0; g < 4; g++) {
            float curv[8], delv[8];
#pragma unroll
            for (int i = 0; i < 8; i++) {
                int p = p0 + (g * 8 + i) * 4;
                int l = l0 + p, ld = l - d;
                curv[i] = hb[(size_t)l * 64 + c];
                delv[i] = (ld >= 0) ? hb[(size_t)ld * 64 + c] : 0.f;
            }
#pragma unroll
            for (int i = 0; i < 8; i++) {
                int p = p0 + (g * 8 + i) * 4;
                uint32_t hi, lo; bfsplit2(delv[i], curv[i], hi, lo);
                s_xh[p * PX + c] = hi; s_xl[p * PX + c] = lo;
            }
        }
    }
    // ---- stage conv W half 0 (pairs 0..31) ----
    for (int e = tid; e < 1024; e += 256) {
        int row = e >> 3, q = e & 7;
        *(uint4*)&s_cwh[row * PW + q * 4] = *(const uint4*)&wdch[row * 64 + q * 4];
        *(uint4*)&s_cwl[row * PW + q * 4] = *(const uint4*)&wdcl[row * 64 + q * 4];
    }
    __syncthreads();

    // ================= conv GEMM: D[128 pos][128 o'], K=128 =================
    const int posb = (w >> 2) * 64;     // 2 pos-groups of 64 (4 mt)
    const int nb   = (w & 3) * 32;      // 4 o'-groups of 32 (4 nt)
    float acc[4][4][4];
#pragma unroll
    for (int mt = 0; mt < 4; mt++)
#pragma unroll
        for (int nt = 0; nt < 4; nt++)
#pragma unroll
            for (int r = 0; r < 4; r++) acc[mt][nt][r] = 0.f;

#pragma unroll 1
    for (int half = 0; half < 2; half++) {
        if (half == 1) {
            __syncthreads();   // half-0 W consumed
            for (int e = tid; e < 1024; e += 256) {
                int row = e >> 3, q = e & 7;
                *(uint4*)&s_cwh[row * PW + q * 4] = *(const uint4*)&wdch[row * 64 + 32 + q * 4];
                *(uint4*)&s_cwl[row * PW + q * 4] = *(const uint4*)&wdcl[row * 64 + 32 + q * 4];
            }
            __syncthreads();
        }
#pragma unroll 1
        for (int ksl = 0; ksl < 4; ksl++) {
            const int kpX = (half * 4 + ksl) * 8 + lc;
            const int kpW = ksl * 8 + lc;
            uint32_t ah[4][4], al[4][4], bh[4][2], bl[4][2];
#pragma unroll
            for (int mt = 0; mt < 4; mt++) {
                int r0 = (posb + mt * 16 + lr) * PX + kpX, r8 = r0 + 8 * PX;
                ah[mt][0] = s_xh[r0]; ah[mt][1] = s_xh[r8];
                ah[mt][2] = s_xh[r0 + 4]; ah[mt][3] = s_xh[r8 + 4];
                al[mt][0] = s_xl[r0]; al[mt][1] = s_xl[r8];
                al[mt][2] = s_xl[r0 + 4]; al[mt][3] = s_xl[r8 + 4];
            }
#pragma unroll
            for (int nt = 0; nt < 4; nt++) {
                int q = (nb + nt * 8 + lr) * PW + kpW;
                bh[nt][0] = s_cwh[q]; bh[nt][1] = s_cwh[q + 4];
                bl[nt][0] = s_cwl[q]; bl[nt][1] = s_cwl[q + 4];
            }
#pragma unroll
            for (int mt = 0; mt < 4; mt++)
#pragma unroll
                for (int nt = 0; nt < 4; nt++) {
                    mma_bf16(acc[mt][nt], ah[mt], bh[nt]);
                    mma_bf16(acc[mt][nt], ah[mt], bl[nt]);
                    mma_bf16(acc[mt][nt], al[mt], bh[nt]);
                }
        }
    }
    __syncthreads();   // X dead, conv W dead

    // ---- register gate -> G (region A); stage wr/ws (region B + ws-lo) ----
    {
        uint16_t* gh16 = (uint16_t*)s_gh;
        uint16_t* gl16 = (uint16_t*)s_gl;
#pragma unroll
        for (int nt = 0; nt < 4; nt++) {
            int j = (nb >> 1) + nt * 4 + lc;
            float bt = bd[j], bsg = bd[64 + j];
#pragma unroll
            for (int mt = 0; mt < 4; mt++)
#pragma unroll
                for (int rh = 0; rh < 2; rh++) {
                    float t = acc[mt][nt][rh * 2 + 0] + bt;
                    float s = acc[mt][nt][rh * 2 + 1] + bsg;
                    float g = fast_gate(t, s);
                    int pos = posb + mt * 16 + lr + rh * 8;
                    uint16_t hi, lo; bfsplit1(g, hi, lo);
                    int wi = (pos * PW + (j >> 1)) * 2 + (j & 1);
                    gh16[wi] = hi; gl16[wi] = lo;
                }
        }
    }
    for (int e = tid; e < 512; e += 256) {
        int row = e >> 3, q = e & 7;
        *(uint4*)&s_wrh[row * PW + q * 4] = *(const uint4*)&wrh[row * 32 + q * 4];
        *(uint4*)&s_wrl[row * PW + q * 4] = *(const uint4*)&wrl[row * 32 + q * 4];
    }
    for (int e = tid; e < 1024; e += 256) {
        int row = e >> 3, q = e & 7;
        *(uint4*)&s_wsh[row * PW + q * 4] = *(const uint4*)&wsh[row * 32 + q * 4];
        *(uint4*)&s_wsl[row * PW + q * 4] = *(const uint4*)&wsl[row * 32 + q * 4];
    }
    __syncthreads();

    // ================= res GEMM: D[128 pos][64 out], K=64 =================
    {
        const int rnb = (w & 3) * 16;   // 2 nt
        float racc[4][2][4];
#pragma unroll
        for (int mt = 0; mt < 4; mt++)
#pragma unroll
            for (int nt = 0; nt < 2; nt++)
#pragma unroll
                for (int r = 0; r < 4; r++) racc[mt][nt][r] = 0.f;
#pragma unroll 1
        for (int ks = 0; ks < 4; ks++) {
            const int kp = ks * 8 + lc;
            uint32_t ah[4][4], al[4][4], bh[2][2], bl[2][2];
#pragma unroll
            for (int mt = 0; mt < 4; mt++) {
                int r0 = (posb + mt * 16 + lr) * PW + kp, r8 = r0 + 8 * PW;
                ah[mt][0] = s_gh[r0]; ah[mt][1] = s_gh[r8];
                ah[mt][2] = s_gh[r0 + 4]; ah[mt][3] = s_gh[r8 + 4];
                al[mt][0] = s_gl[r0]; al[mt][1] = s_gl[r8];
                al[mt][2] = s_gl[r0 + 4]; al[mt][3] = s_gl[r8 + 4];
            }
#pragma unroll
            for (int nt = 0; nt < 2; nt++) {
                int q = (rnb + nt * 8 + lr) * PW + kp;
                bh[nt][0] = s_wrh[q]; bh[nt][1] = s_wrh[q + 4];
                bl[nt][0] = s_wrl[q]; bl[nt][1] = s_wrl[q + 4];
            }
#pragma unroll
            for (int mt = 0; mt < 4; mt++)
#pragma unroll
                for (int nt = 0; nt < 2; nt++) {
                    mma_bf16(racc[mt][nt], ah[mt], bh[nt]);
                    mma_bf16(racc[mt][nt], ah[mt], bl[nt]);
                    mma_bf16(racc[mt][nt], al[mt], bh[nt]);
                }
        }
        const float* hb = h_in + (size_t)b * LL * 64;
        float* ho = h_out + (size_t)b * LL * 64;
#pragma unroll
        for (int nt = 0; nt < 2; nt++) {
            int c = rnb + nt * 8 + 2 * lc;
            float2 brv = *(const float2*)&br[c];
#pragma unroll
            for (int mt = 0; mt < 4; mt++)
#pragma unroll
                for (int rh = 0; rh < 2; rh++) {
                    int pos = posb + mt * 16 + lr + rh * 8;
                    size_t gi = (size_t)(l0 + pos) * 64 + c;
                    float2 hv = *(const float2*)&hb[gi];
                    float2 o;
                    o.x = racc[mt][nt][rh * 2 + 0] + brv.x + hv.x;
                    o.y = racc[mt][nt][rh * 2 + 1] + brv.y + hv.y;
                    *(float2*)&ho[gi] = o;
                }
        }
    }

    // ================= skip GEMM: D[128 pos][128 out], K=64 =================
    {
        const int snb = (w & 3) * 32;   // 4 nt
        float sacc[4][4][4];
#pragma unroll
        for (int mt = 0; mt < 4; mt++)
#pragma unroll
            for (int nt = 0; nt < 4; nt++)
#pragma unroll
                for (int r = 0; r < 4; r++) sacc[mt][nt][r] = 0.f;
#pragma unroll 1
        for (int ks = 0; ks < 4; ks++) {
            const int kp = ks * 8 + lc;
            uint32_t ah[4][4], al[4][4], bh[4][2], bl[4][2];
#pragma unroll
            for (int mt = 0; mt < 4; mt++) {
                int r0 = (posb + mt * 16 + lr) * PW + kp, r8 = r0 + 8 * PW;
                ah[mt][0] = s_gh[r0]; ah[mt][1] = s_gh[r8];
                ah[mt][2] = s_gh[r0 + 4]; ah[mt][3] = s_gh[r8 + 4];
                al[mt][0] = s_gl[r0]; al[mt][1] = s_gl[r8];
                al[mt][2] = s_gl[r0 + 4]; al[mt][3] = s_gl[r8 + 4];
            }
#pragma unroll
            for (int nt = 0; nt < 4; nt++) {
                int q = (snb + nt * 8 + lr) * PW + kp;
                bh[nt][0] = s_wsh[q]; bh[nt][1] = s_wsh[q + 4];
                bl[nt][0] = s_wsl[q]; bl[nt][1] = s_wsl[q + 4];
            }
#pragma unroll
            for (int mt = 0; mt < 4; mt++)
#pragma unroll
                for (int nt = 0; nt < 4; nt++) {
                    mma_bf16(sacc[mt][nt], ah[mt], bh[nt]);
                    mma_bf16(sacc[mt][nt], ah[mt], bl[nt]);
                    mma_bf16(sacc[mt][nt], al[mt], bh[nt]);
                }
        }
        float* sk = skip + (size_t)b * LL * 128;
#pragma unroll
        for (int nt = 0; nt < 4; nt++) {
            int s = snb + nt * 8 + 2 * lc;
            float2 bsv = *(const float2*)&bs[s];
#pragma unroll
            for (int mt = 0; mt < 4; mt++)
#pragma unroll
                for (int rh = 0; rh < 2; rh++) {
                    int pos = posb + mt * 16 + lr + rh * 8;
                    size_t gi = (size_t)(l0 + pos) * 128 + s;
                    float2 v;
                    v.x = sacc[mt][nt][rh * 2 + 0] + bsv.x;
                    v.y = sacc[mt][nt][rh * 2 + 1] + bsv.y;
                    if (!first) {
                        float2 old = *(const float2*)&sk[gi];
                        v.x += old.x; v.y += old.y;
                    }
                    *(float2*)&sk[gi] = v;
                }
        }
    }
}

// ---------------------------------------------------------------------------
// Post: relu(skip) -> out1 -> relu -> out2 -> per-tile column sums (bf16 mma)
// ---------------------------------------------------------------------------
__global__ __launch_bounds__(256) void post_kernel(
    const float* __restrict__ skip,
    const float* __restrict__ w1g, const float* __restrict__ b1,
    const float* __restrict__ w2g, const float* __restrict__ b2,
    float* __restrict__ partial)
{
    extern __shared__ float sm[];
    float*    s_ts = sm;
    uint32_t* s_rh = (uint32_t*)(sm + 128 * P);
    uint32_t* s_rl = s_rh + 128 * PX;
    uint32_t* s_wh = s_rl + 128 * PX;
    uint32_t* s_wl = s_wh + 128 * PX;

    const int tid  = threadIdx.x;
    const int lane = tid & 31;
    const int w    = tid >> 5;
    const int lr   = lane >> 2;
    const int lc   = lane & 3;
    const int b    = blockIdx.y;
    const int l0   = blockIdx.x * 128;

    const int out0 = (w >> 2) * 64;
    const int pos0 = (w & 3) * 32;

    {
        int cp = tid & 63, p0 = tid >> 6;
#pragma unroll
        for (int p = p0; p < 128; p += 4) {
            float2 v = *(const float2*)(skip + ((size_t)b * LL + l0 + p) * 128 + 2 * cp);
            v.x = fmaxf(v.x, 0.f); v.y = fmaxf(v.y, 0.f);
            uint32_t hi, lo; bfsplit2(v.x, v.y, hi, lo);
            s_rh[p * PX + cp] = hi; s_rl[p * PX + cp] = lo;
        }
    }
    for (int e = tid; e < 8192; e += 256) {
        int o = e >> 6, j = e & 63;
        float2 v = *(const float2*)(w1g + o * 128 + 2 * j);
        uint32_t hi, lo; bfsplit2(v.x, v.y, hi, lo);
        s_wh[o * PX + j] = hi; s_wl[o * PX + j] = lo;
    }
    __syncthreads();

    {
        float acc[4][4][4];
#pragma unroll
        for (int mt = 0; mt < 4; mt++)
#pragma unroll
            for (int nt = 0; nt < 4; nt++)
#pragma unroll
                for (int r = 0; r < 4; r++) acc[mt][nt][r] = 0.f;
#pragma unroll 1
        for (int ks = 0; ks < 8; ks++) {
            const int kp = ks * 8 + lc;
            uint32_t ah[4][4], al[4][4], bh[4][2], bl[4][2];
#pragma unroll
            for (int mt = 0; mt < 4; mt++) {
                int r0 = (out0 + mt * 16 + lr) * PX + kp, r8 = r0 + 8 * PX;
                ah[mt][0] = s_wh[r0]; ah[mt][1] = s_wh[r8];
                ah[mt][2] = s_wh[r0 + 4]; ah[mt][3] = s_wh[r8 + 4];
                al[mt][0] = s_wl[r0]; al[mt][1] = s_wl[r8];
                al[mt][2] = s_wl[r0 + 4]; al[mt][3] = s_wl[r8 + 4];
            }
#pragma unroll
            for (int nt = 0; nt < 4; nt++) {
                int q = (pos0 + nt * 8 + lr) * PX + kp;
                bh[nt][0] = s_rh[q]; bh[nt][1] = s_rh[q + 4];
                bl[nt][0] = s_rl[q]; bl[nt][1] = s_rl[q + 4];
            }
#pragma unroll
            for (int mt = 0; mt < 4; mt++)
#pragma unroll
                for (int nt = 0; nt < 4; nt++) {
                    mma_bf16(acc[mt][nt], ah[mt], bh[nt]);
                    mma_bf16(acc[mt][nt], ah[mt], bl[nt]);
                    mma_bf16(acc[mt][nt], al[mt], bh[nt]);
                }
        }
#pragma unroll
        for (int mt = 0; mt < 4; mt++) {
            int row = out0 + mt * 16 + lr;
            float bv0 = b1[row], bv8 = b1[row + 8];
#pragma unroll
            for (int nt = 0; nt < 4; nt++) {
                int col = pos0 + nt * 8 + 2 * lc;
                *(float2*)&s_ts[row * P + col] =
                    make_float2(fmaxf(acc[mt][nt][0] + bv0, 0.f), fmaxf(acc[mt][nt][1] + bv0, 0.f));
                *(float2*)&s_ts[(row + 8) * P + col] =
                    make_float2(fmaxf(acc[mt][nt][2] + bv8, 0.f), fmaxf(acc[mt][nt][3] + bv8, 0.f));
            }
        }
    }
    __syncthreads();

    for (int e = tid; e < 8192; e += 256) {
        int o = e >> 6, j = e & 63;
        float2 v = *(const float2*)(w2g + o * 128 + 2 * j);
        uint32_t hi, lo; bfsplit2(v.x, v.y, hi, lo);
        s_wh[o * PX + j] = hi; s_wl[o * PX + j] = lo;
    }
    for (int it = w; it < 256; it += 8) {
        int cp = it >> 2, pos = (it & 3) * 32 + lane;
        float v0 = s_ts[(2 * cp) * P + pos];
        float v1 = s_ts[(2 * cp + 1) * P + pos];
        uint32_t hi, lo; bfsplit2(v0, v1, hi, lo);
        s_rh[pos * PX + cp] = hi; s_rl[pos * PX + cp] = lo;
    }
    __syncthreads();

    {
        float acc[4][4][4];
#pragma unroll
        for (int mt = 0; mt < 4; mt++)
#pragma unroll
            for (int nt = 0; nt < 4; nt++)
#pragma unroll
                for (int r = 0; r < 4; r++) acc[mt][nt][r] = 0.f;
#pragma unroll 1
        for (int ks = 0; ks < 8; ks++) {
            const int kp = ks * 8 + lc;
            uint32_t ah[4][4], al[4][4], bh[4][2], bl[4][2];
#pragma unroll
            for (int mt = 0; mt < 4; mt++) {
                int r0 = (out0 + mt * 16 + lr) * PX + kp, r8 = r0 + 8 * PX;
                ah[mt][0] = s_wh[r0]; ah[mt][1] = s_wh[r8];
                ah[mt][2] = s_wh[r0 + 4]; ah[mt][3] = s_wh[r8 + 4];
                al[mt][0] = s_wl[r0]; al[mt][1] = s_wl[r8];
                al[mt][2] = s_wl[r0 + 4]; al[mt][3] = s_wl[r8 + 4];
            }
#pragma unroll
            for (int nt = 0; nt < 4; nt++) {
                int q = (pos0 + nt * 8 + lr) * PX + kp;
                bh[nt][0] = s_rh[q]; bh[nt][1] = s_rh[q + 4];
                bl[nt][0] = s_rl[q]; bl[nt][1] = s_rl[q + 4];
            }
#pragma unroll
            for (int mt = 0; mt < 4; mt++)
#pragma unroll
                for (int nt = 0; nt < 4; nt++) {
                    mma_bf16(acc[mt][nt], ah[mt], bh[nt]);
                    mma_bf16(acc[mt][nt], ah[mt], bl[nt]);
                    mma_bf16(acc[mt][nt], al[mt], bh[nt]);
                }
        }
#pragma unroll
        for (int mt = 0; mt < 4; mt++)
#pragma unroll
            for (int nt = 0; nt < 4; nt++) {
                int row = out0 + mt * 16 + lr;
                int col = pos0 + nt * 8 + 2 * lc;
                *(float2*)&s_ts[row * P + col] = make_float2(acc[mt][nt][0], acc[mt][nt][1]);
                *(float2*)&s_ts[(row + 8) * P + col] = make_float2(acc[mt][nt][2], acc[mt][nt][3]);
            }
    }
    __syncthreads();

    {
        float* sred = (float*)s_rh;
        int c = tid & 127, half = tid >> 7;
        float sum = 0.f;
        for (int p = half * 64; p < half * 64 + 64; p++) sum += s_ts[c * P + p];
        sred[half * 128 + c] = sum;
        __syncthreads();
        if (tid < 128)
            partial[((size_t)b * 32 + blockIdx.x) * 128 + tid] =
                sred[tid] + sred[128 + tid] + 128.f * b2[tid];
    }
}

// ---------------------------------------------------------------------------
__global__ __launch_bounds__(256) void final_kernel(
    const float* __restrict__ partial,
    const float* __restrict__ wf1, const float* __restrict__ bf1,
    const float* __restrict__ wf2, const float* __restrict__ bf2,
    const float* __restrict__ wf3, const float* __restrict__ bf3,
    float* __restrict__ out)
{
    __shared__ float pooled[128];
    __shared__ float z1[256];
    __shared__ float z2[128];
    int b = blockIdx.x, tid = threadIdx.x;
    if (tid < 128) {
        float s = 0.f;
        for (int t = 0; t < 32; t++) s += partial[((size_t)b * 32 + t) * 128 + tid];
        pooled[tid] = s * (1.f / (float)LL);
    }
    __syncthreads();
    {
        float a = bf1[tid];
        for (int c = 0; c < 128; c++) a += wf1[tid * 128 + c] * pooled[c];
        z1[tid] = fmaxf(a, 0.f);
    }
    __syncthreads();
    if (tid < 128) {
        float a = bf2[tid];
        for (int c = 0; c < 256; c++) a += wf2[tid * 256 + c] * z1[c];
        z2[tid] = fmaxf(a, 0.f);
    }
    __syncthreads();
    if (tid < 6) {
        float a = bf3[tid];
        for (int c = 0; c < 128; c++) a += wf3[tid * 128 + c] * z2[c];
        out[b * 6 + tid] = a;
    }
}

// ---------------------------------------------------------------------------
extern "C" void kernel_launch(void* const* d_in, const int* in_sizes, int n_in,
                              void* d_out, int out_size)
{
    const float* x      = (const float*)d_in[0];
    const float* w_in   = (const float*)d_in[1];
    const float* b_in   = (const float*)d_in[2];
    const float* w_dil  = (const float*)d_in[3];
    const float* b_dil  = (const float*)d_in[4];
    const float* w_res  = (const float*)d_in[5];
    const float* b_res  = (const float*)d_in[6];
    const float* w_skip = (const float*)d_in[7];
    const float* b_skip = (const float*)d_in[8];
    const float* w_out1 = (const float*)d_in[9];
    const float* b_out1 = (const float*)d_in[10];
    const float* w_out2 = (const float*)d_in[11];
    const float* b_out2 = (const float*)d_in[12];
    const float* w_fc1  = (const float*)d_in[13];
    const float* b_fc1  = (const float*)d_in[14];
    const float* w_fc2  = (const float*)d_in[15];
    const float* b_fc2  = (const float*)d_in[16];
    const float* w_fc3  = (const float*)d_in[17];
    const float* b_fc3  = (const float*)d_in[18];
    float* out = (float*)d_out;

    float *h0, *h1, *skipb, *partial;
    uint32_t *wdch, *wdcl, *wrh, *wrl, *wsh, *wsl;
    cudaGetSymbolAddress((void**)&h0,      g_h0);
    cudaGetSymbolAddress((void**)&h1,      g_h1);
    cudaGetSymbolAddress((void**)&skipb,   g_skip);
    cudaGetSymbolAddress((void**)&partial, g_partial);
    cudaGetSymbolAddress((void**)&wdch,    g_wdch);
    cudaGetSymbolAddress((void**)&wdcl,    g_wdcl);
    cudaGetSymbolAddress((void**)&wrh,     g_wrh);
    cudaGetSymbolAddress((void**)&wrl,     g_wrl);
    cudaGetSymbolAddress((void**)&wsh,     g_wsh);
    cudaGetSymbolAddress((void**)&wsl,     g_wsl);

    const int BLOCK_SMEM = (2 * 128 * PX + 2 * 128 * PW) * 4;    // 106,496 B
    const int POST_SMEM  = (128 * P + 4 * 128 * PX) * 4;         // 206,848 B
    cudaFuncSetAttribute(block_kernel, cudaFuncAttributeMaxDynamicSharedMemorySize, BLOCK_SMEM);
    cudaFuncSetAttribute(post_kernel,  cudaFuncAttributeMaxDynamicSharedMemorySize, POST_SMEM);

    split_kernel<<<(NBLK * 14336 + 255) / 256, 256>>>(w_dil, w_res, w_skip);
    proj_kernel<<<(BB * LL * 64) / 256, 256>>>(x, w_in, b_in, h0);

    dim3 grid(LL / 128, BB);
    const float* hin = h0;
    float* hout = h1;
    for (int i = 0; i < NBLK; ++i) {
        int d = 1 << (i % 10);
        block_kernel<<<grid, 256, BLOCK_SMEM>>>(
            hin, hout, skipb,
            wdch + i * 8192, wdcl + i * 8192, b_dil + i * 128,
            wrh + i * 2048,  wrl + i * 2048,  b_res + i * 64,
            wsh + i * 4096,  wsl + i * 4096,  b_skip + i * 128,
            d, (i == 0) ? 1 : 0);
        const float* t = hout;
        hout = (float*)hin;
        hin = t;
    }

    post_kernel<<<grid, 256, POST_SMEM>>>(skipb, w_out1, b_out1, w_out2, b_out2, partial);
    final_kernel<<<BB, 256>>>(partial, w_fc1, b_fc1, w_fc2, b_fc2, w_fc3, b_fc3, out);
}

// round 12
// speedup vs baseline: 1.4136x; 1.0236x over previous
#include <cuda_runtime.h>
#include <cuda_bf16.h>
#include <math.h>
#include <stdint.h>

#define BB   64
#define LL   4096
#define RC   64
#define SC   128
#define NBLK 30
#define P    132    // post_kernel fp32 staging pitch
#define PX   68     // X pitch (words), 68 mod 32 == 4 -> conflict-free
#define PW   36     // weight/G pitch (words), 36 mod 32 == 4

// Static device scratch (allocation-free contract)
__device__ float g_h0[(size_t)BB * LL * RC];
__device__ float g_h1[(size_t)BB * LL * RC];
__device__ float g_skip[(size_t)BB * LL * SC];
__device__ float g_partial[(size_t)BB * 32 * SC];
// pre-split weights (bf16x2 hi/lo pair-words)
__device__ uint32_t g_wdch[NBLK * 8192], g_wdcl[NBLK * 8192];
__device__ uint32_t g_wrh[NBLK * 2048], g_wrl[NBLK * 2048];
__device__ uint32_t g_wsh[NBLK * 4096], g_wsl[NBLK * 4096];

// ---------------------------------------------------------------------------
__device__ __forceinline__ void bfsplit2(float v0, float v1, uint32_t& hi, uint32_t& lo) {
    __nv_bfloat16 h0 = __float2bfloat16_rn(v0);
    __nv_bfloat16 h1 = __float2bfloat16_rn(v1);
    float r0 = v0 - __bfloat162float(h0);
    float r1 = v1 - __bfloat162float(h1);
    __nv_bfloat16 l0 = __float2bfloat16_rn(r0);
    __nv_bfloat16 l1 = __float2bfloat16_rn(r1);
    hi = (uint32_t)__bfloat16_as_ushort(h0) | ((uint32_t)__bfloat16_as_ushort(h1) << 16);
    lo = (uint32_t)__bfloat16_as_ushort(l0) | ((uint32_t)__bfloat16_as_ushort(l1) << 16);
}
__device__ __forceinline__ void bfsplit1(float v, uint16_t& hi, uint16_t& lo) {
    __nv_bfloat16 h = __float2bfloat16_rn(v);
    float r = v - __bfloat162float(h);
    hi = __bfloat16_as_ushort(h);
    lo = __bfloat16_as_ushort(__float2bfloat16_rn(r));
}

__device__ __forceinline__ void mma_bf16(float* d, const uint32_t* a, const uint32_t* b) {
    asm volatile(
        "mma.sync.aligned.m16n8k16.row.col.f32.bf16.bf16.f32 "
        "{%0,%1,%2,%3}, {%4,%5,%6,%7}, {%8,%9}, {%0,%1,%2,%3};"
        : "+f"(d[0]), "+f"(d[1]), "+f"(d[2]), "+f"(d[3])
        : "r"(a[0]), "r"(a[1]), "r"(a[2]), "r"(a[3]), "r"(b[0]), "r"(b[1]));
}

__device__ __forceinline__ uint32_t smaddr(const void* p) {
    return (uint32_t)__cvta_generic_to_shared(p);
}
__device__ __forceinline__ void ldm_x4(uint32_t* r, uint32_t addr) {
    asm volatile("ldmatrix.sync.aligned.m8n8.x4.shared.b16 {%0,%1,%2,%3}, [%4];"
        : "=r"(r[0]), "=r"(r[1]), "=r"(r[2]), "=r"(r[3]) : "r"(addr));
}

__device__ __forceinline__ float fast_gate(float t, float s) {
    float th = 2.f * __fdividef(1.f, 1.f + __expf(-2.f * t)) - 1.f;
    float sg = __fdividef(1.f, 1.f + __expf(-s));
    return th * sg;
}

// ---------------------------------------------------------------------------
__global__ __launch_bounds__(256) void split_kernel(
    const float* __restrict__ wd, const float* __restrict__ wr,
    const float* __restrict__ ws)
{
    int id = blockIdx.x * 256 + threadIdx.x;
    if (id >= NBLK * 14336) return;
    int i = id / 14336, r = id % 14336;
    if (r < 8192) {
        int op = r >> 6, j = r & 63;
        int o = ((op & 1) << 6) + (op >> 1);          // permuted source row
        float2 v = *(const float2*)(wd + (size_t)i * 16384 + o * 128 + 2 * j);
        uint32_t hi, lo; bfsplit2(v.x, v.y, hi, lo);
        g_wdch[i * 8192 + r] = hi; g_wdcl[i * 8192 + r] = lo;
    } else if (r < 10240) {
        int off = r - 8192;
        float2 v = *(const float2*)(wr + (size_t)i * 4096 + 2 * off);
        uint32_t hi, lo; bfsplit2(v.x, v.y, hi, lo);
        g_wrh[i * 2048 + off] = hi; g_wrl[i * 2048 + off] = lo;
    } else {
        int off = r - 10240;
        float2 v = *(const float2*)(ws + (size_t)i * 8192 + 2 * off);
        uint32_t hi, lo; bfsplit2(v.x, v.y, hi, lo);
        g_wsh[i * 4096 + off] = hi; g_wsl[i * 4096 + off] = lo;
    }
}

// ---------------------------------------------------------------------------
__global__ __launch_bounds__(256) void proj_kernel(
    const float* __restrict__ x, const float* __restrict__ w_in,
    const float* __restrict__ b_in, float* __restrict__ h)
{
    int idx = blockIdx.x * 256 + threadIdx.x;
    int oc = idx & 63;
    int l  = (idx >> 6) & (LL - 1);
    int b  = idx >> 18;
    float acc = b_in[oc];
#pragma unroll
    for (int c = 0; c < 8; ++c)
        acc += w_in[oc * 8 + c] * x[((size_t)(b * 8 + c)) * LL + l];
    h[(size_t)idx] = acc;
}

// ---------------------------------------------------------------------------
// One WaveNet block. 256 threads, 2 CTAs/SM. All fragment loads via ldmatrix.
// ---------------------------------------------------------------------------
__global__ __launch_bounds__(256, 2) void block_kernel(
    const float* __restrict__ h_in, float* __restrict__ h_out,
    float* __restrict__ skip,
    const uint32_t* __restrict__ wdch, const uint32_t* __restrict__ wdcl,
    const float* __restrict__ bd,
    const uint32_t* __restrict__ wrh, const uint32_t* __restrict__ wrl,
    const float* __restrict__ br,
    const uint32_t* __restrict__ wsh, const uint32_t* __restrict__ wsl,
    const float* __restrict__ bs,
    int d, int first)
{
    extern __shared__ uint32_t smw[];
    // region A: X during conv; G + ws-lo after
    uint32_t* s_xh = smw;                         // [128 pos][PX]
    uint32_t* s_xl = smw + 128 * PX;
    uint32_t* s_gh  = smw;                        // [128 pos][PW] (overlay)
    uint32_t* s_gl  = smw + 128 * PW;
    uint32_t* s_wsl = smw + 2 * 128 * PW;         // [128][PW]    (overlay)
    // region B: conv-W half during conv; wr + ws-hi after
    uint32_t* s_cwh = smw + 2 * 128 * PX;         // [128 o'][PW]
    uint32_t* s_cwl = s_cwh + 128 * PW;
    uint32_t* s_wrh = s_cwh;                      // [64][PW]     (overlay)
    uint32_t* s_wrl = s_cwh + 64 * PW;
    uint32_t* s_wsh = s_cwh + 128 * PW;           // [128][PW]    (overlay)

    const int tid  = threadIdx.x;
    const int lane = tid & 31;
    const int w    = tid >> 5;      // warp 0..7
    const int lr   = lane >> 2;     // 0..7
    const int lc   = lane & 3;      // 0..3
    const int b    = blockIdx.y;
    const int l0   = blockIdx.x * 128;

    // ldmatrix lane-address components
    const int arow8 = (lane & 7) + ((lane >> 3) & 1) * 8;   // A: row within 16
    const int acol4 = (lane >> 4) * 4;                      // A: kpair base 0/4
    const int brow8 = (lane & 7) + ((lane >> 4) & 1) * 8;   // B: row within 16
    const int bcol4 = ((lane >> 3) & 1) * 4;                // B: kpair base 0/4

    // ---- stage X split ----
    {
        int c = tid & 63, p0 = tid >> 6;
        const float* hb = h_in + (size_t)b * LL * 64;
#pragma unroll
        for (int g = 0; g < 4; g++) {
            float curv[8], delv[8];
#pragma unroll
            for (int i = 0; i < 8; i++) {
                int p = p0 + (g * 8 + i) * 4;
                int l = l0 + p, ld = l - d;
                curv[i] = hb[(size_t)l * 64 + c];
                delv[i] = (ld >= 0) ? hb[(size_t)ld * 64 + c] : 0.f;
            }
#pragma unroll
            for (int i = 0; i < 8; i++) {
                int p = p0 + (g * 8 + i) * 4;
                uint32_t hi, lo; bfsplit2(delv[i], curv[i], hi, lo);
                s_xh[p * PX + c] = hi; s_xl[p * PX + c] = lo;
            }
        }
    }
    // ---- stage conv W half 0 ----
    for (int e = tid; e < 1024; e += 256) {
        int row = e >> 3, q = e & 7;
        *(uint4*)&s_cwh[row * PW + q * 4] = *(const uint4*)&wdch[row * 64 + q * 4];
        *(uint4*)&s_cwl[row * PW + q * 4] = *(const uint4*)&wdcl[row * 64 + q * 4];
    }
    __syncthreads();

    // ================= conv GEMM: D[128 pos][128 o'], K=128 =================
    const int posb = (w >> 2) * 64;
    const int nb   = (w & 3) * 32;
    float acc[4][4][4];
#pragma unroll
    for (int mt = 0; mt < 4; mt++)
#pragma unroll
        for (int nt = 0; nt < 4; nt++)
#pragma unroll
            for (int r = 0; r < 4; r++) acc[mt][nt][r] = 0.f;

    const uint32_t aXh = smaddr(s_xh) + ((posb + arow8) * PX + acol4) * 4;
    const uint32_t aXl = aXh + 128 * PX * 4;
    const uint32_t bCh = smaddr(s_cwh) + ((nb + brow8) * PW + bcol4) * 4;
    const uint32_t bCl = bCh + 128 * PW * 4;

#pragma unroll 1
    for (int half = 0; half < 2; half++) {
        if (half == 1) {
            __syncthreads();
            for (int e = tid; e < 1024; e += 256) {
                int row = e >> 3, q = e & 7;
                *(uint4*)&s_cwh[row * PW + q * 4] = *(const uint4*)&wdch[row * 64 + 32 + q * 4];
                *(uint4*)&s_cwl[row * PW + q * 4] = *(const uint4*)&wdcl[row * 64 + 32 + q * 4];
            }
            __syncthreads();
        }
#pragma unroll 1
        for (int ksl = 0; ksl < 4; ksl++) {
            const uint32_t offX = (uint32_t)((half * 4 + ksl) * 32);
            const uint32_t offW = (uint32_t)(ksl * 32);
            uint32_t ah[4][4], al[4][4], bh[2][4], bl[2][4];
#pragma unroll
            for (int mt = 0; mt < 4; mt++) {
                ldm_x4(ah[mt], aXh + (uint32_t)(mt * 16 * PX * 4) + offX);
                ldm_x4(al[mt], aXl + (uint32_t)(mt * 16 * PX * 4) + offX);
            }
#pragma unroll
            for (int t = 0; t < 2; t++) {
                ldm_x4(bh[t], bCh + (uint32_t)(t * 16 * PW * 4) + offW);
                ldm_x4(bl[t], bCl + (uint32_t)(t * 16 * PW * 4) + offW);
            }
#pragma unroll
            for (int mt = 0; mt < 4; mt++)
#pragma unroll
                for (int nt = 0; nt < 4; nt++) {
                    const uint32_t* bhp = &bh[nt >> 1][(nt & 1) * 2];
                    const uint32_t* blp = &bl[nt >> 1][(nt & 1) * 2];
                    mma_bf16(acc[mt][nt], ah[mt], bhp);
                    mma_bf16(acc[mt][nt], ah[mt], blp);
                    mma_bf16(acc[mt][nt], al[mt], bhp);
                }
        }
    }
    __syncthreads();   // X dead, conv W dead

    // ---- register gate -> G; stage wr/ws ----
    {
        uint16_t* gh16 = (uint16_t*)s_gh;
        uint16_t* gl16 = (uint16_t*)s_gl;
#pragma unroll
        for (int nt = 0; nt < 4; nt++) {
            int j = (nb >> 1) + nt * 4 + lc;
            float bt = bd[j], bsg = bd[64 + j];
#pragma unroll
            for (int mt = 0; mt < 4; mt++)
#pragma unroll
                for (int rh = 0; rh < 2; rh++) {
                    float t = acc[mt][nt][rh * 2 + 0] + bt;
                    float s = acc[mt][nt][rh * 2 + 1] + bsg;
                    float g = fast_gate(t, s);
                    int pos = posb + mt * 16 + lr + rh * 8;
                    uint16_t hi, lo; bfsplit1(g, hi, lo);
                    int wi = (pos * PW + (j >> 1)) * 2 + (j & 1);
                    gh16[wi] = hi; gl16[wi] = lo;
                }
        }
    }
    for (int e = tid; e < 512; e += 256) {
        int row = e >> 3, q = e & 7;
        *(uint4*)&s_wrh[row * PW + q * 4] = *(const uint4*)&wrh[row * 32 + q * 4];
        *(uint4*)&s_wrl[row * PW + q * 4] = *(const uint4*)&wrl[row * 32 + q * 4];
    }
    for (int e = tid; e < 1024; e += 256) {
        int row = e >> 3, q = e & 7;
        *(uint4*)&s_wsh[row * PW + q * 4] = *(const uint4*)&wsh[row * 32 + q * 4];
        *(uint4*)&s_wsl[row * PW + q * 4] = *(const uint4*)&wsl[row * 32 + q * 4];
    }
    __syncthreads();

    const uint32_t aGh = smaddr(s_gh) + ((posb + arow8) * PW + acol4) * 4;
    const uint32_t aGl = aGh + 128 * PW * 4;

    // ================= res GEMM: D[128 pos][64 out], K=64 =================
    {
        const int rnb = (w & 3) * 16;
        const uint32_t bRh = smaddr(s_wrh) + ((rnb + brow8) * PW + bcol4) * 4;
        const uint32_t bRl = bRh + 64 * PW * 4;
        float racc[4][2][4];
#pragma unroll
        for (int mt = 0; mt < 4; mt++)
#pragma unroll
            for (int nt = 0; nt < 2; nt++)
#pragma unroll
                for (int r = 0; r < 4; r++) racc[mt][nt][r] = 0.f;
#pragma unroll 1
        for (int ks = 0; ks < 4; ks++) {
            const uint32_t off = (uint32_t)(ks * 32);
            uint32_t ah[4][4], al[4][4], bh[4], bl[4];
#pragma unroll
            for (int mt = 0; mt < 4; mt++) {
                ldm_x4(ah[mt], aGh + (uint32_t)(mt * 16 * PW * 4) + off);
                ldm_x4(al[mt], aGl + (uint32_t)(mt * 16 * PW * 4) + off);
            }
            ldm_x4(bh, bRh + off);
            ldm_x4(bl, bRl + off);
#pragma unroll
            for (int mt = 0; mt < 4; mt++)
#pragma unroll
                for (int nt = 0; nt < 2; nt++) {
                    mma_bf16(racc[mt][nt], ah[mt], &bh[nt * 2]);
                    mma_bf16(racc[mt][nt], ah[mt], &bl[nt * 2]);
                    mma_bf16(racc[mt][nt], al[mt], &bh[nt * 2]);
                }
        }
        const float* hb = h_in + (size_t)b * LL * 64;
        float* ho = h_out + (size_t)b * LL * 64;
#pragma unroll
        for (int nt = 0; nt < 2; nt++) {
            int c = rnb + nt * 8 + 2 * lc;
            float2 brv = *(const float2*)&br[c];
#pragma unroll
            for (int mt = 0; mt < 4; mt++)
#pragma unroll
                for (int rh = 0; rh < 2; rh++) {
                    int pos = posb + mt * 16 + lr + rh * 8;
                    size_t gi = (size_t)(l0 + pos) * 64 + c;
                    float2 hv = *(const float2*)&hb[gi];
                    float2 o;
                    o.x = racc[mt][nt][rh * 2 + 0] + brv.x + hv.x;
                    o.y = racc[mt][nt][rh * 2 + 1] + brv.y + hv.y;
                    *(float2*)&ho[gi] = o;
                }
        }
    }

    // ================= skip GEMM: D[128 pos][128 out], K=64 =================
    {
        const int snb = (w & 3) * 32;
        const uint32_t bSh = smaddr(s_wsh) + ((snb + brow8) * PW + bcol4) * 4;
        const uint32_t bSl = smaddr(s_wsl) + ((snb + brow8) * PW + bcol4) * 4;
        float sacc[4][4][4];
#pragma unroll
        for (int mt = 0; mt < 4; mt++)
#pragma unroll
            for (int nt = 0; nt < 4; nt++)
#pragma unroll
                for (int r = 0; r < 4; r++) sacc[mt][nt][r] = 0.f;
#pragma unroll 1
        for (int ks = 0; ks < 4; ks++) {
            const uint32_t off = (uint32_t)(ks * 32);
            uint32_t ah[4][4], al[4][4], bh[2][4], bl[2][4];
#pragma unroll
            for (int mt = 0; mt < 4; mt++) {
                ldm_x4(ah[mt], aGh + (uint32_t)(mt * 16 * PW * 4) + off);
                ldm_x4(al[mt], aGl + (uint32_t)(mt * 16 * PW * 4) + off);
            }
#pragma unroll
            for (int t = 0; t < 2; t++) {
                ldm_x4(bh[t], bSh + (uint32_t)(t * 16 * PW * 4) + off);
                ldm_x4(bl[t], bSl + (uint32_t)(t * 16 * PW * 4) + off);
            }
#pragma unroll
            for (int mt = 0; mt < 4; mt++)
#pragma unroll
                for (int nt = 0; nt < 4; nt++) {
                    const uint32_t* bhp = &bh[nt >> 1][(nt & 1) * 2];
                    const uint32_t* blp = &bl[nt >> 1][(nt & 1) * 2];
                    mma_bf16(sacc[mt][nt], ah[mt], bhp);
                    mma_bf16(sacc[mt][nt], ah[mt], blp);
                    mma_bf16(sacc[mt][nt], al[mt], bhp);
                }
        }
        float* sk = skip + (size_t)b * LL * 128;
#pragma unroll
        for (int nt = 0; nt < 4; nt++) {
            int s = snb + nt * 8 + 2 * lc;
            float2 bsv = *(const float2*)&bs[s];
#pragma unroll
            for (int mt = 0; mt < 4; mt++)
#pragma unroll
                for (int rh = 0; rh < 2; rh++) {
                    int pos = posb + mt * 16 + lr + rh * 8;
                    size_t gi = (size_t)(l0 + pos) * 128 + s;
                    float2 v;
                    v.x = sacc[mt][nt][rh * 2 + 0] + bsv.x;
                    v.y = sacc[mt][nt][rh * 2 + 1] + bsv.y;
                    if (!first) {
                        float2 old = *(const float2*)&sk[gi];
                        v.x += old.x; v.y += old.y;
                    }
                    *(float2*)&sk[gi] = v;
                }
        }
    }
}

// ---------------------------------------------------------------------------
// Post: relu(skip) -> out1 -> relu -> out2 -> per-tile column sums (ldmatrix)
// ---------------------------------------------------------------------------
__global__ __launch_bounds__(256) void post_kernel(
    const float* __restrict__ skip,
    const float* __restrict__ w1g, const float* __restrict__ b1,
    const float* __restrict__ w2g, const float* __restrict__ b2,
    float* __restrict__ partial)
{
    extern __shared__ float sm[];
    float*    s_ts = sm;
    uint32_t* s_rh = (uint32_t*)(sm + 128 * P);
    uint32_t* s_rl = s_rh + 128 * PX;
    uint32_t* s_wh = s_rl + 128 * PX;
    uint32_t* s_wl = s_wh + 128 * PX;

    const int tid  = threadIdx.x;
    const int lane = tid & 31;
    const int w    = tid >> 5;
    const int lr   = lane >> 2;
    const int lc   = lane & 3;
    const int b    = blockIdx.y;
    const int l0   = blockIdx.x * 128;

    const int out0 = (w >> 2) * 64;
    const int pos0 = (w & 3) * 32;

    const int arow8 = (lane & 7) + ((lane >> 3) & 1) * 8;
    const int acol4 = (lane >> 4) * 4;
    const int brow8 = (lane & 7) + ((lane >> 4) & 1) * 8;
    const int bcol4 = ((lane >> 3) & 1) * 4;

    {
        int cp = tid & 63, p0 = tid >> 6;
#pragma unroll
        for (int p = p0; p < 128; p += 4) {
            float2 v = *(const float2*)(skip + ((size_t)b * LL + l0 + p) * 128 + 2 * cp);
            v.x = fmaxf(v.x, 0.f); v.y = fmaxf(v.y, 0.f);
            uint32_t hi, lo; bfsplit2(v.x, v.y, hi, lo);
            s_rh[p * PX + cp] = hi; s_rl[p * PX + cp] = lo;
        }
    }
    for (int e = tid; e < 8192; e += 256) {
        int o = e >> 6, j = e & 63;
        float2 v = *(const float2*)(w1g + o * 128 + 2 * j);
        uint32_t hi, lo; bfsplit2(v.x, v.y, hi, lo);
        s_wh[o * PX + j] = hi; s_wl[o * PX + j] = lo;
    }
    __syncthreads();

    const uint32_t aWh = smaddr(s_wh) + ((out0 + arow8) * PX + acol4) * 4;
    const uint32_t aWl = aWh + 128 * PX * 4;
    const uint32_t bRh = smaddr(s_rh) + ((pos0 + brow8) * PX + bcol4) * 4;
    const uint32_t bRl = bRh + 128 * PX * 4;

    {
        float acc[4][4][4];
#pragma unroll
        for (int mt = 0; mt < 4; mt++)
#pragma unroll
            for (int nt = 0; nt < 4; nt++)
#pragma unroll
                for (int r = 0; r < 4; r++) acc[mt][nt][r] = 0.f;
#pragma unroll 1
        for (int ks = 0; ks < 8; ks++) {
            const uint32_t off = (uint32_t)(ks * 32);
            uint32_t ah[4][4], al[4][4], bh[2][4], bl[2][4];
#pragma unroll
            for (int mt = 0; mt < 4; mt++) {
                ldm_x4(ah[mt], aWh + (uint32_t)(mt * 16 * PX * 4) + off);
                ldm_x4(al[mt], aWl + (uint32_t)(mt * 16 * PX * 4) + off);
            }
#pragma unroll
            for (int t = 0; t < 2; t++) {
                ldm_x4(bh[t], bRh + (uint32_t)(t * 16 * PX * 4) + off);
                ldm_x4(bl[t], bRl + (uint32_t)(t * 16 * PX * 4) + off);
            }
#pragma unroll
            for (int mt = 0; mt < 4; mt++)
#pragma unroll
                for (int nt = 0; nt < 4; nt++) {
                    const uint32_t* bhp = &bh[nt >> 1][(nt & 1) * 2];
                    const uint32_t* blp = &bl[nt >> 1][(nt & 1) * 2];
                    mma_bf16(acc[mt][nt], ah[mt], bhp);
                    mma_bf16(acc[mt][nt], ah[mt], blp);
                    mma_bf16(acc[mt][nt], al[mt], bhp);
                }
        }
#pragma unroll
        for (int mt = 0; mt < 4; mt++) {
            int row = out0 + mt * 16 + lr;
            float bv0 = b1[row], bv8 = b1[row + 8];
#pragma unroll
            for (int nt = 0; nt < 4; nt++) {
                int col = pos0 + nt * 8 + 2 * lc;
                *(float2*)&s_ts[row * P + col] =
                    make_float2(fmaxf(acc[mt][nt][0] + bv0, 0.f), fmaxf(acc[mt][nt][1] + bv0, 0.f));
                *(float2*)&s_ts[(row + 8) * P + col] =
                    make_float2(fmaxf(acc[mt][nt][2] + bv8, 0.f), fmaxf(acc[mt][nt][3] + bv8, 0.f));
            }
        }
    }
    __syncthreads();

    for (int e = tid; e < 8192; e += 256) {
        int o = e >> 6, j = e & 63;
        float2 v = *(const float2*)(w2g + o * 128 + 2 * j);
        uint32_t hi, lo; bfsplit2(v.x, v.y, hi, lo);
        s_wh[o * PX + j] = hi; s_wl[o * PX + j] = lo;
    }
    for (int it = w; it < 256; it += 8) {
        int cp = it >> 2, pos = (it & 3) * 32 + lane;
        float v0 = s_ts[(2 * cp) * P + pos];
        float v1 = s_ts[(2 * cp + 1) * P + pos];
        uint32_t hi, lo; bfsplit2(v0, v1, hi, lo);
        s_rh[pos * PX + cp] = hi; s_rl[pos * PX + cp] = lo;
    }
    __syncthreads();

    {
        float acc[4][4][4];
#pragma unroll
        for (int mt = 0; mt < 4; mt++)
#pragma unroll
            for (int nt = 0; nt < 4; nt++)
#pragma unroll
                for (int r = 0; r < 4; r++) acc[mt][nt][r] = 0.f;
#pragma unroll 1
        for (int ks = 0; ks < 8; ks++) {
            const uint32_t off = (uint32_t)(ks * 32);
            uint32_t ah[4][4], al[4][4], bh[2][4], bl[2][4];
#pragma unroll
            for (int mt = 0; mt < 4; mt++) {
                ldm_x4(ah[mt], aWh + (uint32_t)(mt * 16 * PX * 4) + off);
                ldm_x4(al[mt], aWl + (uint32_t)(mt * 16 * PX * 4) + off);
            }
#pragma unroll
            for (int t = 0; t < 2; t++) {
                ldm_x4(bh[t], bRh + (uint32_t)(t * 16 * PX * 4) + off);
                ldm_x4(bl[t], bRl + (uint32_t)(t * 16 * PX * 4) + off);
            }
#pragma unroll
            for (int mt = 0; mt < 4; mt++)
#pragma unroll
                for (int nt = 0; nt < 4; nt++) {
                    const uint32_t* bhp = &bh[nt >> 1][(nt & 1) * 2];
                    const uint32_t* blp = &bl[nt >> 1][(nt & 1) * 2];
                    mma_bf16(acc[mt][nt], ah[mt], bhp);
                    mma_bf16(acc[mt][nt], ah[mt], blp);
                    mma_bf16(acc[mt][nt], al[mt], bhp);
                }
        }
#pragma unroll
        for (int mt = 0; mt < 4; mt++)
#pragma unroll
            for (int nt = 0; nt < 4; nt++) {
                int row = out0 + mt * 16 + lr;
                int col = pos0 + nt * 8 + 2 * lc;
                *(float2*)&s_ts[row * P + col] = make_float2(acc[mt][nt][0], acc[mt][nt][1]);
                *(float2*)&s_ts[(row + 8) * P + col] = make_float2(acc[mt][nt][2], acc[mt][nt][3]);
            }
    }
    __syncthreads();

    {
        float* sred = (float*)s_rh;
        int c = tid & 127, half = tid >> 7;
        float sum = 0.f;
        for (int p = half * 64; p < half * 64 + 64; p++) sum += s_ts[c * P + p];
        sred[half * 128 + c] = sum;
        __syncthreads();
        if (tid < 128)
            partial[((size_t)b * 32 + blockIdx.x) * 128 + tid] =
                sred[tid] + sred[128 + tid] + 128.f * b2[tid];
    }
}

// ---------------------------------------------------------------------------
__global__ __launch_bounds__(256) void final_kernel(
    const float* __restrict__ partial,
    const float* __restrict__ wf1, const float* __restrict__ bf1,
    const float* __restrict__ wf2, const float* __restrict__ bf2,
    const float* __restrict__ wf3, const float* __restrict__ bf3,
    float* __restrict__ out)
{
    __shared__ float pooled[128];
    __shared__ float z1[256];
    __shared__ float z2[128];
    int b = blockIdx.x, tid = threadIdx.x;
    if (tid < 128) {
        float s = 0.f;
        for (int t = 0; t < 32; t++) s += partial[((size_t)b * 32 + t) * 128 + tid];
        pooled[tid] = s * (1.f / (float)LL);
    }
    __syncthreads();
    {
        float a = bf1[tid];
        for (int c = 0; c < 128; c++) a += wf1[tid * 128 + c] * pooled[c];
        z1[tid] = fmaxf(a, 0.f);
    }
    __syncthreads();
    if (tid < 128) {
        float a = bf2[tid];
        for (int c = 0; c < 256; c++) a += wf2[tid * 256 + c] * z1[c];
        z2[tid] = fmaxf(a, 0.f);
    }
    __syncthreads();
    if (tid < 6) {
        float a = bf3[tid];
        for (int c = 0; c < 128; c++) a += wf3[tid * 128 + c] * z2[c];
        out[b * 6 + tid] = a;
    }
}

// ---------------------------------------------------------------------------
extern "C" void kernel_launch(void* const* d_in, const int* in_sizes, int n_in,
                              void* d_out, int out_size)
{
    const float* x      = (const float*)d_in[0];
    const float* w_in   = (const float*)d_in[1];
    const float* b_in   = (const float*)d_in[2];
    const float* w_dil  = (const float*)d_in[3];
    const float* b_dil  = (const float*)d_in[4];
    const float* w_res  = (const float*)d_in[5];
    const float* b_res  = (const float*)d_in[6];
    const float* w_skip = (const float*)d_in[7];
    const float* b_skip = (const float*)d_in[8];
    const float* w_out1 = (const float*)d_in[9];
    const float* b_out1 = (const float*)d_in[10];
    const float* w_out2 = (const float*)d_in[11];
    const float* b_out2 = (const float*)d_in[12];
    const float* w_fc1  = (const float*)d_in[13];
    const float* b_fc1  = (const float*)d_in[14];
    const float* w_fc2  = (const float*)d_in[15];
    const float* b_fc2  = (const float*)d_in[16];
    const float* w_fc3  = (const float*)d_in[17];
    const float* b_fc3  = (const float*)d_in[18];
    float* out = (float*)d_out;

    float *h0, *h1, *skipb, *partial;
    uint32_t *wdch, *wdcl, *wrh, *wrl, *wsh, *wsl;
    cudaGetSymbolAddress((void**)&h0,      g_h0);
    cudaGetSymbolAddress((void**)&h1,      g_h1);
    cudaGetSymbolAddress((void**)&skipb,   g_skip);
    cudaGetSymbolAddress((void**)&partial, g_partial);
    cudaGetSymbolAddress((void**)&wdch,    g_wdch);
    cudaGetSymbolAddress((void**)&wdcl,    g_wdcl);
    cudaGetSymbolAddress((void**)&wrh,     g_wrh);
    cudaGetSymbolAddress((void**)&wrl,     g_wrl);
    cudaGetSymbolAddress((void**)&wsh,     g_wsh);
    cudaGetSymbolAddress((void**)&wsl,     g_wsl);

    const int BLOCK_SMEM = (2 * 128 * PX + 2 * 128 * PW) * 4;    // 106,496 B
    const int POST_SMEM  = (128 * P + 4 * 128 * PX) * 4;         // 206,848 B
    cudaFuncSetAttribute(block_kernel, cudaFuncAttributeMaxDynamicSharedMemorySize, BLOCK_SMEM);
    cudaFuncSetAttribute(post_kernel,  cudaFuncAttributeMaxDynamicSharedMemorySize, POST_SMEM);

    split_kernel<<<(NBLK * 14336 + 255) / 256, 256>>>(w_dil, w_res, w_skip);
    proj_kernel<<<(BB * LL * 64) / 256, 256>>>(x, w_in, b_in, h0);

    dim3 grid(LL / 128, BB);
    const float* hin = h0;
    float* hout = h1;
    for (int i = 0; i < NBLK; ++i) {
        int d = 1 << (i % 10);
        block_kernel<<<grid, 256, BLOCK_SMEM>>>(
            hin, hout, skipb,
            wdch + i * 8192, wdcl + i * 8192, b_dil + i * 128,
            wrh + i * 2048,  wrl + i * 2048,  b_res + i * 64,
            wsh + i * 4096,  wsl + i * 4096,  b_skip + i * 128,
            d, (i == 0) ? 1 : 0);
        const float* t = hout;
        hout = (float*)hin;
        hin = t;
    }

    post_kernel<<<grid, 256, POST_SMEM>>>(skipb, w_out1, b_out1, w_out2, b_out2, partial);
    final_kernel<<<BB, 256>>>(partial, w_fc1, b_fc1, w_fc2, b_fc2, w_fc3, b_fc3, out);
}

// round 13
// speedup vs baseline: 1.4922x; 1.0556x over previous
#include <cuda_runtime.h>
#include <cuda_bf16.h>
#include <math.h>
#include <stdint.h>

#define BB   64
#define LL   4096
#define RC   64
#define SC   128
#define NBLK 30
#define P    132    // post_kernel fp32 staging pitch
#define PX   68     // X pitch (words), 68 mod 32 == 4 -> conflict-free
#define PW   36     // weight/G pitch (words), 36 mod 32 == 4

// Static device scratch (allocation-free contract)
__device__ float g_h0[(size_t)BB * LL * RC];
__device__ float g_h1[(size_t)BB * LL * RC];
__device__ float g_skip[(size_t)BB * LL * SC];
__device__ float g_partial[(size_t)BB * 32 * SC];
// pre-split weights (bf16x2 hi/lo pair-words)
__device__ uint32_t g_wdch[NBLK * 8192], g_wdcl[NBLK * 8192];
__device__ uint32_t g_wrh[NBLK * 2048], g_wrl[NBLK * 2048];
__device__ uint32_t g_wsh[NBLK * 4096], g_wsl[NBLK * 4096];

// ---------------------------------------------------------------------------
__device__ __forceinline__ void bfsplit2(float v0, float v1, uint32_t& hi, uint32_t& lo) {
    __nv_bfloat16 h0 = __float2bfloat16_rn(v0);
    __nv_bfloat16 h1 = __float2bfloat16_rn(v1);
    float r0 = v0 - __bfloat162float(h0);
    float r1 = v1 - __bfloat162float(h1);
    __nv_bfloat16 l0 = __float2bfloat16_rn(r0);
    __nv_bfloat16 l1 = __float2bfloat16_rn(r1);
    hi = (uint32_t)__bfloat16_as_ushort(h0) | ((uint32_t)__bfloat16_as_ushort(h1) << 16);
    lo = (uint32_t)__bfloat16_as_ushort(l0) | ((uint32_t)__bfloat16_as_ushort(l1) << 16);
}
__device__ __forceinline__ void bfsplit1(float v, uint16_t& hi, uint16_t& lo) {
    __nv_bfloat16 h = __float2bfloat16_rn(v);
    float r = v - __bfloat162float(h);
    hi = __bfloat16_as_ushort(h);
    lo = __bfloat16_as_ushort(__float2bfloat16_rn(r));
}

__device__ __forceinline__ void mma_bf16(float* d, const uint32_t* a, const uint32_t* b) {
    asm volatile(
        "mma.sync.aligned.m16n8k16.row.col.f32.bf16.bf16.f32 "
        "{%0,%1,%2,%3}, {%4,%5,%6,%7}, {%8,%9}, {%0,%1,%2,%3};"
        : "+f"(d[0]), "+f"(d[1]), "+f"(d[2]), "+f"(d[3])
        : "r"(a[0]), "r"(a[1]), "r"(a[2]), "r"(a[3]), "r"(b[0]), "r"(b[1]));
}

__device__ __forceinline__ uint32_t smaddr(const void* p) {
    return (uint32_t)__cvta_generic_to_shared(p);
}
__device__ __forceinline__ void ldm_x4(uint32_t* r, uint32_t addr) {
    asm volatile("ldmatrix.sync.aligned.m8n8.x4.shared.b16 {%0,%1,%2,%3}, [%4];"
        : "=r"(r[0]), "=r"(r[1]), "=r"(r[2]), "=r"(r[3]) : "r"(addr));
}
__device__ __forceinline__ void cp16(uint32_t dst, const void* src) {
    asm volatile("cp.async.cg.shared.global [%0], [%1], 16;" :: "r"(dst), "l"(src));
}
__device__ __forceinline__ void cp_commit() {
    asm volatile("cp.async.commit_group;");
}
__device__ __forceinline__ void cp_wait0() {
    asm volatile("cp.async.wait_group 0;");
}

__device__ __forceinline__ float fast_gate(float t, float s) {
    float th = 2.f * __fdividef(1.f, 1.f + __expf(-2.f * t)) - 1.f;
    float sg = __fdividef(1.f, 1.f + __expf(-s));
    return th * sg;
}

// ---------------------------------------------------------------------------
__global__ __launch_bounds__(256) void split_kernel(
    const float* __restrict__ wd, const float* __restrict__ wr,
    const float* __restrict__ ws)
{
    int id = blockIdx.x * 256 + threadIdx.x;
    if (id >= NBLK * 14336) return;
    int i = id / 14336, r = id % 14336;
    if (r < 8192) {
        int op = r >> 6, j = r & 63;
        int o = ((op & 1) << 6) + (op >> 1);          // permuted source row
        float2 v = *(const float2*)(wd + (size_t)i * 16384 + o * 128 + 2 * j);
        uint32_t hi, lo; bfsplit2(v.x, v.y, hi, lo);
        g_wdch[i * 8192 + r] = hi; g_wdcl[i * 8192 + r] = lo;
    } else if (r < 10240) {
        int off = r - 8192;
        float2 v = *(const float2*)(wr + (size_t)i * 4096 + 2 * off);
        uint32_t hi, lo; bfsplit2(v.x, v.y, hi, lo);
        g_wrh[i * 2048 + off] = hi; g_wrl[i * 2048 + off] = lo;
    } else {
        int off = r - 10240;
        float2 v = *(const float2*)(ws + (size_t)i * 8192 + 2 * off);
        uint32_t hi, lo; bfsplit2(v.x, v.y, hi, lo);
        g_wsh[i * 4096 + off] = hi; g_wsl[i * 4096 + off] = lo;
    }
}

// ---------------------------------------------------------------------------
__global__ __launch_bounds__(256) void proj_kernel(
    const float* __restrict__ x, const float* __restrict__ w_in,
    const float* __restrict__ b_in, float* __restrict__ h)
{
    int idx = blockIdx.x * 256 + threadIdx.x;
    int oc = idx & 63;
    int l  = (idx >> 6) & (LL - 1);
    int b  = idx >> 18;
    float acc = b_in[oc];
#pragma unroll
    for (int c = 0; c < 8; ++c)
        acc += w_in[oc * 8 + c] * x[((size_t)(b * 8 + c)) * LL + l];
    h[(size_t)idx] = acc;
}

// ---------------------------------------------------------------------------
// One WaveNet block. 256 threads, 2 CTAs/SM, ldmatrix fragments,
// cp.async weight staging overlapped with X staging / gate computation.
// ---------------------------------------------------------------------------
__global__ __launch_bounds__(256, 2) void block_kernel(
    const float* __restrict__ h_in, float* __restrict__ h_out,
    float* __restrict__ skip,
    const uint32_t* __restrict__ wdch, const uint32_t* __restrict__ wdcl,
    const float* __restrict__ bd,
    const uint32_t* __restrict__ wrh, const uint32_t* __restrict__ wrl,
    const float* __restrict__ br,
    const uint32_t* __restrict__ wsh, const uint32_t* __restrict__ wsl,
    const float* __restrict__ bs,
    int d, int first)
{
    extern __shared__ uint32_t smw[];
    // region A: X during conv; G + ws-lo after
    uint32_t* s_xh = smw;                         // [128 pos][PX]
    uint32_t* s_xl = smw + 128 * PX;
    uint32_t* s_gh  = smw;                        // [128 pos][PW] (overlay)
    uint32_t* s_gl  = smw + 128 * PW;
    uint32_t* s_wsl = smw + 2 * 128 * PW;         // [128][PW]    (overlay)
    // region B: conv-W half during conv; wr + ws-hi after
    uint32_t* s_cwh = smw + 2 * 128 * PX;         // [128 o'][PW]
    uint32_t* s_cwl = s_cwh + 128 * PW;
    uint32_t* s_wrh = s_cwh;                      // [64][PW]     (overlay)
    uint32_t* s_wrl = s_cwh + 64 * PW;
    uint32_t* s_wsh = s_cwh + 128 * PW;           // [128][PW]    (overlay)

    const int tid  = threadIdx.x;
    const int lane = tid & 31;
    const int w    = tid >> 5;      // warp 0..7
    const int lr   = lane >> 2;     // 0..7
    const int lc   = lane & 3;      // 0..3
    const int b    = blockIdx.y;
    const int l0   = blockIdx.x * 128;

    // ldmatrix lane-address components
    const int arow8 = (lane & 7) + ((lane >> 3) & 1) * 8;
    const int acol4 = (lane >> 4) * 4;
    const int brow8 = (lane & 7) + ((lane >> 4) & 1) * 8;
    const int bcol4 = ((lane >> 3) & 1) * 4;

    // ---- issue conv W half-0 cp.async FIRST (overlaps X staging) ----
    {
        const uint32_t dh = smaddr(s_cwh), dl = smaddr(s_cwl);
        for (int e = tid; e < 1024; e += 256) {
            int row = e >> 3, q = e & 7;
            cp16(dh + (row * PW + q * 4) * 4, &wdch[row * 64 + q * 4]);
            cp16(dl + (row * PW + q * 4) * 4, &wdcl[row * 64 + q * 4]);
        }
        cp_commit();
    }

    // ---- stage X split (long LDG chain, hides the W copy) ----
    {
        int c = tid & 63, p0 = tid >> 6;
        const float* hb = h_in + (size_t)b * LL * 64;
#pragma unroll
        for (int g = 0; g < 4; g++) {
            float curv[8], delv[8];
#pragma unroll
            for (int i = 0; i < 8; i++) {
                int p = p0 + (g * 8 + i) * 4;
                int l = l0 + p, ld = l - d;
                curv[i] = hb[(size_t)l * 64 + c];
                delv[i] = (ld >= 0) ? hb[(size_t)ld * 64 + c] : 0.f;
            }
#pragma unroll
            for (int i = 0; i < 8; i++) {
                int p = p0 + (g * 8 + i) * 4;
                uint32_t hi, lo; bfsplit2(delv[i], curv[i], hi, lo);
                s_xh[p * PX + c] = hi; s_xl[p * PX + c] = lo;
            }
        }
    }
    cp_wait0();
    __syncthreads();   // [1]

    // ================= conv GEMM: D[128 pos][128 o'], K=128 =================
    const int posb = (w >> 2) * 64;
    const int nb   = (w & 3) * 32;
    float acc[4][4][4];
#pragma unroll
    for (int mt = 0; mt < 4; mt++)
#pragma unroll
        for (int nt = 0; nt < 4; nt++)
#pragma unroll
            for (int r = 0; r < 4; r++) acc[mt][nt][r] = 0.f;

    const uint32_t aXh = smaddr(s_xh) + ((posb + arow8) * PX + acol4) * 4;
    const uint32_t aXl = aXh + 128 * PX * 4;
    const uint32_t bCh = smaddr(s_cwh) + ((nb + brow8) * PW + bcol4) * 4;
    const uint32_t bCl = bCh + 128 * PW * 4;

#pragma unroll 1
    for (int half = 0; half < 2; half++) {
        if (half == 1) {
            __syncthreads();
            const uint32_t dh = smaddr(s_cwh), dl = smaddr(s_cwl);
            for (int e = tid; e < 1024; e += 256) {
                int row = e >> 3, q = e & 7;
                cp16(dh + (row * PW + q * 4) * 4, &wdch[row * 64 + 32 + q * 4]);
                cp16(dl + (row * PW + q * 4) * 4, &wdcl[row * 64 + 32 + q * 4]);
            }
            cp_commit();
            cp_wait0();
            __syncthreads();
        }
#pragma unroll 1
        for (int ksl = 0; ksl < 4; ksl++) {
            const uint32_t offX = (uint32_t)((half * 4 + ksl) * 32);
            const uint32_t offW = (uint32_t)(ksl * 32);
            uint32_t ah[4][4], al[4][4], bh[2][4], bl[2][4];
#pragma unroll
            for (int mt = 0; mt < 4; mt++) {
                ldm_x4(ah[mt], aXh + (uint32_t)(mt * 16 * PX * 4) + offX);
                ldm_x4(al[mt], aXl + (uint32_t)(mt * 16 * PX * 4) + offX);
            }
#pragma unroll
            for (int t = 0; t < 2; t++) {
                ldm_x4(bh[t], bCh + (uint32_t)(t * 16 * PW * 4) + offW);
                ldm_x4(bl[t], bCl + (uint32_t)(t * 16 * PW * 4) + offW);
            }
#pragma unroll
            for (int mt = 0; mt < 4; mt++)
#pragma unroll
                for (int nt = 0; nt < 4; nt++) {
                    const uint32_t* bhp = &bh[nt >> 1][(nt & 1) * 2];
                    const uint32_t* blp = &bl[nt >> 1][(nt & 1) * 2];
                    mma_bf16(acc[mt][nt], ah[mt], bhp);
                    mma_bf16(acc[mt][nt], ah[mt], blp);
                    mma_bf16(acc[mt][nt], al[mt], bhp);
                }
        }
    }
    __syncthreads();   // [2] X dead, conv W dead

    // ---- issue wr/ws cp.async, then compute gate under the copy ----
    {
        const uint32_t dwrh = smaddr(s_wrh), dwrl = smaddr(s_wrl);
        const uint32_t dwsh = smaddr(s_wsh), dwsl = smaddr(s_wsl);
        for (int e = tid; e < 512; e += 256) {
            int row = e >> 3, q = e & 7;
            cp16(dwrh + (row * PW + q * 4) * 4, &wrh[row * 32 + q * 4]);
            cp16(dwrl + (row * PW + q * 4) * 4, &wrl[row * 32 + q * 4]);
        }
        for (int e = tid; e < 1024; e += 256) {
            int row = e >> 3, q = e & 7;
            cp16(dwsh + (row * PW + q * 4) * 4, &wsh[row * 32 + q * 4]);
            cp16(dwsl + (row * PW + q * 4) * 4, &wsl[row * 32 + q * 4]);
        }
        cp_commit();
    }
    // ---- register gate -> G (overlaps weight copy) ----
    {
        uint16_t* gh16 = (uint16_t*)s_gh;
        uint16_t* gl16 = (uint16_t*)s_gl;
#pragma unroll
        for (int nt = 0; nt < 4; nt++) {
            int j = (nb >> 1) + nt * 4 + lc;
            float bt = bd[j], bsg = bd[64 + j];
#pragma unroll
            for (int mt = 0; mt < 4; mt++)
#pragma unroll
                for (int rh = 0; rh < 2; rh++) {
                    float t = acc[mt][nt][rh * 2 + 0] + bt;
                    float s = acc[mt][nt][rh * 2 + 1] + bsg;
                    float g = fast_gate(t, s);
                    int pos = posb + mt * 16 + lr + rh * 8;
                    uint16_t hi, lo; bfsplit1(g, hi, lo);
                    int wi = (pos * PW + (j >> 1)) * 2 + (j & 1);
                    gh16[wi] = hi; gl16[wi] = lo;
                }
        }
    }
    cp_wait0();
    __syncthreads();   // [3]

    const uint32_t aGh = smaddr(s_gh) + ((posb + arow8) * PW + acol4) * 4;
    const uint32_t aGl = aGh + 128 * PW * 4;

    // ================= res GEMM: D[128 pos][64 out], K=64 =================
    {
        const int rnb = (w & 3) * 16;
        const uint32_t bRh = smaddr(s_wrh) + ((rnb + brow8) * PW + bcol4) * 4;
        const uint32_t bRl = bRh + 64 * PW * 4;
        float racc[4][2][4];
#pragma unroll
        for (int mt = 0; mt < 4; mt++)
#pragma unroll
            for (int nt = 0; nt < 2; nt++)
#pragma unroll
                for (int r = 0; r < 4; r++) racc[mt][nt][r] = 0.f;
#pragma unroll 1
        for (int ks = 0; ks < 4; ks++) {
            const uint32_t off = (uint32_t)(ks * 32);
            uint32_t ah[4][4], al[4][4], bh[4], bl[4];
#pragma unroll
            for (int mt = 0; mt < 4; mt++) {
                ldm_x4(ah[mt], aGh + (uint32_t)(mt * 16 * PW * 4) + off);
                ldm_x4(al[mt], aGl + (uint32_t)(mt * 16 * PW * 4) + off);
            }
            ldm_x4(bh, bRh + off);
            ldm_x4(bl, bRl + off);
#pragma unroll
            for (int mt = 0; mt < 4; mt++)
#pragma unroll
                for (int nt = 0; nt < 2; nt++) {
                    mma_bf16(racc[mt][nt], ah[mt], &bh[nt * 2]);
                    mma_bf16(racc[mt][nt], ah[mt], &bl[nt * 2]);
                    mma_bf16(racc[mt][nt], al[mt], &bh[nt * 2]);
                }
        }
        const float* hb = h_in + (size_t)b * LL * 64;
        float* ho = h_out + (size_t)b * LL * 64;
#pragma unroll
        for (int nt = 0; nt < 2; nt++) {
            int c = rnb + nt * 8 + 2 * lc;
            float2 brv = *(const float2*)&br[c];
#pragma unroll
            for (int mt = 0; mt < 4; mt++)
#pragma unroll
                for (int rh = 0; rh < 2; rh++) {
                    int pos = posb + mt * 16 + lr + rh * 8;
                    size_t gi = (size_t)(l0 + pos) * 64 + c;
                    float2 hv = *(const float2*)&hb[gi];
                    float2 o;
                    o.x = racc[mt][nt][rh * 2 + 0] + brv.x + hv.x;
                    o.y = racc[mt][nt][rh * 2 + 1] + brv.y + hv.y;
                    *(float2*)&ho[gi] = o;
                }
        }
    }

    // ================= skip GEMM: D[128 pos][128 out], K=64 =================
    {
        const int snb = (w & 3) * 32;
        const uint32_t bSh = smaddr(s_wsh) + ((snb + brow8) * PW + bcol4) * 4;
        const uint32_t bSl = smaddr(s_wsl) + ((snb + brow8) * PW + bcol4) * 4;
        float sacc[4][4][4];
#pragma unroll
        for (int mt = 0; mt < 4; mt++)
#pragma unroll
            for (int nt = 0; nt < 4; nt++)
#pragma unroll
                for (int r = 0; r < 4; r++) sacc[mt][nt][r] = 0.f;
#pragma unroll 1
        for (int ks = 0; ks < 4; ks++) {
            const uint32_t off = (uint32_t)(ks * 32);
            uint32_t ah[4][4], al[4][4], bh[2][4], bl[2][4];
#pragma unroll
            for (int mt = 0; mt < 4; mt++) {
                ldm_x4(ah[mt], aGh + (uint32_t)(mt * 16 * PW * 4) + off);
                ldm_x4(al[mt], aGl + (uint32_t)(mt * 16 * PW * 4) + off);
            }
#pragma unroll
            for (int t = 0; t < 2; t++) {
                ldm_x4(bh[t], bSh + (uint32_t)(t * 16 * PW * 4) + off);
                ldm_x4(bl[t], bSl + (uint32_t)(t * 16 * PW * 4) + off);
            }
#pragma unroll
            for (int mt = 0; mt < 4; mt++)
#pragma unroll
                for (int nt = 0; nt < 4; nt++) {
                    const uint32_t* bhp = &bh[nt >> 1][(nt & 1) * 2];
                    const uint32_t* blp = &bl[nt >> 1][(nt & 1) * 2];
                    mma_bf16(sacc[mt][nt], ah[mt], bhp);
                    mma_bf16(sacc[mt][nt], ah[mt], blp);
                    mma_bf16(sacc[mt][nt], al[mt], bhp);
                }
        }
        float* sk = skip + (size_t)b * LL * 128;
#pragma unroll
        for (int nt = 0; nt < 4; nt++) {
            int s = snb + nt * 8 + 2 * lc;
            float2 bsv = *(const float2*)&bs[s];
#pragma unroll
            for (int mt = 0; mt < 4; mt++)
#pragma unroll
                for (int rh = 0; rh < 2; rh++) {
                    int pos = posb + mt * 16 + lr + rh * 8;
                    size_t gi = (size_t)(l0 + pos) * 128 + s;
                    float2 v;
                    v.x = sacc[mt][nt][rh * 2 + 0] + bsv.x;
                    v.y = sacc[mt][nt][rh * 2 + 1] + bsv.y;
                    if (!first) {
                        float2 old = *(const float2*)&sk[gi];
                        v.x += old.x; v.y += old.y;
                    }
                    *(float2*)&sk[gi] = v;
                }
        }
    }
}

// ---------------------------------------------------------------------------
// Post: relu(skip) -> out1 -> relu -> out2 -> per-tile column sums (ldmatrix)
// ---------------------------------------------------------------------------
__global__ __launch_bounds__(256) void post_kernel(
    const float* __restrict__ skip,
    const float* __restrict__ w1g, const float* __restrict__ b1,
    const float* __restrict__ w2g, const float* __restrict__ b2,
    float* __restrict__ partial)
{
    extern __shared__ float sm[];
    float*    s_ts = sm;
    uint32_t* s_rh = (uint32_t*)(sm + 128 * P);
    uint32_t* s_rl = s_rh + 128 * PX;
    uint32_t* s_wh = s_rl + 128 * PX;
    uint32_t* s_wl = s_wh + 128 * PX;

    const int tid  = threadIdx.x;
    const int lane = tid & 31;
    const int w    = tid >> 5;
    const int lr   = lane >> 2;
    const int lc   = lane & 3;
    const int b    = blockIdx.y;
    const int l0   = blockIdx.x * 128;

    const int out0 = (w >> 2) * 64;
    const int pos0 = (w & 3) * 32;

    const int arow8 = (lane & 7) + ((lane >> 3) & 1) * 8;
    const int acol4 = (lane >> 4) * 4;
    const int brow8 = (lane & 7) + ((lane >> 4) & 1) * 8;
    const int bcol4 = ((lane >> 3) & 1) * 4;

    {
        int cp = tid & 63, p0 = tid >> 6;
#pragma unroll
        for (int p = p0; p < 128; p += 4) {
            float2 v = *(const float2*)(skip + ((size_t)b * LL + l0 + p) * 128 + 2 * cp);
            v.x = fmaxf(v.x, 0.f); v.y = fmaxf(v.y, 0.f);
            uint32_t hi, lo; bfsplit2(v.x, v.y, hi, lo);
            s_rh[p * PX + cp] = hi; s_rl[p * PX + cp] = lo;
        }
    }
    for (int e = tid; e < 8192; e += 256) {
        int o = e >> 6, j = e & 63;
        float2 v = *(const float2*)(w1g + o * 128 + 2 * j);
        uint32_t hi, lo; bfsplit2(v.x, v.y, hi, lo);
        s_wh[o * PX + j] = hi; s_wl[o * PX + j] = lo;
    }
    __syncthreads();

    const uint32_t aWh = smaddr(s_wh) + ((out0 + arow8) * PX + acol4) * 4;
    const uint32_t aWl = aWh + 128 * PX * 4;
    const uint32_t bRh = smaddr(s_rh) + ((pos0 + brow8) * PX + bcol4) * 4;
    const uint32_t bRl = bRh + 128 * PX * 4;

    {
        float acc[4][4][4];
#pragma unroll
        for (int mt = 0; mt < 4; mt++)
#pragma unroll
            for (int nt = 0; nt < 4; nt++)
#pragma unroll
                for (int r = 0; r < 4; r++) acc[mt][nt][r] = 0.f;
#pragma unroll 1
        for (int ks = 0; ks < 8; ks++) {
            const uint32_t off = (uint32_t)(ks * 32);
            uint32_t ah[4][4], al[4][4], bh[2][4], bl[2][4];
#pragma unroll
            for (int mt = 0; mt < 4; mt++) {
                ldm_x4(ah[mt], aWh + (uint32_t)(mt * 16 * PX * 4) + off);
                ldm_x4(al[mt], aWl + (uint32_t)(mt * 16 * PX * 4) + off);
            }
#pragma unroll
            for (int t = 0; t < 2; t++) {
                ldm_x4(bh[t], bRh + (uint32_t)(t * 16 * PX * 4) + off);
                ldm_x4(bl[t], bRl + (uint32_t)(t * 16 * PX * 4) + off);
            }
#pragma unroll
            for (int mt = 0; mt < 4; mt++)
#pragma unroll
                for (int nt = 0; nt < 4; nt++) {
                    const uint32_t* bhp = &bh[nt >> 1][(nt & 1) * 2];
                    const uint32_t* blp = &bl[nt >> 1][(nt & 1) * 2];
                    mma_bf16(acc[mt][nt], ah[mt], bhp);
                    mma_bf16(acc[mt][nt], ah[mt], blp);
                    mma_bf16(acc[mt][nt], al[mt], bhp);
                }
        }
#pragma unroll
        for (int mt = 0; mt < 4; mt++) {
            int row = out0 + mt * 16 + lr;
            float bv0 = b1[row], bv8 = b1[row + 8];
#pragma unroll
            for (int nt = 0; nt < 4; nt++) {
                int col = pos0 + nt * 8 + 2 * lc;
                *(float2*)&s_ts[row * P + col] =
                    make_float2(fmaxf(acc[mt][nt][0] + bv0, 0.f), fmaxf(acc[mt][nt][1] + bv0, 0.f));
                *(float2*)&s_ts[(row + 8) * P + col] =
                    make_float2(fmaxf(acc[mt][nt][2] + bv8, 0.f), fmaxf(acc[mt][nt][3] + bv8, 0.f));
            }
        }
    }
    __syncthreads();

    for (int e = tid; e < 8192; e += 256) {
        int o = e >> 6, j = e & 63;
        float2 v = *(const float2*)(w2g + o * 128 + 2 * j);
        uint32_t hi, lo; bfsplit2(v.x, v.y, hi, lo);
        s_wh[o * PX + j] = hi; s_wl[o * PX + j] = lo;
    }
    for (int it = w; it < 256; it += 8) {
        int cp = it >> 2, pos = (it & 3) * 32 + lane;
        float v0 = s_ts[(2 * cp) * P + pos];
        float v1 = s_ts[(2 * cp + 1) * P + pos];
        uint32_t hi, lo; bfsplit2(v0, v1, hi, lo);
        s_rh[pos * PX + cp] = hi; s_rl[pos * PX + cp] = lo;
    }
    __syncthreads();

    {
        float acc[4][4][4];
#pragma unroll
        for (int mt = 0; mt < 4; mt++)
#pragma unroll
            for (int nt = 0; nt < 4; nt++)
#pragma unroll
                for (int r = 0; r < 4; r++) acc[mt][nt][r] = 0.f;
#pragma unroll 1
        for (int ks = 0; ks < 8; ks++) {
            const uint32_t off = (uint32_t)(ks * 32);
            uint32_t ah[4][4], al[4][4], bh[2][4], bl[2][4];
#pragma unroll
            for (int mt = 0; mt < 4; mt++) {
                ldm_x4(ah[mt], aWh + (uint32_t)(mt * 16 * PX * 4) + off);
                ldm_x4(al[mt], aWl + (uint32_t)(mt * 16 * PX * 4) + off);
            }
#pragma unroll
            for (int t = 0; t < 2; t++) {
                ldm_x4(bh[t], bRh + (uint32_t)(t * 16 * PX * 4) + off);
                ldm_x4(bl[t], bRl + (uint32_t)(t * 16 * PX * 4) + off);
            }
#pragma unroll
            for (int mt = 0; mt < 4; mt++)
#pragma unroll
                for (int nt = 0; nt < 4; nt++) {
                    const uint32_t* bhp = &bh[nt >> 1][(nt & 1) * 2];
                    const uint32_t* blp = &bl[nt >> 1][(nt & 1) * 2];
                    mma_bf16(acc[mt][nt], ah[mt], bhp);
                    mma_bf16(acc[mt][nt], ah[mt], blp);
                    mma_bf16(acc[mt][nt], al[mt], bhp);
                }
        }
#pragma unroll
        for (int mt = 0; mt < 4; mt++)
#pragma unroll
            for (int nt = 0; nt < 4; nt++) {
                int row = out0 + mt * 16 + lr;
                int col = pos0 + nt * 8 + 2 * lc;
                *(float2*)&s_ts[row * P + col] = make_float2(acc[mt][nt][0], acc[mt][nt][1]);
                *(float2*)&s_ts[(row + 8) * P + col] = make_float2(acc[mt][nt][2], acc[mt][nt][3]);
            }
    }
    __syncthreads();

    {
        float* sred = (float*)s_rh;
        int c = tid & 127, half = tid >> 7;
        float sum = 0.f;
        for (int p = half * 64; p < half * 64 + 64; p++) sum += s_ts[c * P + p];
        sred[half * 128 + c] = sum;
        __syncthreads();
        if (tid < 128)
            partial[((size_t)b * 32 + blockIdx.x) * 128 + tid] =
                sred[tid] + sred[128 + tid] + 128.f * b2[tid];
    }
}

// ---------------------------------------------------------------------------
__global__ __launch_bounds__(256) void final_kernel(
    const float* __restrict__ partial,
    const float* __restrict__ wf1, const float* __restrict__ bf1,
    const float* __restrict__ wf2, const float* __restrict__ bf2,
    const float* __restrict__ wf3, const float* __restrict__ bf3,
    float* __restrict__ out)
{
    __shared__ float pooled[128];
    __shared__ float z1[256];
    __shared__ float z2[128];
    int b = blockIdx.x, tid = threadIdx.x;
    if (tid < 128) {
        float s = 0.f;
        for (int t = 0; t < 32; t++) s += partial[((size_t)b * 32 + t) * 128 + tid];
        pooled[tid] = s * (1.f / (float)LL);
    }
    __syncthreads();
    {
        float a = bf1[tid];
        for (int c = 0; c < 128; c++) a += wf1[tid * 128 + c] * pooled[c];
        z1[tid] = fmaxf(a, 0.f);
    }
    __syncthreads();
    if (tid < 128) {
        float a = bf2[tid];
        for (int c = 0; c < 256; c++) a += wf2[tid * 256 + c] * z1[c];
        z2[tid] = fmaxf(a, 0.f);
    }
    __syncthreads();
    if (tid < 6) {
        float a = bf3[tid];
        for (int c = 0; c < 128; c++) a += wf3[tid * 128 + c] * z2[c];
        out[b * 6 + tid] = a;
    }
}

// ---------------------------------------------------------------------------
extern "C" void kernel_launch(void* const* d_in, const int* in_sizes, int n_in,
                              void* d_out, int out_size)
{
    const float* x      = (const float*)d_in[0];
    const float* w_in   = (const float*)d_in[1];
    const float* b_in   = (const float*)d_in[2];
    const float* w_dil  = (const float*)d_in[3];
    const float* b_dil  = (const float*)d_in[4];
    const float* w_res  = (const float*)d_in[5];
    const float* b_res  = (const float*)d_in[6];
    const float* w_skip = (const float*)d_in[7];
    const float* b_skip = (const float*)d_in[8];
    const float* w_out1 = (const float*)d_in[9];
    const float* b_out1 = (const float*)d_in[10];
    const float* w_out2 = (const float*)d_in[11];
    const float* b_out2 = (const float*)d_in[12];
    const float* w_fc1  = (const float*)d_in[13];
    const float* b_fc1  = (const float*)d_in[14];
    const float* w_fc2  = (const float*)d_in[15];
    const float* b_fc2  = (const float*)d_in[16];
    const float* w_fc3  = (const float*)d_in[17];
    const float* b_fc3  = (const float*)d_in[18];
    float* out = (float*)d_out;

    float *h0, *h1, *skipb, *partial;
    uint32_t *wdch, *wdcl, *wrh, *wrl, *wsh, *wsl;
    cudaGetSymbolAddress((void**)&h0,      g_h0);
    cudaGetSymbolAddress((void**)&h1,      g_h1);
    cudaGetSymbolAddress((void**)&skipb,   g_skip);
    cudaGetSymbolAddress((void**)&partial, g_partial);
    cudaGetSymbolAddress((void**)&wdch,    g_wdch);
    cudaGetSymbolAddress((void**)&wdcl,    g_wdcl);
    cudaGetSymbolAddress((void**)&wrh,     g_wrh);
    cudaGetSymbolAddress((void**)&wrl,     g_wrl);
    cudaGetSymbolAddress((void**)&wsh,     g_wsh);
    cudaGetSymbolAddress((void**)&wsl,     g_wsl);

    const int BLOCK_SMEM = (2 * 128 * PX + 2 * 128 * PW) * 4;    // 106,496 B
    const int POST_SMEM  = (128 * P + 4 * 128 * PX) * 4;         // 206,848 B
    cudaFuncSetAttribute(block_kernel, cudaFuncAttributeMaxDynamicSharedMemorySize, BLOCK_SMEM);
    cudaFuncSetAttribute(post_kernel,  cudaFuncAttributeMaxDynamicSharedMemorySize, POST_SMEM);

    split_kernel<<<(NBLK * 14336 + 255) / 256, 256>>>(w_dil, w_res, w_skip);
    proj_kernel<<<(BB * LL * 64) / 256, 256>>>(x, w_in, b_in, h0);

    dim3 grid(LL / 128, BB);
    const float* hin = h0;
    float* hout = h1;
    for (int i = 0; i < NBLK; ++i) {
        int d = 1 << (i % 10);
        block_kernel<<<grid, 256, BLOCK_SMEM>>>(
            hin, hout, skipb,
            wdch + i * 8192, wdcl + i * 8192, b_dil + i * 128,
            wrh + i * 2048,  wrl + i * 2048,  b_res + i * 64,
            wsh + i * 4096,  wsl + i * 4096,  b_skip + i * 128,
            d, (i == 0) ? 1 : 0);
        const float* t = hout;
        hout = (float*)hin;
        hin = t;
    }

    post_kernel<<<grid, 256, POST_SMEM>>>(skipb, w_out1, b_out1, w_out2, b_out2, partial);
    final_kernel<<<BB, 256>>>(partial, w_fc1, b_fc1, w_fc2, b_fc2, w_fc3, b_fc3, out);
}

// round 14
// speedup vs baseline: 1.5488x; 1.0379x over previous
#include <cuda_runtime.h>
#include <cuda_bf16.h>
#include <math.h>
#include <stdint.h>

#define BB   64
#define LL   4096
#define RC   64
#define SC   128
#define NBLK 30
#define P    132    // post_kernel fp32 staging pitch
#define PX   68     // X pitch (words), 68 mod 32 == 4 -> conflict-free
#define PW   36     // weight/G pitch (words), 36 mod 32 == 4

// Static device scratch (allocation-free contract)
__device__ float g_h0[(size_t)BB * LL * RC];
__device__ float g_h1[(size_t)BB * LL * RC];
__device__ float g_skip[(size_t)BB * LL * SC];
__device__ float g_partial[(size_t)BB * 32 * SC];
__device__ int   g_flags[NBLK * BB * 32];
// pre-split weights (bf16x2 hi/lo pair-words)
__device__ uint32_t g_wdch[NBLK * 8192], g_wdcl[NBLK * 8192];
__device__ uint32_t g_wrh[NBLK * 2048], g_wrl[NBLK * 2048];
__device__ uint32_t g_wsh[NBLK * 4096], g_wsl[NBLK * 4096];

// ---------------------------------------------------------------------------
__device__ __forceinline__ void bfsplit2(float v0, float v1, uint32_t& hi, uint32_t& lo) {
    __nv_bfloat16 h0 = __float2bfloat16_rn(v0);
    __nv_bfloat16 h1 = __float2bfloat16_rn(v1);
    float r0 = v0 - __bfloat162float(h0);
    float r1 = v1 - __bfloat162float(h1);
    __nv_bfloat16 l0 = __float2bfloat16_rn(r0);
    __nv_bfloat16 l1 = __float2bfloat16_rn(r1);
    hi = (uint32_t)__bfloat16_as_ushort(h0) | ((uint32_t)__bfloat16_as_ushort(h1) << 16);
    lo = (uint32_t)__bfloat16_as_ushort(l0) | ((uint32_t)__bfloat16_as_ushort(l1) << 16);
}
__device__ __forceinline__ void bfsplit1(float v, uint16_t& hi, uint16_t& lo) {
    __nv_bfloat16 h = __float2bfloat16_rn(v);
    float r = v - __bfloat162float(h);
    hi = __bfloat16_as_ushort(h);
    lo = __bfloat16_as_ushort(__float2bfloat16_rn(r));
}

__device__ __forceinline__ void mma_bf16(float* d, const uint32_t* a, const uint32_t* b) {
    asm volatile(
        "mma.sync.aligned.m16n8k16.row.col.f32.bf16.bf16.f32 "
        "{%0,%1,%2,%3}, {%4,%5,%6,%7}, {%8,%9}, {%0,%1,%2,%3};"
        : "+f"(d[0]), "+f"(d[1]), "+f"(d[2]), "+f"(d[3])
        : "r"(a[0]), "r"(a[1]), "r"(a[2]), "r"(a[3]), "r"(b[0]), "r"(b[1]));
}

__device__ __forceinline__ uint32_t smaddr(const void* p) {
    return (uint32_t)__cvta_generic_to_shared(p);
}
__device__ __forceinline__ void ldm_x4(uint32_t* r, uint32_t addr) {
    asm volatile("ldmatrix.sync.aligned.m8n8.x4.shared.b16 {%0,%1,%2,%3}, [%4];"
        : "=r"(r[0]), "=r"(r[1]), "=r"(r[2]), "=r"(r[3]) : "r"(addr));
}
__device__ __forceinline__ void cp16(uint32_t dst, const void* src) {
    asm volatile("cp.async.cg.shared.global [%0], [%1], 16;" :: "r"(dst), "l"(src));
}
__device__ __forceinline__ void cp_commit() {
    asm volatile("cp.async.commit_group;");
}
__device__ __forceinline__ void cp_wait0() {
    asm volatile("cp.async.wait_group 0;");
}
__device__ __forceinline__ int ld_acq(const int* p) {
    int v;
    asm volatile("ld.acquire.gpu.global.b32 %0, [%1];" : "=r"(v) : "l"(p));
    return v;
}
__device__ __forceinline__ void st_rel(int* p, int v) {
    asm volatile("st.release.gpu.global.b32 [%0], %1;" :: "l"(p), "r"(v));
}

__device__ __forceinline__ float fast_gate(float t, float s) {
    float th = 2.f * __fdividef(1.f, 1.f + __expf(-2.f * t)) - 1.f;
    float sg = __fdividef(1.f, 1.f + __expf(-s));
    return th * sg;
}

// ---------------------------------------------------------------------------
__global__ __launch_bounds__(256) void split_kernel(
    const float* __restrict__ wd, const float* __restrict__ wr,
    const float* __restrict__ ws)
{
    int id = blockIdx.x * 256 + threadIdx.x;
    if (id >= NBLK * 14336) return;
    int i = id / 14336, r = id % 14336;
    if (r < 8192) {
        int op = r >> 6, j = r & 63;
        int o = ((op & 1) << 6) + (op >> 1);          // permuted source row
        float2 v = *(const float2*)(wd + (size_t)i * 16384 + o * 128 + 2 * j);
        uint32_t hi, lo; bfsplit2(v.x, v.y, hi, lo);
        g_wdch[i * 8192 + r] = hi; g_wdcl[i * 8192 + r] = lo;
    } else if (r < 10240) {
        int off = r - 8192;
        float2 v = *(const float2*)(wr + (size_t)i * 4096 + 2 * off);
        uint32_t hi, lo; bfsplit2(v.x, v.y, hi, lo);
        g_wrh[i * 2048 + off] = hi; g_wrl[i * 2048 + off] = lo;
    } else {
        int off = r - 10240;
        float2 v = *(const float2*)(ws + (size_t)i * 8192 + 2 * off);
        uint32_t hi, lo; bfsplit2(v.x, v.y, hi, lo);
        g_wsh[i * 4096 + off] = hi; g_wsl[i * 4096 + off] = lo;
    }
}

// ---------------------------------------------------------------------------
__global__ __launch_bounds__(256) void proj_kernel(
    const float* __restrict__ x, const float* __restrict__ w_in,
    const float* __restrict__ b_in, float* __restrict__ h)
{
    int idx = blockIdx.x * 256 + threadIdx.x;
    int oc = idx & 63;
    int l  = (idx >> 6) & (LL - 1);
    int b  = idx >> 18;
    float acc = b_in[oc];
#pragma unroll
    for (int c = 0; c < 8; ++c)
        acc += w_in[oc * 8 + c] * x[((size_t)(b * 8 + c)) * LL + l];
    h[(size_t)idx] = acc;
}

// ---------------------------------------------------------------------------
// ALL 30 WaveNet layers in ONE launch. CTA = (layer i, batch b, tile t).
// Per-tile dataflow flags: CTA waits (acquire) on flags[i-1][b][t-4..t+4]
// (backward 4 = dilation RAW; forward 4 = h ping-pong WAR), releases its own
// flag when done. Deadlock-free: all deps have blockIdx >= 2044 lower and HW
// dispatches CTAs in order. Body identical to the R13 per-layer kernel.
// ---------------------------------------------------------------------------
__global__ __launch_bounds__(256, 2) void mega_kernel(
    const float* __restrict__ b_dil, const float* __restrict__ b_res,
    const float* __restrict__ b_skip)
{
    extern __shared__ uint32_t smw[];
    uint32_t* s_xh = smw;                         // [128 pos][PX]
    uint32_t* s_xl = smw + 128 * PX;
    uint32_t* s_gh  = smw;                        // [128 pos][PW] (overlay)
    uint32_t* s_gl  = smw + 128 * PW;
    uint32_t* s_cwh = smw + 2 * 128 * PX;         // [128 o'][PW]
    uint32_t* s_cwl = s_cwh + 128 * PW;
    uint32_t* s_wrh = s_cwh;                      // [64][PW]  (overlay)
    uint32_t* s_wrl = s_cwh + 64 * PW;
    uint32_t* s_wsh = s_cwh + 128 * PW;           // [128][PW] (overlay)
    uint32_t* s_wsl = smw + 2 * 128 * PW;         // [128][PW] (overlay in region A)

    const int tid  = threadIdx.x;
    const int lane = tid & 31;
    const int w    = tid >> 5;
    const int lr   = lane >> 2;
    const int lc   = lane & 3;

    // ---- decode (layer, batch, tile) ----
    const int bx = blockIdx.x;
    const int i  = bx >> 11;            // layer 0..29
    const int r  = bx & 2047;
    const int b  = r >> 5;
    const int t  = r & 31;
    const int l0 = t * 128;
    const int d  = 1 << (i % 10);
    const int first = (i == 0);

    const uint32_t* wdch = g_wdch + i * 8192;
    const uint32_t* wdcl = g_wdcl + i * 8192;
    const uint32_t* wrh  = g_wrh  + i * 2048;
    const uint32_t* wrl  = g_wrl  + i * 2048;
    const uint32_t* wsh  = g_wsh  + i * 4096;
    const uint32_t* wsl  = g_wsl  + i * 4096;
    const float* bd = b_dil  + i * 128;
    const float* br = b_res  + i * 64;
    const float* bs = b_skip + i * 128;
    const float* h_in  = (i & 1) ? g_h1 : g_h0;
    float*       h_out = (i & 1) ? g_h0 : g_h1;
    float*       skip  = g_skip;

    const int arow8 = (lane & 7) + ((lane >> 3) & 1) * 8;
    const int acol4 = (lane >> 4) * 4;
    const int brow8 = (lane & 7) + ((lane >> 4) & 1) * 8;
    const int bcol4 = ((lane >> 3) & 1) * 4;

    // ---- issue conv W half-0 cp.async (no data dependency) ----
    {
        const uint32_t dh = smaddr(s_cwh), dl = smaddr(s_cwl);
        for (int e = tid; e < 1024; e += 256) {
            int row = e >> 3, q = e & 7;
            cp16(dh + (row * PW + q * 4) * 4, &wdch[row * 64 + q * 4]);
            cp16(dl + (row * PW + q * 4) * 4, &wdcl[row * 64 + q * 4]);
        }
        cp_commit();
    }

    // ---- dataflow wait: flags[i-1][b][t-4 .. t+4] ----
    if (i > 0) {
        int jlo = t - 4; if (jlo < 0) jlo = 0;
        int jhi = t + 4; if (jhi > 31) jhi = 31;
        int nj = jhi - jlo + 1;          // <= 9
        if (w == 0 && lane < nj) {
            const int* f = &g_flags[(i - 1) * 2048 + b * 32 + jlo + lane];
            while (ld_acq(f) == 0) { __nanosleep(64); }
        }
    }
    __syncthreads();   // [0] deps satisfied, visible to all threads

    // ---- stage X split ----
    {
        int c = tid & 63, p0 = tid >> 6;
        const float* hb = h_in + (size_t)b * LL * 64;
#pragma unroll
        for (int g = 0; g < 4; g++) {
            float curv[8], delv[8];
#pragma unroll
            for (int ii = 0; ii < 8; ii++) {
                int p = p0 + (g * 8 + ii) * 4;
                int l = l0 + p, ld = l - d;
                curv[ii] = hb[(size_t)l * 64 + c];
                delv[ii] = (ld >= 0) ? hb[(size_t)ld * 64 + c] : 0.f;
            }
#pragma unroll
            for (int ii = 0; ii < 8; ii++) {
                int p = p0 + (g * 8 + ii) * 4;
                uint32_t hi, lo; bfsplit2(delv[ii], curv[ii], hi, lo);
                s_xh[p * PX + c] = hi; s_xl[p * PX + c] = lo;
            }
        }
    }
    cp_wait0();
    __syncthreads();   // [1]

    // ================= conv GEMM: D[128 pos][128 o'], K=128 =================
    const int posb = (w >> 2) * 64;
    const int nb   = (w & 3) * 32;
    float acc[4][4][4];
#pragma unroll
    for (int mt = 0; mt < 4; mt++)
#pragma unroll
        for (int nt = 0; nt < 4; nt++)
#pragma unroll
            for (int rr = 0; rr < 4; rr++) acc[mt][nt][rr] = 0.f;

    const uint32_t aXh = smaddr(s_xh) + ((posb + arow8) * PX + acol4) * 4;
    const uint32_t aXl = aXh + 128 * PX * 4;
    const uint32_t bCh = smaddr(s_cwh) + ((nb + brow8) * PW + bcol4) * 4;
    const uint32_t bCl = bCh + 128 * PW * 4;

#pragma unroll 1
    for (int half = 0; half < 2; half++) {
        if (half == 1) {
            __syncthreads();
            const uint32_t dh = smaddr(s_cwh), dl = smaddr(s_cwl);
            for (int e = tid; e < 1024; e += 256) {
                int row = e >> 3, q = e & 7;
                cp16(dh + (row * PW + q * 4) * 4, &wdch[row * 64 + 32 + q * 4]);
                cp16(dl + (row * PW + q * 4) * 4, &wdcl[row * 64 + 32 + q * 4]);
            }
            cp_commit();
            cp_wait0();
            __syncthreads();
        }
#pragma unroll 1
        for (int ksl = 0; ksl < 4; ksl++) {
            const uint32_t offX = (uint32_t)((half * 4 + ksl) * 32);
            const uint32_t offW = (uint32_t)(ksl * 32);
            uint32_t ah[4][4], al[4][4], bh[2][4], bl[2][4];
#pragma unroll
            for (int mt = 0; mt < 4; mt++) {
                ldm_x4(ah[mt], aXh + (uint32_t)(mt * 16 * PX * 4) + offX);
                ldm_x4(al[mt], aXl + (uint32_t)(mt * 16 * PX * 4) + offX);
            }
#pragma unroll
            for (int tt = 0; tt < 2; tt++) {
                ldm_x4(bh[tt], bCh + (uint32_t)(tt * 16 * PW * 4) + offW);
                ldm_x4(bl[tt], bCl + (uint32_t)(tt * 16 * PW * 4) + offW);
            }
#pragma unroll
            for (int mt = 0; mt < 4; mt++)
#pragma unroll
                for (int nt = 0; nt < 4; nt++) {
                    const uint32_t* bhp = &bh[nt >> 1][(nt & 1) * 2];
                    const uint32_t* blp = &bl[nt >> 1][(nt & 1) * 2];
                    mma_bf16(acc[mt][nt], ah[mt], bhp);
                    mma_bf16(acc[mt][nt], ah[mt], blp);
                    mma_bf16(acc[mt][nt], al[mt], bhp);
                }
        }
    }
    __syncthreads();   // [2] X dead, conv W dead

    // ---- issue wr/ws cp.async, gate under the copy ----
    {
        const uint32_t dwrh = smaddr(s_wrh), dwrl = smaddr(s_wrl);
        const uint32_t dwsh = smaddr(s_wsh), dwsl = smaddr(s_wsl);
        for (int e = tid; e < 512; e += 256) {
            int row = e >> 3, q = e & 7;
            cp16(dwrh + (row * PW + q * 4) * 4, &wrh[row * 32 + q * 4]);
            cp16(dwrl + (row * PW + q * 4) * 4, &wrl[row * 32 + q * 4]);
        }
        for (int e = tid; e < 1024; e += 256) {
            int row = e >> 3, q = e & 7;
            cp16(dwsh + (row * PW + q * 4) * 4, &wsh[row * 32 + q * 4]);
            cp16(dwsl + (row * PW + q * 4) * 4, &wsl[row * 32 + q * 4]);
        }
        cp_commit();
    }
    {
        uint16_t* gh16 = (uint16_t*)s_gh;
        uint16_t* gl16 = (uint16_t*)s_gl;
#pragma unroll
        for (int nt = 0; nt < 4; nt++) {
            int j = (nb >> 1) + nt * 4 + lc;
            float bt = bd[j], bsg = bd[64 + j];
#pragma unroll
            for (int mt = 0; mt < 4; mt++)
#pragma unroll
                for (int rh = 0; rh < 2; rh++) {
                    float tv = acc[mt][nt][rh * 2 + 0] + bt;
                    float sv = acc[mt][nt][rh * 2 + 1] + bsg;
                    float g = fast_gate(tv, sv);
                    int pos = posb + mt * 16 + lr + rh * 8;
                    uint16_t hi, lo; bfsplit1(g, hi, lo);
                    int wi = (pos * PW + (j >> 1)) * 2 + (j & 1);
                    gh16[wi] = hi; gl16[wi] = lo;
                }
        }
    }
    cp_wait0();
    __syncthreads();   // [3]

    const uint32_t aGh = smaddr(s_gh) + ((posb + arow8) * PW + acol4) * 4;
    const uint32_t aGl = aGh + 128 * PW * 4;

    // ================= res GEMM: D[128 pos][64 out], K=64 =================
    {
        const int rnb = (w & 3) * 16;
        const uint32_t bRh = smaddr(s_wrh) + ((rnb + brow8) * PW + bcol4) * 4;
        const uint32_t bRl = bRh + 64 * PW * 4;
        float racc[4][2][4];
#pragma unroll
        for (int mt = 0; mt < 4; mt++)
#pragma unroll
            for (int nt = 0; nt < 2; nt++)
#pragma unroll
                for (int rr = 0; rr < 4; rr++) racc[mt][nt][rr] = 0.f;
#pragma unroll 1
        for (int ks = 0; ks < 4; ks++) {
            const uint32_t off = (uint32_t)(ks * 32);
            uint32_t ah[4][4], al[4][4], bh[4], bl[4];
#pragma unroll
            for (int mt = 0; mt < 4; mt++) {
                ldm_x4(ah[mt], aGh + (uint32_t)(mt * 16 * PW * 4) + off);
                ldm_x4(al[mt], aGl + (uint32_t)(mt * 16 * PW * 4) + off);
            }
            ldm_x4(bh, bRh + off);
            ldm_x4(bl, bRl + off);
#pragma unroll
            for (int mt = 0; mt < 4; mt++)
#pragma unroll
                for (int nt = 0; nt < 2; nt++) {
                    mma_bf16(racc[mt][nt], ah[mt], &bh[nt * 2]);
                    mma_bf16(racc[mt][nt], ah[mt], &bl[nt * 2]);
                    mma_bf16(racc[mt][nt], al[mt], &bh[nt * 2]);
                }
        }
        const float* hb = h_in + (size_t)b * LL * 64;
        float* ho = h_out + (size_t)b * LL * 64;
#pragma unroll
        for (int nt = 0; nt < 2; nt++) {
            int c = rnb + nt * 8 + 2 * lc;
            float2 brv = *(const float2*)&br[c];
#pragma unroll
            for (int mt = 0; mt < 4; mt++)
#pragma unroll
                for (int rh = 0; rh < 2; rh++) {
                    int pos = posb + mt * 16 + lr + rh * 8;
                    size_t gi = (size_t)(l0 + pos) * 64 + c;
                    float2 hv = *(const float2*)&hb[gi];
                    float2 o;
                    o.x = racc[mt][nt][rh * 2 + 0] + brv.x + hv.x;
                    o.y = racc[mt][nt][rh * 2 + 1] + brv.y + hv.y;
                    *(float2*)&ho[gi] = o;
                }
        }
    }

    // ================= skip GEMM: D[128 pos][128 out], K=64 =================
    {
        const int snb = (w & 3) * 32;
        const uint32_t bSh = smaddr(s_wsh) + ((snb + brow8) * PW + bcol4) * 4;
        const uint32_t bSl = smaddr(s_wsl) + ((snb + brow8) * PW + bcol4) * 4;
        float sacc[4][4][4];
#pragma unroll
        for (int mt = 0; mt < 4; mt++)
#pragma unroll
            for (int nt = 0; nt < 4; nt++)
#pragma unroll
                for (int rr = 0; rr < 4; rr++) sacc[mt][nt][rr] = 0.f;
#pragma unroll 1
        for (int ks = 0; ks < 4; ks++) {
            const uint32_t off = (uint32_t)(ks * 32);
            uint32_t ah[4][4], al[4][4], bh[2][4], bl[2][4];
#pragma unroll
            for (int mt = 0; mt < 4; mt++) {
                ldm_x4(ah[mt], aGh + (uint32_t)(mt * 16 * PW * 4) + off);
                ldm_x4(al[mt], aGl + (uint32_t)(mt * 16 * PW * 4) + off);
            }
#pragma unroll
            for (int tt = 0; tt < 2; tt++) {
                ldm_x4(bh[tt], bSh + (uint32_t)(tt * 16 * PW * 4) + off);
                ldm_x4(bl[tt], bSl + (uint32_t)(tt * 16 * PW * 4) + off);
            }
#pragma unroll
            for (int mt = 0; mt < 4; mt++)
#pragma unroll
                for (int nt = 0; nt < 4; nt++) {
                    const uint32_t* bhp = &bh[nt >> 1][(nt & 1) * 2];
                    const uint32_t* blp = &bl[nt >> 1][(nt & 1) * 2];
                    mma_bf16(sacc[mt][nt], ah[mt], bhp);
                    mma_bf16(sacc[mt][nt], ah[mt], blp);
                    mma_bf16(sacc[mt][nt], al[mt], bhp);
                }
        }
        float* sk = skip + (size_t)b * LL * 128;
#pragma unroll
        for (int nt = 0; nt < 4; nt++) {
            int s = snb + nt * 8 + 2 * lc;
            float2 bsv = *(const float2*)&bs[s];
#pragma unroll
            for (int mt = 0; mt < 4; mt++)
#pragma unroll
                for (int rh = 0; rh < 2; rh++) {
                    int pos = posb + mt * 16 + lr + rh * 8;
                    size_t gi = (size_t)(l0 + pos) * 128 + s;
                    float2 v;
                    v.x = sacc[mt][nt][rh * 2 + 0] + bsv.x;
                    v.y = sacc[mt][nt][rh * 2 + 1] + bsv.y;
                    if (!first) {
                        float2 old = *(const float2*)&sk[gi];
                        v.x += old.x; v.y += old.y;
                    }
                    *(float2*)&sk[gi] = v;
                }
        }
    }

    // ---- release our flag ----
    __syncthreads();
    if (tid == 0) st_rel(&g_flags[i * 2048 + b * 32 + t], 1);
}

// ---------------------------------------------------------------------------
// Post: relu(skip) -> out1 -> relu -> out2 -> per-tile column sums (ldmatrix)
// ---------------------------------------------------------------------------
__global__ __launch_bounds__(256) void post_kernel(
    const float* __restrict__ skip,
    const float* __restrict__ w1g, const float* __restrict__ b1,
    const float* __restrict__ w2g, const float* __restrict__ b2,
    float* __restrict__ partial)
{
    extern __shared__ float sm[];
    float*    s_ts = sm;
    uint32_t* s_rh = (uint32_t*)(sm + 128 * P);
    uint32_t* s_rl = s_rh + 128 * PX;
    uint32_t* s_wh = s_rl + 128 * PX;
    uint32_t* s_wl = s_wh + 128 * PX;

    const int tid  = threadIdx.x;
    const int lane = tid & 31;
    const int w    = tid >> 5;
    const int lr   = lane >> 2;
    const int lc   = lane & 3;
    const int b    = blockIdx.y;
    const int l0   = blockIdx.x * 128;

    const int out0 = (w >> 2) * 64;
    const int pos0 = (w & 3) * 32;

    const int arow8 = (lane & 7) + ((lane >> 3) & 1) * 8;
    const int acol4 = (lane >> 4) * 4;
    const int brow8 = (lane & 7) + ((lane >> 4) & 1) * 8;
    const int bcol4 = ((lane >> 3) & 1) * 4;

    {
        int cp = tid & 63, p0 = tid >> 6;
#pragma unroll
        for (int p = p0; p < 128; p += 4) {
            float2 v = *(const float2*)(skip + ((size_t)b * LL + l0 + p) * 128 + 2 * cp);
            v.x = fmaxf(v.x, 0.f); v.y = fmaxf(v.y, 0.f);
            uint32_t hi, lo; bfsplit2(v.x, v.y, hi, lo);
            s_rh[p * PX + cp] = hi; s_rl[p * PX + cp] = lo;
        }
    }
    for (int e = tid; e < 8192; e += 256) {
        int o = e >> 6, j = e & 63;
        float2 v = *(const float2*)(w1g + o * 128 + 2 * j);
        uint32_t hi, lo; bfsplit2(v.x, v.y, hi, lo);
        s_wh[o * PX + j] = hi; s_wl[o * PX + j] = lo;
    }
    __syncthreads();

    const uint32_t aWh = smaddr(s_wh) + ((out0 + arow8) * PX + acol4) * 4;
    const uint32_t aWl = aWh + 128 * PX * 4;
    const uint32_t bRh = smaddr(s_rh) + ((pos0 + brow8) * PX + bcol4) * 4;
    const uint32_t bRl = bRh + 128 * PX * 4;

    {
        float acc[4][4][4];
#pragma unroll
        for (int mt = 0; mt < 4; mt++)
#pragma unroll
            for (int nt = 0; nt < 4; nt++)
#pragma unroll
                for (int rr = 0; rr < 4; rr++) acc[mt][nt][rr] = 0.f;
#pragma unroll 1
        for (int ks = 0; ks < 8; ks++) {
            const uint32_t off = (uint32_t)(ks * 32);
            uint32_t ah[4][4], al[4][4], bh[2][4], bl[2][4];
#pragma unroll
            for (int mt = 0; mt < 4; mt++) {
                ldm_x4(ah[mt], aWh + (uint32_t)(mt * 16 * PX * 4) + off);
                ldm_x4(al[mt], aWl + (uint32_t)(mt * 16 * PX * 4) + off);
            }
#pragma unroll
            for (int t = 0; t < 2; t++) {
                ldm_x4(bh[t], bRh + (uint32_t)(t * 16 * PX * 4) + off);
                ldm_x4(bl[t], bRl + (uint32_t)(t * 16 * PX * 4) + off);
            }
#pragma unroll
            for (int mt = 0; mt < 4; mt++)
#pragma unroll
                for (int nt = 0; nt < 4; nt++) {
                    const uint32_t* bhp = &bh[nt >> 1][(nt & 1) * 2];
                    const uint32_t* blp = &bl[nt >> 1][(nt & 1) * 2];
                    mma_bf16(acc[mt][nt], ah[mt], bhp);
                    mma_bf16(acc[mt][nt], ah[mt], blp);
                    mma_bf16(acc[mt][nt], al[mt], bhp);
                }
        }
#pragma unroll
        for (int mt = 0; mt < 4; mt++) {
            int row = out0 + mt * 16 + lr;
            float bv0 = b1[row], bv8 = b1[row + 8];
#pragma unroll
            for (int nt = 0; nt < 4; nt++) {
                int col = pos0 + nt * 8 + 2 * lc;
                *(float2*)&s_ts[row * P + col] =
                    make_float2(fmaxf(acc[mt][nt][0] + bv0, 0.f), fmaxf(acc[mt][nt][1] + bv0, 0.f));
                *(float2*)&s_ts[(row + 8) * P + col] =
                    make_float2(fmaxf(acc[mt][nt][2] + bv8, 0.f), fmaxf(acc[mt][nt][3] + bv8, 0.f));
            }
        }
    }
    __syncthreads();

    for (int e = tid; e < 8192; e += 256) {
        int o = e >> 6, j = e & 63;
        float2 v = *(const float2*)(w2g + o * 128 + 2 * j);
        uint32_t hi, lo; bfsplit2(v.x, v.y, hi, lo);
        s_wh[o * PX + j] = hi; s_wl[o * PX + j] = lo;
    }
    for (int it = w; it < 256; it += 8) {
        int cp = it >> 2, pos = (it & 3) * 32 + lane;
        float v0 = s_ts[(2 * cp) * P + pos];
        float v1 = s_ts[(2 * cp + 1) * P + pos];
        uint32_t hi, lo; bfsplit2(v0, v1, hi, lo);
        s_rh[pos * PX + cp] = hi; s_rl[pos * PX + cp] = lo;
    }
    __syncthreads();

    {
        float acc[4][4][4];
#pragma unroll
        for (int mt = 0; mt < 4; mt++)
#pragma unroll
            for (int nt = 0; nt < 4; nt++)
#pragma unroll
                for (int rr = 0; rr < 4; rr++) acc[mt][nt][rr] = 0.f;
#pragma unroll 1
        for (int ks = 0; ks < 8; ks++) {
            const uint32_t off = (uint32_t)(ks * 32);
            uint32_t ah[4][4], al[4][4], bh[2][4], bl[2][4];
#pragma unroll
            for (int mt = 0; mt < 4; mt++) {
                ldm_x4(ah[mt], aWh + (uint32_t)(mt * 16 * PX * 4) + off);
                ldm_x4(al[mt], aWl + (uint32_t)(mt * 16 * PX * 4) + off);
            }
#pragma unroll
            for (int t = 0; t < 2; t++) {
                ldm_x4(bh[t], bRh + (uint32_t)(t * 16 * PX * 4) + off);
                ldm_x4(bl[t], bRl + (uint32_t)(t * 16 * PX * 4) + off);
            }
#pragma unroll
            for (int mt = 0; mt < 4; mt++)
#pragma unroll
                for (int nt = 0; nt < 4; nt++) {
                    const uint32_t* bhp = &bh[nt >> 1][(nt & 1) * 2];
                    const uint32_t* blp = &bl[nt >> 1][(nt & 1) * 2];
                    mma_bf16(acc[mt][nt], ah[mt], bhp);
                    mma_bf16(acc[mt][nt], ah[mt], blp);
                    mma_bf16(acc[mt][nt], al[mt], bhp);
                }
        }
#pragma unroll
        for (int mt = 0; mt < 4; mt++)
#pragma unroll
            for (int nt = 0; nt < 4; nt++) {
                int row = out0 + mt * 16 + lr;
                int col = pos0 + nt * 8 + 2 * lc;
                *(float2*)&s_ts[row * P + col] = make_float2(acc[mt][nt][0], acc[mt][nt][1]);
                *(float2*)&s_ts[(row + 8) * P + col] = make_float2(acc[mt][nt][2], acc[mt][nt][3]);
            }
    }
    __syncthreads();

    {
        float* sred = (float*)s_rh;
        int c = tid & 127, half = tid >> 7;
        float sum = 0.f;
        for (int p = half * 64; p < half * 64 + 64; p++) sum += s_ts[c * P + p];
        sred[half * 128 + c] = sum;
        __syncthreads();
        if (tid < 128)
            partial[((size_t)b * 32 + blockIdx.x) * 128 + tid] =
                sred[tid] + sred[128 + tid] + 128.f * b2[tid];
    }
}

// ---------------------------------------------------------------------------
__global__ __launch_bounds__(256) void final_kernel(
    const float* __restrict__ partial,
    const float* __restrict__ wf1, const float* __restrict__ bf1,
    const float* __restrict__ wf2, const float* __restrict__ bf2,
    const float* __restrict__ wf3, const float* __restrict__ bf3,
    float* __restrict__ out)
{
    __shared__ float pooled[128];
    __shared__ float z1[256];
    __shared__ float z2[128];
    int b = blockIdx.x, tid = threadIdx.x;
    if (tid < 128) {
        float s = 0.f;
        for (int t = 0; t < 32; t++) s += partial[((size_t)b * 32 + t) * 128 + tid];
        pooled[tid] = s * (1.f / (float)LL);
    }
    __syncthreads();
    {
        float a = bf1[tid];
        for (int c = 0; c < 128; c++) a += wf1[tid * 128 + c] * pooled[c];
        z1[tid] = fmaxf(a, 0.f);
    }
    __syncthreads();
    if (tid < 128) {
        float a = bf2[tid];
        for (int c = 0; c < 256; c++) a += wf2[tid * 256 + c] * z1[c];
        z2[tid] = fmaxf(a, 0.f);
    }
    __syncthreads();
    if (tid < 6) {
        float a = bf3[tid];
        for (int c = 0; c < 128; c++) a += wf3[tid * 128 + c] * z2[c];
        out[b * 6 + tid] = a;
    }
}

// ---------------------------------------------------------------------------
extern "C" void kernel_launch(void* const* d_in, const int* in_sizes, int n_in,
                              void* d_out, int out_size)
{
    const float* x      = (const float*)d_in[0];
    const float* w_in   = (const float*)d_in[1];
    const float* b_in   = (const float*)d_in[2];
    const float* w_dil  = (const float*)d_in[3];
    const float* b_dil  = (const float*)d_in[4];
    const float* w_res  = (const float*)d_in[5];
    const float* b_res  = (const float*)d_in[6];
    const float* w_skip = (const float*)d_in[7];
    const float* b_skip = (const float*)d_in[8];
    const float* w_out1 = (const float*)d_in[9];
    const float* b_out1 = (const float*)d_in[10];
    const float* w_out2 = (const float*)d_in[11];
    const float* b_out2 = (const float*)d_in[12];
    const float* w_fc1  = (const float*)d_in[13];
    const float* b_fc1  = (const float*)d_in[14];
    const float* w_fc2  = (const float*)d_in[15];
    const float* b_fc2  = (const float*)d_in[16];
    const float* w_fc3  = (const float*)d_in[17];
    const float* b_fc3  = (const float*)d_in[18];
    float* out = (float*)d_out;

    float *h0, *skipb, *partial;
    int* flags;
    cudaGetSymbolAddress((void**)&h0,      g_h0);
    cudaGetSymbolAddress((void**)&skipb,   g_skip);
    cudaGetSymbolAddress((void**)&partial, g_partial);
    cudaGetSymbolAddress((void**)&flags,   g_flags);

    const int BLOCK_SMEM = (2 * 128 * PX + 2 * 128 * PW) * 4;    // 106,496 B
    const int POST_SMEM  = (128 * P + 4 * 128 * PX) * 4;         // 206,848 B
    cudaFuncSetAttribute(mega_kernel,  cudaFuncAttributeMaxDynamicSharedMemorySize, BLOCK_SMEM);
    cudaFuncSetAttribute(post_kernel,  cudaFuncAttributeMaxDynamicSharedMemorySize, POST_SMEM);

    cudaMemsetAsync(flags, 0, NBLK * BB * 32 * sizeof(int));
    split_kernel<<<(NBLK * 14336 + 255) / 256, 256>>>(w_dil, w_res, w_skip);
    proj_kernel<<<(BB * LL * 64) / 256, 256>>>(x, w_in, b_in, h0);

    mega_kernel<<<NBLK * 2048, 256, BLOCK_SMEM>>>(b_dil, b_res, b_skip);

    dim3 grid(LL / 128, BB);
    post_kernel<<<grid, 256, POST_SMEM>>>(skipb, w_out1, b_out1, w_out2, b_out2, partial);
    final_kernel<<<BB, 256>>>(partial, w_fc1, b_fc1, w_fc2, b_fc2, w_fc3, b_fc3, out);
}

// round 16
// speedup vs baseline: 1.5863x; 1.0242x over previous
#include <cuda_runtime.h>
#include <cuda_bf16.h>
#include <math.h>
#include <stdint.h>

#define BB   64
#define LL   4096
#define RC   64
#define SC   128
#define NBLK 30
#define PX   68     // act pitch (words), 68 mod 32 == 4 -> conflict-free
#define PW   36     // weight/G pitch (words), 36 mod 32 == 4

// Static device scratch (allocation-free contract)
__device__ float g_h0[(size_t)BB * LL * RC];
__device__ float g_h1[(size_t)BB * LL * RC];
__device__ float g_skip[(size_t)BB * LL * SC];
__device__ float g_partial[(size_t)BB * 32 * SC];
__device__ int   g_flags[NBLK * BB * 32];
// pre-split weights (bf16x2 hi/lo pair-words)
__device__ uint32_t g_wdch[NBLK * 8192], g_wdcl[NBLK * 8192];
__device__ uint32_t g_wrh[NBLK * 2048], g_wrl[NBLK * 2048];
__device__ uint32_t g_wsh[NBLK * 4096], g_wsl[NBLK * 4096];
__device__ uint32_t g_w1h[8192], g_w1l[8192];   // out1 [128 o][64 pairs]
__device__ uint32_t g_w2h[8192], g_w2l[8192];   // out2 [128 o][64 pairs]

// ---------------------------------------------------------------------------
__device__ __forceinline__ void bfsplit2(float v0, float v1, uint32_t& hi, uint32_t& lo) {
    __nv_bfloat16 h0 = __float2bfloat16_rn(v0);
    __nv_bfloat16 h1 = __float2bfloat16_rn(v1);
    float r0 = v0 - __bfloat162float(h0);
    float r1 = v1 - __bfloat162float(h1);
    __nv_bfloat16 l0 = __float2bfloat16_rn(r0);
    __nv_bfloat16 l1 = __float2bfloat16_rn(r1);
    hi = (uint32_t)__bfloat16_as_ushort(h0) | ((uint32_t)__bfloat16_as_ushort(h1) << 16);
    lo = (uint32_t)__bfloat16_as_ushort(l0) | ((uint32_t)__bfloat16_as_ushort(l1) << 16);
}
__device__ __forceinline__ void bfsplit1(float v, uint16_t& hi, uint16_t& lo) {
    __nv_bfloat16 h = __float2bfloat16_rn(v);
    float r = v - __bfloat162float(h);
    hi = __bfloat16_as_ushort(h);
    lo = __bfloat16_as_ushort(__float2bfloat16_rn(r));
}

__device__ __forceinline__ void mma_bf16(float* d, const uint32_t* a, const uint32_t* b) {
    asm volatile(
        "mma.sync.aligned.m16n8k16.row.col.f32.bf16.bf16.f32 "
        "{%0,%1,%2,%3}, {%4,%5,%6,%7}, {%8,%9}, {%0,%1,%2,%3};"
        : "+f"(d[0]), "+f"(d[1]), "+f"(d[2]), "+f"(d[3])
        : "r"(a[0]), "r"(a[1]), "r"(a[2]), "r"(a[3]), "r"(b[0]), "r"(b[1]));
}

__device__ __forceinline__ uint32_t smaddr(const void* p) {
    return (uint32_t)__cvta_generic_to_shared(p);
}
__device__ __forceinline__ void ldm_x4(uint32_t* r, uint32_t addr) {
    asm volatile("ldmatrix.sync.aligned.m8n8.x4.shared.b16 {%0,%1,%2,%3}, [%4];"
        : "=r"(r[0]), "=r"(r[1]), "=r"(r[2]), "=r"(r[3]) : "r"(addr));
}
__device__ __forceinline__ void cp16(uint32_t dst, const void* src) {
    asm volatile("cp.async.cg.shared.global [%0], [%1], 16;" :: "r"(dst), "l"(src));
}
__device__ __forceinline__ void cp_commit() {
    asm volatile("cp.async.commit_group;");
}
__device__ __forceinline__ void cp_wait0() {
    asm volatile("cp.async.wait_group 0;");
}
__device__ __forceinline__ int ld_acq(const int* p) {
    int v;
    asm volatile("ld.acquire.gpu.global.b32 %0, [%1];" : "=r"(v) : "l"(p));
    return v;
}
__device__ __forceinline__ void st_rel(int* p, int v) {
    asm volatile("st.release.gpu.global.b32 [%0], %1;" :: "l"(p), "r"(v));
}

__device__ __forceinline__ float fast_gate(float t, float s) {
    float th = 2.f * __fdividef(1.f, 1.f + __expf(-2.f * t)) - 1.f;
    float sg = __fdividef(1.f, 1.f + __expf(-s));
    return th * sg;
}

// ---------------------------------------------------------------------------
__global__ __launch_bounds__(256) void split_kernel(
    const float* __restrict__ wd, const float* __restrict__ wr,
    const float* __restrict__ ws, const float* __restrict__ w1,
    const float* __restrict__ w2)
{
    int id = blockIdx.x * 256 + threadIdx.x;
    if (id >= NBLK * 14336 + 16384) return;
    if (id >= NBLK * 14336) {
        int r2 = id - NBLK * 14336;
        const float* src = (r2 < 8192) ? w1 : w2;
        uint32_t* dh = (r2 < 8192) ? g_w1h : g_w2h;
        uint32_t* dl = (r2 < 8192) ? g_w1l : g_w2l;
        int off = r2 & 8191;
        float2 v = *(const float2*)(src + 2 * off);
        uint32_t hi, lo; bfsplit2(v.x, v.y, hi, lo);
        dh[off] = hi; dl[off] = lo;
        return;
    }
    int i = id / 14336, r = id % 14336;
    if (r < 8192) {
        int op = r >> 6, j = r & 63;
        int o = ((op & 1) << 6) + (op >> 1);          // permuted source row
        float2 v = *(const float2*)(wd + (size_t)i * 16384 + o * 128 + 2 * j);
        uint32_t hi, lo; bfsplit2(v.x, v.y, hi, lo);
        g_wdch[i * 8192 + r] = hi; g_wdcl[i * 8192 + r] = lo;
    } else if (r < 10240) {
        int off = r - 8192;
        float2 v = *(const float2*)(wr + (size_t)i * 4096 + 2 * off);
        uint32_t hi, lo; bfsplit2(v.x, v.y, hi, lo);
        g_wrh[i * 2048 + off] = hi; g_wrl[i * 2048 + off] = lo;
    } else {
        int off = r - 10240;
        float2 v = *(const float2*)(ws + (size_t)i * 8192 + 2 * off);
        uint32_t hi, lo; bfsplit2(v.x, v.y, hi, lo);
        g_wsh[i * 4096 + off] = hi; g_wsl[i * 4096 + off] = lo;
    }
}

// ---------------------------------------------------------------------------
__global__ __launch_bounds__(256) void proj_kernel(
    const float* __restrict__ x, const float* __restrict__ w_in,
    const float* __restrict__ b_in, float* __restrict__ h)
{
    int idx = blockIdx.x * 256 + threadIdx.x;
    int oc = idx & 63;
    int l  = (idx >> 6) & (LL - 1);
    int b  = idx >> 18;
    float acc = b_in[oc];
#pragma unroll
    for (int c = 0; c < 8; ++c)
        acc += w_in[oc * 8 + c] * x[((size_t)(b * 8 + c)) * LL + l];
    h[(size_t)idx] = acc;
}

// ---------------------------------------------------------------------------
// 30 WaveNet layers + the post MLP, all in ONE launch.
// i < NBLK : layer CTA (R14 body). i == NBLK : post tile — waits on
// flags[29][b][t], runs relu->out1->relu->out2->column sums with w1/w2
// streamed in K-halves and register relu/reduction (no fp32 staging).
// ---------------------------------------------------------------------------
__global__ __launch_bounds__(256, 2) void mega_kernel(
    const float* __restrict__ b_dil, const float* __restrict__ b_res,
    const float* __restrict__ b_skip,
    const float* __restrict__ b1g, const float* __restrict__ b2g)
{
    extern __shared__ uint32_t smw[];
    uint32_t* s_xh = smw;                         // [128 pos][PX]
    uint32_t* s_xl = smw + 128 * PX;
    uint32_t* s_gh  = smw;                        // [128 pos][PW] (overlay)
    uint32_t* s_gl  = smw + 128 * PW;
    uint32_t* s_cwh = smw + 2 * 128 * PX;         // [128][PW]
    uint32_t* s_cwl = s_cwh + 128 * PW;
    uint32_t* s_wrh = s_cwh;                      // [64][PW]  (overlay)
    uint32_t* s_wrl = s_cwh + 64 * PW;
    uint32_t* s_wsh = s_cwh + 128 * PW;           // [128][PW] (overlay)
    uint32_t* s_wsl = smw + 2 * 128 * PW;         // [128][PW] (overlay in region A)

    const int tid  = threadIdx.x;
    const int lane = tid & 31;
    const int w    = tid >> 5;
    const int lr   = lane >> 2;
    const int lc   = lane & 3;

    const int bx = blockIdx.x;
    const int i  = bx >> 11;            // 0..NBLK (NBLK = post)
    const int r  = bx & 2047;
    const int b  = r >> 5;
    const int t  = r & 31;
    const int l0 = t * 128;

    const uint32_t* wdch = (i < NBLK) ? g_wdch + i * 8192 : g_w1h;
    const uint32_t* wdcl = (i < NBLK) ? g_wdcl + i * 8192 : g_w1l;

    const int arow8 = (lane & 7) + ((lane >> 3) & 1) * 8;
    const int acol4 = (lane >> 4) * 4;
    const int brow8 = (lane & 7) + ((lane >> 4) & 1) * 8;
    const int bcol4 = ((lane >> 3) & 1) * 4;

    // ---- issue first GEMM's weight half-0 (no data dependency) ----
    {
        const uint32_t dh = smaddr(s_cwh), dl = smaddr(s_cwl);
        for (int e = tid; e < 1024; e += 256) {
            int row = e >> 3, q = e & 7;
            cp16(dh + (row * PW + q * 4) * 4, &wdch[row * 64 + q * 4]);
            cp16(dl + (row * PW + q * 4) * 4, &wdcl[row * 64 + q * 4]);
        }
        cp_commit();
    }

    const int posb = (w >> 2) * 64;
    const int nb   = (w & 3) * 32;

    if (i < NBLK) {
        // =================== LAYER CTA ===================
        const int d     = 1 << (i % 10);
        const int first = (i == 0);
        const uint32_t* wrh = g_wrh + i * 2048;
        const uint32_t* wrl = g_wrl + i * 2048;
        const uint32_t* wsh = g_wsh + i * 4096;
        const uint32_t* wsl = g_wsl + i * 4096;
        const float* bd = b_dil  + i * 128;
        const float* br = b_res  + i * 64;
        const float* bs = b_skip + i * 128;
        const float* h_in  = (i & 1) ? g_h1 : g_h0;
        float*       h_out = (i & 1) ? g_h0 : g_h1;

        if (i > 0) {
            int jlo = t - 4; if (jlo < 0) jlo = 0;
            int jhi = t + 4; if (jhi > 31) jhi = 31;
            int nj = jhi - jlo + 1;
            if (w == 0 && lane < nj) {
                const int* f = &g_flags[(i - 1) * 2048 + b * 32 + jlo + lane];
                while (ld_acq(f) == 0) { __nanosleep(64); }
            }
        }
        __syncthreads();

        // ---- stage X split ----
        {
            int c = tid & 63, p0 = tid >> 6;
            const float* hb = h_in + (size_t)b * LL * 64;
#pragma unroll
            for (int g = 0; g < 4; g++) {
                float curv[8], delv[8];
#pragma unroll
                for (int ii = 0; ii < 8; ii++) {
                    int p = p0 + (g * 8 + ii) * 4;
                    int l = l0 + p, ld = l - d;
                    curv[ii] = hb[(size_t)l * 64 + c];
                    delv[ii] = (ld >= 0) ? hb[(size_t)ld * 64 + c] : 0.f;
                }
#pragma unroll
                for (int ii = 0; ii < 8; ii++) {
                    int p = p0 + (g * 8 + ii) * 4;
                    uint32_t hi, lo; bfsplit2(delv[ii], curv[ii], hi, lo);
                    s_xh[p * PX + c] = hi; s_xl[p * PX + c] = lo;
                }
            }
        }
        cp_wait0();
        __syncthreads();

        // ---- conv GEMM ----
        float acc[4][4][4];
#pragma unroll
        for (int mt = 0; mt < 4; mt++)
#pragma unroll
            for (int nt = 0; nt < 4; nt++)
#pragma unroll
                for (int rr = 0; rr < 4; rr++) acc[mt][nt][rr] = 0.f;

        const uint32_t aXh = smaddr(s_xh) + ((posb + arow8) * PX + acol4) * 4;
        const uint32_t aXl = aXh + 128 * PX * 4;
        const uint32_t bCh = smaddr(s_cwh) + ((nb + brow8) * PW + bcol4) * 4;
        const uint32_t bCl = bCh + 128 * PW * 4;

#pragma unroll 1
        for (int half = 0; half < 2; half++) {
            if (half == 1) {
                __syncthreads();
                const uint32_t dh = smaddr(s_cwh), dl = smaddr(s_cwl);
                for (int e = tid; e < 1024; e += 256) {
                    int row = e >> 3, q = e & 7;
                    cp16(dh + (row * PW + q * 4) * 4, &wdch[row * 64 + 32 + q * 4]);
                    cp16(dl + (row * PW + q * 4) * 4, &wdcl[row * 64 + 32 + q * 4]);
                }
                cp_commit();
                cp_wait0();
                __syncthreads();
            }
#pragma unroll 1
            for (int ksl = 0; ksl < 4; ksl++) {
                const uint32_t offX = (uint32_t)((half * 4 + ksl) * 32);
                const uint32_t offW = (uint32_t)(ksl * 32);
                uint32_t ah[4][4], al[4][4], bh[2][4], bl[2][4];
#pragma unroll
                for (int mt = 0; mt < 4; mt++) {
                    ldm_x4(ah[mt], aXh + (uint32_t)(mt * 16 * PX * 4) + offX);
                    ldm_x4(al[mt], aXl + (uint32_t)(mt * 16 * PX * 4) + offX);
                }
#pragma unroll
                for (int tt = 0; tt < 2; tt++) {
                    ldm_x4(bh[tt], bCh + (uint32_t)(tt * 16 * PW * 4) + offW);
                    ldm_x4(bl[tt], bCl + (uint32_t)(tt * 16 * PW * 4) + offW);
                }
#pragma unroll
                for (int mt = 0; mt < 4; mt++)
#pragma unroll
                    for (int nt = 0; nt < 4; nt++) {
                        const uint32_t* bhp = &bh[nt >> 1][(nt & 1) * 2];
                        const uint32_t* blp = &bl[nt >> 1][(nt & 1) * 2];
                        mma_bf16(acc[mt][nt], ah[mt], bhp);
                        mma_bf16(acc[mt][nt], ah[mt], blp);
                        mma_bf16(acc[mt][nt], al[mt], bhp);
                    }
            }
        }
        __syncthreads();

        // ---- wr/ws cp.async + register gate ----
        {
            const uint32_t dwrh = smaddr(s_wrh), dwrl = smaddr(s_wrl);
            const uint32_t dwsh = smaddr(s_wsh), dwsl = smaddr(s_wsl);
            for (int e = tid; e < 512; e += 256) {
                int row = e >> 3, q = e & 7;
                cp16(dwrh + (row * PW + q * 4) * 4, &wrh[row * 32 + q * 4]);
                cp16(dwrl + (row * PW + q * 4) * 4, &wrl[row * 32 + q * 4]);
            }
            for (int e = tid; e < 1024; e += 256) {
                int row = e >> 3, q = e & 7;
                cp16(dwsh + (row * PW + q * 4) * 4, &wsh[row * 32 + q * 4]);
                cp16(dwsl + (row * PW + q * 4) * 4, &wsl[row * 32 + q * 4]);
            }
            cp_commit();
        }
        {
            uint16_t* gh16 = (uint16_t*)s_gh;
            uint16_t* gl16 = (uint16_t*)s_gl;
#pragma unroll
            for (int nt = 0; nt < 4; nt++) {
                int j = (nb >> 1) + nt * 4 + lc;
                float bt = bd[j], bsg = bd[64 + j];
#pragma unroll
                for (int mt = 0; mt < 4; mt++)
#pragma unroll
                    for (int rh = 0; rh < 2; rh++) {
                        float tv = acc[mt][nt][rh * 2 + 0] + bt;
                        float sv = acc[mt][nt][rh * 2 + 1] + bsg;
                        float g = fast_gate(tv, sv);
                        int pos = posb + mt * 16 + lr + rh * 8;
                        uint16_t hi, lo; bfsplit1(g, hi, lo);
                        int wi = (pos * PW + (j >> 1)) * 2 + (j & 1);
                        gh16[wi] = hi; gl16[wi] = lo;
                    }
            }
        }
        cp_wait0();
        __syncthreads();

        const uint32_t aGh = smaddr(s_gh) + ((posb + arow8) * PW + acol4) * 4;
        const uint32_t aGl = aGh + 128 * PW * 4;

        // ---- res GEMM -> h_out ----
        {
            const int rnb = (w & 3) * 16;
            const uint32_t bRh = smaddr(s_wrh) + ((rnb + brow8) * PW + bcol4) * 4;
            const uint32_t bRl = bRh + 64 * PW * 4;
            float racc[4][2][4];
#pragma unroll
            for (int mt = 0; mt < 4; mt++)
#pragma unroll
                for (int nt = 0; nt < 2; nt++)
#pragma unroll
                    for (int rr = 0; rr < 4; rr++) racc[mt][nt][rr] = 0.f;
#pragma unroll 1
            for (int ks = 0; ks < 4; ks++) {
                const uint32_t off = (uint32_t)(ks * 32);
                uint32_t ah[4][4], al[4][4], bh[4], bl[4];
#pragma unroll
                for (int mt = 0; mt < 4; mt++) {
                    ldm_x4(ah[mt], aGh + (uint32_t)(mt * 16 * PW * 4) + off);
                    ldm_x4(al[mt], aGl + (uint32_t)(mt * 16 * PW * 4) + off);
                }
                ldm_x4(bh, bRh + off);
                ldm_x4(bl, bRl + off);
#pragma unroll
                for (int mt = 0; mt < 4; mt++)
#pragma unroll
                    for (int nt = 0; nt < 2; nt++) {
                        mma_bf16(racc[mt][nt], ah[mt], &bh[nt * 2]);
                        mma_bf16(racc[mt][nt], ah[mt], &bl[nt * 2]);
                        mma_bf16(racc[mt][nt], al[mt], &bh[nt * 2]);
                    }
            }
            const float* hb = h_in + (size_t)b * LL * 64;
            float* ho = h_out + (size_t)b * LL * 64;
#pragma unroll
            for (int nt = 0; nt < 2; nt++) {
                int c = rnb + nt * 8 + 2 * lc;
                float2 brv = *(const float2*)&br[c];
#pragma unroll
                for (int mt = 0; mt < 4; mt++)
#pragma unroll
                    for (int rh = 0; rh < 2; rh++) {
                        int pos = posb + mt * 16 + lr + rh * 8;
                        size_t gi = (size_t)(l0 + pos) * 64 + c;
                        float2 hv = *(const float2*)&hb[gi];
                        float2 o;
                        o.x = racc[mt][nt][rh * 2 + 0] + brv.x + hv.x;
                        o.y = racc[mt][nt][rh * 2 + 1] + brv.y + hv.y;
                        *(float2*)&ho[gi] = o;
                    }
            }
        }

        // ---- skip GEMM -> RMW ----
        {
            const int snb = (w & 3) * 32;
            const uint32_t bSh = smaddr(s_wsh) + ((snb + brow8) * PW + bcol4) * 4;
            const uint32_t bSl = smaddr(s_wsl) + ((snb + brow8) * PW + bcol4) * 4;
            float sacc[4][4][4];
#pragma unroll
            for (int mt = 0; mt < 4; mt++)
#pragma unroll
                for (int nt = 0; nt < 4; nt++)
#pragma unroll
                    for (int rr = 0; rr < 4; rr++) sacc[mt][nt][rr] = 0.f;
#pragma unroll 1
            for (int ks = 0; ks < 4; ks++) {
                const uint32_t off = (uint32_t)(ks * 32);
                uint32_t ah[4][4], al[4][4], bh[2][4], bl[2][4];
#pragma unroll
                for (int mt = 0; mt < 4; mt++) {
                    ldm_x4(ah[mt], aGh + (uint32_t)(mt * 16 * PW * 4) + off);
                    ldm_x4(al[mt], aGl + (uint32_t)(mt * 16 * PW * 4) + off);
                }
#pragma unroll
                for (int tt = 0; tt < 2; tt++) {
                    ldm_x4(bh[tt], bSh + (uint32_t)(tt * 16 * PW * 4) + off);
                    ldm_x4(bl[tt], bSl + (uint32_t)(tt * 16 * PW * 4) + off);
                }
#pragma unroll
                for (int mt = 0; mt < 4; mt++)
#pragma unroll
                    for (int nt = 0; nt < 4; nt++) {
                        const uint32_t* bhp = &bh[nt >> 1][(nt & 1) * 2];
                        const uint32_t* blp = &bl[nt >> 1][(nt & 1) * 2];
                        mma_bf16(sacc[mt][nt], ah[mt], bhp);
                        mma_bf16(sacc[mt][nt], ah[mt], blp);
                        mma_bf16(sacc[mt][nt], al[mt], bhp);
                    }
            }
            float* sk = g_skip + (size_t)b * LL * 128;
#pragma unroll
            for (int nt = 0; nt < 4; nt++) {
                int s = snb + nt * 8 + 2 * lc;
                float2 bsv = *(const float2*)&bs[s];
#pragma unroll
                for (int mt = 0; mt < 4; mt++)
#pragma unroll
                    for (int rh = 0; rh < 2; rh++) {
                        int pos = posb + mt * 16 + lr + rh * 8;
                        size_t gi = (size_t)(l0 + pos) * 128 + s;
                        float2 v;
                        v.x = sacc[mt][nt][rh * 2 + 0] + bsv.x;
                        v.y = sacc[mt][nt][rh * 2 + 1] + bsv.y;
                        if (!first) {
                            float2 old = *(const float2*)&sk[gi];
                            v.x += old.x; v.y += old.y;
                        }
                        *(float2*)&sk[gi] = v;
                    }
            }
        }

        __syncthreads();
        if (tid == 0) st_rel(&g_flags[i * 2048 + b * 32 + t], 1);

    } else {
        // =================== POST TILE ===================
        // wait on the final layer's flag for this tile
        if (tid == 0) {
            const int* f = &g_flags[(NBLK - 1) * 2048 + b * 32 + t];
            while (ld_acq(f) == 0) { __nanosleep(64); }
        }
        __syncthreads();

        // ---- stage relu(skip) split ----
        {
            int cp = tid & 63, p0 = tid >> 6;
            const float* sk = g_skip + (size_t)b * LL * 128;
#pragma unroll
            for (int p = p0; p < 128; p += 4) {
                float2 v = *(const float2*)(sk + (size_t)(l0 + p) * 128 + 2 * cp);
                v.x = fmaxf(v.x, 0.f); v.y = fmaxf(v.y, 0.f);
                uint32_t hi, lo; bfsplit2(v.x, v.y, hi, lo);
                s_xh[p * PX + cp] = hi; s_xl[p * PX + cp] = lo;
            }
        }
        cp_wait0();
        __syncthreads();

        const uint32_t aXh = smaddr(s_xh) + ((posb + arow8) * PX + acol4) * 4;
        const uint32_t aXl = aXh + 128 * PX * 4;
        const uint32_t bCh = smaddr(s_cwh) + ((nb + brow8) * PW + bcol4) * 4;
        const uint32_t bCl = bCh + 128 * PW * 4;

        // ---- GEMM1: D1[pos][o1] = act * w1, K-halved ----
        float acc[4][4][4];
#pragma unroll
        for (int mt = 0; mt < 4; mt++)
#pragma unroll
            for (int nt = 0; nt < 4; nt++)
#pragma unroll
                for (int rr = 0; rr < 4; rr++) acc[mt][nt][rr] = 0.f;

#pragma unroll 1
        for (int half = 0; half < 2; half++) {
            if (half == 1) {
                __syncthreads();
                const uint32_t dh = smaddr(s_cwh), dl = smaddr(s_cwl);
                for (int e = tid; e < 1024; e += 256) {
                    int row = e >> 3, q = e & 7;
                    cp16(dh + (row * PW + q * 4) * 4, &g_w1h[row * 64 + 32 + q * 4]);
                    cp16(dl + (row * PW + q * 4) * 4, &g_w1l[row * 64 + 32 + q * 4]);
                }
                cp_commit();
                cp_wait0();
                __syncthreads();
            }
#pragma unroll 1
            for (int ksl = 0; ksl < 4; ksl++) {
                const uint32_t offX = (uint32_t)((half * 4 + ksl) * 32);
                const uint32_t offW = (uint32_t)(ksl * 32);
                uint32_t ah[4][4], al[4][4], bh[2][4], bl[2][4];
#pragma unroll
                for (int mt = 0; mt < 4; mt++) {
                    ldm_x4(ah[mt], aXh + (uint32_t)(mt * 16 * PX * 4) + offX);
                    ldm_x4(al[mt], aXl + (uint32_t)(mt * 16 * PX * 4) + offX);
                }
#pragma unroll
                for (int tt = 0; tt < 2; tt++) {
                    ldm_x4(bh[tt], bCh + (uint32_t)(tt * 16 * PW * 4) + offW);
                    ldm_x4(bl[tt], bCl + (uint32_t)(tt * 16 * PW * 4) + offW);
                }
#pragma unroll
                for (int mt = 0; mt < 4; mt++)
#pragma unroll
                    for (int nt = 0; nt < 4; nt++) {
                        const uint32_t* bhp = &bh[nt >> 1][(nt & 1) * 2];
                        const uint32_t* blp = &bl[nt >> 1][(nt & 1) * 2];
                        mma_bf16(acc[mt][nt], ah[mt], bhp);
                        mma_bf16(acc[mt][nt], ah[mt], blp);
                        mma_bf16(acc[mt][nt], al[mt], bhp);
                    }
            }
        }
        __syncthreads();   // all GEMM1 act reads done

        // ---- issue w2 half-0; relu+bias scatter back into act arrays ----
        {
            const uint32_t dh = smaddr(s_cwh), dl = smaddr(s_cwl);
            for (int e = tid; e < 1024; e += 256) {
                int row = e >> 3, q = e & 7;
                cp16(dh + (row * PW + q * 4) * 4, &g_w2h[row * 64 + q * 4]);
                cp16(dl + (row * PW + q * 4) * 4, &g_w2l[row * 64 + q * 4]);
            }
            cp_commit();
        }
        {
            uint16_t* xh16 = (uint16_t*)s_xh;
            uint16_t* xl16 = (uint16_t*)s_xl;
#pragma unroll
            for (int nt = 0; nt < 4; nt++) {
                int o1 = nb + nt * 8 + 2 * lc;
                float bv0 = b1g[o1], bv1 = b1g[o1 + 1];
#pragma unroll
                for (int mt = 0; mt < 4; mt++)
#pragma unroll
                    for (int rh = 0; rh < 2; rh++) {
                        int pos = posb + mt * 16 + lr + rh * 8;
                        float v0 = fmaxf(acc[mt][nt][rh * 2 + 0] + bv0, 0.f);
                        float v1 = fmaxf(acc[mt][nt][rh * 2 + 1] + bv1, 0.f);
                        uint16_t h0, l0w, h1, l1w;
                        bfsplit1(v0, h0, l0w); bfsplit1(v1, h1, l1w);
                        int wi = (pos * PX + (nb >> 1) + nt * 4 + lc) * 2;
                        xh16[wi] = h0; xh16[wi + 1] = h1;
                        xl16[wi] = l0w; xl16[wi + 1] = l1w;
                    }
            }
        }
        cp_wait0();
        __syncthreads();

        // ---- GEMM2: D2[pos][o2] = relu(D1) * w2, K-halved ----
        float acc2[4][4][4];
#pragma unroll
        for (int mt = 0; mt < 4; mt++)
#pragma unroll
            for (int nt = 0; nt < 4; nt++)
#pragma unroll
                for (int rr = 0; rr < 4; rr++) acc2[mt][nt][rr] = 0.f;

#pragma unroll 1
        for (int half = 0; half < 2; half++) {
            if (half == 1) {
                __syncthreads();
                const uint32_t dh = smaddr(s_cwh), dl = smaddr(s_cwl);
                for (int e = tid; e < 1024; e += 256) {
                    int row = e >> 3, q = e & 7;
                    cp16(dh + (row * PW + q * 4) * 4, &g_w2h[row * 64 + 32 + q * 4]);
                    cp16(dl + (row * PW + q * 4) * 4, &g_w2l[row * 64 + 32 + q * 4]);
                }
                cp_commit();
                cp_wait0();
                __syncthreads();
            }
#pragma unroll 1
            for (int ksl = 0; ksl < 4; ksl++) {
                const uint32_t offX = (uint32_t)((half * 4 + ksl) * 32);
                const uint32_t offW = (uint32_t)(ksl * 32);
                uint32_t ah[4][4], al[4][4], bh[2][4], bl[2][4];
#pragma unroll
                for (int mt = 0; mt < 4; mt++) {
                    ldm_x4(ah[mt], aXh + (uint32_t)(mt * 16 * PX * 4) + offX);
                    ldm_x4(al[mt], aXl + (uint32_t)(mt * 16 * PX * 4) + offX);
                }
#pragma unroll
                for (int tt = 0; tt < 2; tt++) {
                    ldm_x4(bh[tt], bCh + (uint32_t)(tt * 16 * PW * 4) + offW);
                    ldm_x4(bl[tt], bCl + (uint32_t)(tt * 16 * PW * 4) + offW);
                }
#pragma unroll
                for (int mt = 0; mt < 4; mt++)
#pragma unroll
                    for (int nt = 0; nt < 4; nt++) {
                        const uint32_t* bhp = &bh[nt >> 1][(nt & 1) * 2];
                        const uint32_t* blp = &bl[nt >> 1][(nt & 1) * 2];
                        mma_bf16(acc2[mt][nt], ah[mt], bhp);
                        mma_bf16(acc2[mt][nt], ah[mt], blp);
                        mma_bf16(acc2[mt][nt], al[mt], bhp);
                    }
            }
        }

        // ---- register column sums (sum over 128 positions per channel) ----
        float s8[4][2];
#pragma unroll
        for (int nt = 0; nt < 4; nt++)
#pragma unroll
            for (int co = 0; co < 2; co++) {
                float s = 0.f;
#pragma unroll
                for (int mt = 0; mt < 4; mt++)
#pragma unroll
                    for (int rh = 0; rh < 2; rh++) s += acc2[mt][nt][rh * 2 + co];
                s8[nt][co] = s;
            }
#pragma unroll
        for (int m = 4; m <= 16; m <<= 1)
#pragma unroll
            for (int nt = 0; nt < 4; nt++)
#pragma unroll
                for (int co = 0; co < 2; co++)
                    s8[nt][co] += __shfl_xor_sync(0xffffffff, s8[nt][co], m);

        __syncthreads();   // all GEMM2 weight reads done -> reuse region B
        float* sred = (float*)s_cwh;   // [2][128]
        if (lr == 0) {
#pragma unroll
            for (int nt = 0; nt < 4; nt++)
#pragma unroll
                for (int co = 0; co < 2; co++)
                    sred[(w >> 2) * 128 + nb + nt * 8 + 2 * lc + co] = s8[nt][co];
        }
        __syncthreads();
        if (tid < 128)
            g_partial[((size_t)b * 32 + t) * 128 + tid] =
                sred[tid] + sred[128 + tid] + 128.f * b2g[tid];
    }
}

// ---------------------------------------------------------------------------
__global__ __launch_bounds__(256) void final_kernel(
    const float* __restrict__ partial,
    const float* __restrict__ wf1, const float* __restrict__ bf1,
    const float* __restrict__ wf2, const float* __restrict__ bf2,
    const float* __restrict__ wf3, const float* __restrict__ bf3,
    float* __restrict__ out)
{
    __shared__ float pooled[128];
    __shared__ float z1[256];
    __shared__ float z2[128];
    int b = blockIdx.x, tid = threadIdx.x;
    if (tid < 128) {
        float s = 0.f;
        for (int t = 0; t < 32; t++) s += partial[((size_t)b * 32 + t) * 128 + tid];
        pooled[tid] = s * (1.f / (float)LL);
    }
    __syncthreads();
    {
        float a = bf1[tid];
        for (int c = 0; c < 128; c++) a += wf1[tid * 128 + c] * pooled[c];
        z1[tid] = fmaxf(a, 0.f);
    }
    __syncthreads();
    if (tid < 128) {
        float a = bf2[tid];
        for (int c = 0; c < 256; c++) a += wf2[tid * 256 + c] * z1[c];
        z2[tid] = fmaxf(a, 0.f);
    }
    __syncthreads();
    if (tid < 6) {
        float a = bf3[tid];
        for (int c = 0; c < 128; c++) a += wf3[tid * 128 + c] * z2[c];
        out[b * 6 + tid] = a;
    }
}

// ---------------------------------------------------------------------------
extern "C" void kernel_launch(void* const* d_in, const int* in_sizes, int n_in,
                              void* d_out, int out_size)
{
    const float* x      = (const float*)d_in[0];
    const float* w_in   = (const float*)d_in[1];
    const float* b_in   = (const float*)d_in[2];
    const float* w_dil  = (const float*)d_in[3];
    const float* b_dil  = (const float*)d_in[4];
    const float* w_res  = (const float*)d_in[5];
    const float* b_res  = (const float*)d_in[6];
    const float* w_skip = (const float*)d_in[7];
    const float* b_skip = (const float*)d_in[8];
    const float* w_out1 = (const float*)d_in[9];
    const float* b_out1 = (const float*)d_in[10];
    const float* w_out2 = (const float*)d_in[11];
    const float* b_out2 = (const float*)d_in[12];
    const float* w_fc1  = (const float*)d_in[13];
    const float* b_fc1  = (const float*)d_in[14];
    const float* w_fc2  = (const float*)d_in[15];
    const float* b_fc2  = (const float*)d_in[16];
    const float* w_fc3  = (const float*)d_in[17];
    const float* b_fc3  = (const float*)d_in[18];
    float* out = (float*)d_out;

    float *h0, *partial;
    int* flags;
    cudaGetSymbolAddress((void**)&h0,      g_h0);
    cudaGetSymbolAddress((void**)&partial, g_partial);
    cudaGetSymbolAddress((void**)&flags,   g_flags);

    const int BLOCK_SMEM = (2 * 128 * PX + 2 * 128 * PW) * 4;    // 106,496 B
    cudaFuncSetAttribute(mega_kernel, cudaFuncAttributeMaxDynamicSharedMemorySize, BLOCK_SMEM);

    cudaMemsetAsync(flags, 0, NBLK * BB * 32 * sizeof(int));
    split_kernel<<<(NBLK * 14336 + 16384 + 255) / 256, 256>>>(w_dil, w_res, w_skip, w_out1, w_out2);
    proj_kernel<<<(BB * LL * 64) / 256, 256>>>(x, w_in, b_in, h0);

    mega_kernel<<<(NBLK + 1) * 2048, 256, BLOCK_SMEM>>>(b_dil, b_res, b_skip, b_out1, b_out2);

    final_kernel<<<BB, 256>>>(partial, w_fc1, b_fc1, w_fc2, b_fc2, w_fc3, b_fc3, out);
}

// round 17
// speedup vs baseline: 1.6038x; 1.0110x over previous
#include <cuda_runtime.h>
#include <cuda_bf16.h>
#include <math.h>
#include <stdint.h>

#define BB   64
#define LL   4096
#define RC   64
#define SC   128
#define NBLK 30
#define PX   68     // act pitch (words), 68 mod 32 == 4 -> conflict-free
#define PW   36     // weight/G pitch (words), 36 mod 32 == 4

// Static device scratch (allocation-free contract)
__device__ float g_h0[(size_t)BB * LL * RC];
__device__ float g_h1[(size_t)BB * LL * RC];
__device__ float g_skip[(size_t)BB * LL * SC];
__device__ float g_partial[(size_t)BB * 32 * SC];
__device__ int   g_flags[(NBLK + 1) * BB * 32];
// pre-split weights (bf16x2 hi/lo pair-words)
__device__ uint32_t g_wdch[NBLK * 8192], g_wdcl[NBLK * 8192];
__device__ uint32_t g_wrh[NBLK * 2048], g_wrl[NBLK * 2048];
__device__ uint32_t g_wsh[NBLK * 4096], g_wsl[NBLK * 4096];
__device__ uint32_t g_w1h[8192], g_w1l[8192];   // out1 [128 o][64 pairs]
__device__ uint32_t g_w2h[8192], g_w2l[8192];   // out2 [128 o][64 pairs]

// ---------------------------------------------------------------------------
__device__ __forceinline__ void bfsplit2(float v0, float v1, uint32_t& hi, uint32_t& lo) {
    __nv_bfloat16 h0 = __float2bfloat16_rn(v0);
    __nv_bfloat16 h1 = __float2bfloat16_rn(v1);
    float r0 = v0 - __bfloat162float(h0);
    float r1 = v1 - __bfloat162float(h1);
    __nv_bfloat16 l0 = __float2bfloat16_rn(r0);
    __nv_bfloat16 l1 = __float2bfloat16_rn(r1);
    hi = (uint32_t)__bfloat16_as_ushort(h0) | ((uint32_t)__bfloat16_as_ushort(h1) << 16);
    lo = (uint32_t)__bfloat16_as_ushort(l0) | ((uint32_t)__bfloat16_as_ushort(l1) << 16);
}
__device__ __forceinline__ void bfsplit1(float v, uint16_t& hi, uint16_t& lo) {
    __nv_bfloat16 h = __float2bfloat16_rn(v);
    float r = v - __bfloat162float(h);
    hi = __bfloat16_as_ushort(h);
    lo = __bfloat16_as_ushort(__float2bfloat16_rn(r));
}

__device__ __forceinline__ void mma_bf16(float* d, const uint32_t* a, const uint32_t* b) {
    asm volatile(
        "mma.sync.aligned.m16n8k16.row.col.f32.bf16.bf16.f32 "
        "{%0,%1,%2,%3}, {%4,%5,%6,%7}, {%8,%9}, {%0,%1,%2,%3};"
        : "+f"(d[0]), "+f"(d[1]), "+f"(d[2]), "+f"(d[3])
        : "r"(a[0]), "r"(a[1]), "r"(a[2]), "r"(a[3]), "r"(b[0]), "r"(b[1]));
}

__device__ __forceinline__ uint32_t smaddr(const void* p) {
    return (uint32_t)__cvta_generic_to_shared(p);
}
__device__ __forceinline__ void ldm_x4(uint32_t* r, uint32_t addr) {
    asm volatile("ldmatrix.sync.aligned.m8n8.x4.shared.b16 {%0,%1,%2,%3}, [%4];"
        : "=r"(r[0]), "=r"(r[1]), "=r"(r[2]), "=r"(r[3]) : "r"(addr));
}
__device__ __forceinline__ void cp16(uint32_t dst, const void* src) {
    asm volatile("cp.async.cg.shared.global [%0], [%1], 16;" :: "r"(dst), "l"(src));
}
__device__ __forceinline__ void cp_commit() {
    asm volatile("cp.async.commit_group;");
}
__device__ __forceinline__ void cp_wait0() {
    asm volatile("cp.async.wait_group 0;");
}
__device__ __forceinline__ int ld_acq(const int* p) {
    int v;
    asm volatile("ld.acquire.gpu.global.b32 %0, [%1];" : "=r"(v) : "l"(p));
    return v;
}
__device__ __forceinline__ void st_rel(int* p, int v) {
    asm volatile("st.release.gpu.global.b32 [%0], %1;" :: "l"(p), "r"(v));
}

__device__ __forceinline__ float fast_gate(float t, float s) {
    float th = 2.f * __fdividef(1.f, 1.f + __expf(-2.f * t)) - 1.f;
    float sg = __fdividef(1.f, 1.f + __expf(-s));
    return th * sg;
}

// ---------------------------------------------------------------------------
__global__ __launch_bounds__(256) void split_kernel(
    const float* __restrict__ wd, const float* __restrict__ wr,
    const float* __restrict__ ws, const float* __restrict__ w1,
    const float* __restrict__ w2)
{
    int id = blockIdx.x * 256 + threadIdx.x;
    if (id >= NBLK * 14336 + 16384) return;
    if (id >= NBLK * 14336) {
        int r2 = id - NBLK * 14336;
        const float* src = (r2 < 8192) ? w1 : w2;
        uint32_t* dh = (r2 < 8192) ? g_w1h : g_w2h;
        uint32_t* dl = (r2 < 8192) ? g_w1l : g_w2l;
        int off = r2 & 8191;
        float2 v = *(const float2*)(src + 2 * off);
        uint32_t hi, lo; bfsplit2(v.x, v.y, hi, lo);
        dh[off] = hi; dl[off] = lo;
        return;
    }
    int i = id / 14336, r = id % 14336;
    if (r < 8192) {
        int op = r >> 6, j = r & 63;
        int o = ((op & 1) << 6) + (op >> 1);          // permuted source row
        float2 v = *(const float2*)(wd + (size_t)i * 16384 + o * 128 + 2 * j);
        uint32_t hi, lo; bfsplit2(v.x, v.y, hi, lo);
        g_wdch[i * 8192 + r] = hi; g_wdcl[i * 8192 + r] = lo;
    } else if (r < 10240) {
        int off = r - 8192;
        float2 v = *(const float2*)(wr + (size_t)i * 4096 + 2 * off);
        uint32_t hi, lo; bfsplit2(v.x, v.y, hi, lo);
        g_wrh[i * 2048 + off] = hi; g_wrl[i * 2048 + off] = lo;
    } else {
        int off = r - 10240;
        float2 v = *(const float2*)(ws + (size_t)i * 8192 + 2 * off);
        uint32_t hi, lo; bfsplit2(v.x, v.y, hi, lo);
        g_wsh[i * 4096 + off] = hi; g_wsl[i * 4096 + off] = lo;
    }
}

// ---------------------------------------------------------------------------
// 30 WaveNet layers + post MLP + head, all in ONE launch.
//  bx < 31*2048 : i<NBLK layer CTA / i==NBLK post tile (both as R16; layer 0
//                 additionally computes the input projection inline from x).
//  bx >= 31*2048: head CTA for batch fb — waits on post flags, runs the MLP.
// ---------------------------------------------------------------------------
__global__ __launch_bounds__(256, 2) void mega_kernel(
    const float* __restrict__ xg, const float* __restrict__ w_in,
    const float* __restrict__ b_in,
    const float* __restrict__ b_dil, const float* __restrict__ b_res,
    const float* __restrict__ b_skip,
    const float* __restrict__ b1g, const float* __restrict__ b2g,
    const float* __restrict__ wf1, const float* __restrict__ bf1,
    const float* __restrict__ wf2, const float* __restrict__ bf2,
    const float* __restrict__ wf3, const float* __restrict__ bf3,
    float* __restrict__ out)
{
    extern __shared__ uint32_t smw[];
    uint32_t* s_xh = smw;                         // [128 pos][PX]
    uint32_t* s_xl = smw + 128 * PX;
    uint32_t* s_gh  = smw;                        // [128 pos][PW] (overlay)
    uint32_t* s_gl  = smw + 128 * PW;
    uint32_t* s_cwh = smw + 2 * 128 * PX;         // [128][PW]
    uint32_t* s_cwl = s_cwh + 128 * PW;
    uint32_t* s_wrh = s_cwh;                      // [64][PW]  (overlay)
    uint32_t* s_wrl = s_cwh + 64 * PW;
    uint32_t* s_wsh = s_cwh + 128 * PW;           // [128][PW] (overlay)
    uint32_t* s_wsl = smw + 2 * 128 * PW;         // [128][PW] (overlay in region A)
    float*    s_xs  = (float*)(smw + 2 * 128 * PX + 2 * 128 * PW);  // [8][132]

    const int tid  = threadIdx.x;
    const int lane = tid & 31;
    const int w    = tid >> 5;
    const int lr   = lane >> 2;
    const int lc   = lane & 3;

    const int bx = blockIdx.x;
    const int total_lp = (NBLK + 1) * 2048;

    if (bx >= total_lp) {
        // =================== HEAD CTA ===================
        const int fb = bx - total_lp;
        if (tid < 32) {
            const int* f = &g_flags[NBLK * 2048 + fb * 32 + tid];
            while (ld_acq(f) == 0) { __nanosleep(64); }
        }
        __syncthreads();
        float* pooled = (float*)smw;        // [128]
        float* z1     = pooled + 128;       // [256]
        float* z2     = z1 + 256;           // [128]
        if (tid < 128) {
            float s = 0.f;
            for (int tt = 0; tt < 32; tt++)
                s += g_partial[((size_t)fb * 32 + tt) * 128 + tid];
            pooled[tid] = s * (1.f / (float)LL);
        }
        __syncthreads();
        {
            float a = bf1[tid];
            for (int c = 0; c < 128; c++) a += wf1[tid * 128 + c] * pooled[c];
            z1[tid] = fmaxf(a, 0.f);
        }
        __syncthreads();
        if (tid < 128) {
            float a = bf2[tid];
            for (int c = 0; c < 256; c++) a += wf2[tid * 256 + c] * z1[c];
            z2[tid] = fmaxf(a, 0.f);
        }
        __syncthreads();
        if (tid < 6) {
            float a = bf3[tid];
            for (int c = 0; c < 128; c++) a += wf3[tid * 128 + c] * z2[c];
            out[fb * 6 + tid] = a;
        }
        return;
    }

    const int i  = bx >> 11;            // 0..NBLK (NBLK = post)
    const int r  = bx & 2047;
    const int b  = r >> 5;
    const int t  = r & 31;
    const int l0 = t * 128;

    const uint32_t* wdch = (i < NBLK) ? g_wdch + i * 8192 : g_w1h;
    const uint32_t* wdcl = (i < NBLK) ? g_wdcl + i * 8192 : g_w1l;

    const int arow8 = (lane & 7) + ((lane >> 3) & 1) * 8;
    const int acol4 = (lane >> 4) * 4;
    const int brow8 = (lane & 7) + ((lane >> 4) & 1) * 8;
    const int bcol4 = ((lane >> 3) & 1) * 4;

    // ---- issue first GEMM's weight half-0 (no data dependency) ----
    {
        const uint32_t dh = smaddr(s_cwh), dl = smaddr(s_cwl);
        for (int e = tid; e < 1024; e += 256) {
            int row = e >> 3, q = e & 7;
            cp16(dh + (row * PW + q * 4) * 4, &wdch[row * 64 + q * 4]);
            cp16(dl + (row * PW + q * 4) * 4, &wdcl[row * 64 + q * 4]);
        }
        cp_commit();
    }

    const int posb = (w >> 2) * 64;
    const int nb   = (w & 3) * 32;

    if (i < NBLK) {
        // =================== LAYER CTA ===================
        const int d     = 1 << (i % 10);
        const int first = (i == 0);
        const uint32_t* wrh = g_wrh + i * 2048;
        const uint32_t* wrl = g_wrl + i * 2048;
        const uint32_t* wsh = g_wsh + i * 4096;
        const uint32_t* wsl = g_wsl + i * 4096;
        const float* bd = b_dil  + i * 128;
        const float* br = b_res  + i * 64;
        const float* bs = b_skip + i * 128;
        const float* h_in  = (i & 1) ? g_h1 : g_h0;
        float*       h_out = (i & 1) ? g_h0 : g_h1;

        if (i > 0) {
            int jlo = t - 4; if (jlo < 0) jlo = 0;
            int jhi = t + 4; if (jhi > 31) jhi = 31;
            int nj = jhi - jlo + 1;
            if (w == 0 && lane < nj) {
                const int* f = &g_flags[(i - 1) * 2048 + b * 32 + jlo + lane];
                while (ld_acq(f) == 0) { __nanosleep(64); }
            }
        }
        __syncthreads();

        // ---- stage X split ----
        if (first) {
            // inline input projection: h = w_in·x + b_in, from x tile + halo
            for (int e = tid; e < 8 * 129; e += 256) {
                int ch = e / 129, p = e % 129;
                int l = l0 - 1 + p;
                s_xs[ch * 132 + p] = (l >= 0) ? xg[((size_t)(b * 8 + ch)) * LL + l] : 0.f;
            }
            int c = tid & 63, p0 = tid >> 6;
            float wv[8];
#pragma unroll
            for (int ic = 0; ic < 8; ic++) wv[ic] = w_in[c * 8 + ic];
            float bv = b_in[c];
            __syncthreads();
            float* ho0 = g_h0 + (size_t)b * LL * 64;
            for (int p = p0; p < 128; p += 4) {
                float cur = bv, del = bv;
#pragma unroll
                for (int ic = 0; ic < 8; ic++) {
                    cur += wv[ic] * s_xs[ic * 132 + p + 1];
                    del += wv[ic] * s_xs[ic * 132 + p];
                }
                if (l0 + p - 1 < 0) del = 0.f;     // causal zero-pad of h
                uint32_t hi, lo; bfsplit2(del, cur, hi, lo);
                s_xh[p * PX + c] = hi; s_xl[p * PX + c] = lo;
                ho0[(size_t)(l0 + p) * 64 + c] = cur;
            }
        } else {
            int c = tid & 63, p0 = tid >> 6;
            const float* hb = h_in + (size_t)b * LL * 64;
#pragma unroll
            for (int g = 0; g < 4; g++) {
                float curv[8], delv[8];
#pragma unroll
                for (int ii = 0; ii < 8; ii++) {
                    int p = p0 + (g * 8 + ii) * 4;
                    int l = l0 + p, ld = l - d;
                    curv[ii] = hb[(size_t)l * 64 + c];
                    delv[ii] = (ld >= 0) ? hb[(size_t)ld * 64 + c] : 0.f;
                }
#pragma unroll
                for (int ii = 0; ii < 8; ii++) {
                    int p = p0 + (g * 8 + ii) * 4;
                    uint32_t hi, lo; bfsplit2(delv[ii], curv[ii], hi, lo);
                    s_xh[p * PX + c] = hi; s_xl[p * PX + c] = lo;
                }
            }
        }
        cp_wait0();
        __syncthreads();

        // ---- conv GEMM ----
        float acc[4][4][4];
#pragma unroll
        for (int mt = 0; mt < 4; mt++)
#pragma unroll
            for (int nt = 0; nt < 4; nt++)
#pragma unroll
                for (int rr = 0; rr < 4; rr++) acc[mt][nt][rr] = 0.f;

        const uint32_t aXh = smaddr(s_xh) + ((posb + arow8) * PX + acol4) * 4;
        const uint32_t aXl = aXh + 128 * PX * 4;
        const uint32_t bCh = smaddr(s_cwh) + ((nb + brow8) * PW + bcol4) * 4;
        const uint32_t bCl = bCh + 128 * PW * 4;

#pragma unroll 1
        for (int half = 0; half < 2; half++) {
            if (half == 1) {
                __syncthreads();
                const uint32_t dh = smaddr(s_cwh), dl = smaddr(s_cwl);
                for (int e = tid; e < 1024; e += 256) {
                    int row = e >> 3, q = e & 7;
                    cp16(dh + (row * PW + q * 4) * 4, &wdch[row * 64 + 32 + q * 4]);
                    cp16(dl + (row * PW + q * 4) * 4, &wdcl[row * 64 + 32 + q * 4]);
                }
                cp_commit();
                cp_wait0();
                __syncthreads();
            }
#pragma unroll 1
            for (int ksl = 0; ksl < 4; ksl++) {
                const uint32_t offX = (uint32_t)((half * 4 + ksl) * 32);
                const uint32_t offW = (uint32_t)(ksl * 32);
                uint32_t ah[4][4], al[4][4], bh[2][4], bl[2][4];
#pragma unroll
                for (int mt = 0; mt < 4; mt++) {
                    ldm_x4(ah[mt], aXh + (uint32_t)(mt * 16 * PX * 4) + offX);
                    ldm_x4(al[mt], aXl + (uint32_t)(mt * 16 * PX * 4) + offX);
                }
#pragma unroll
                for (int tt = 0; tt < 2; tt++) {
                    ldm_x4(bh[tt], bCh + (uint32_t)(tt * 16 * PW * 4) + offW);
                    ldm_x4(bl[tt], bCl + (uint32_t)(tt * 16 * PW * 4) + offW);
                }
#pragma unroll
                for (int mt = 0; mt < 4; mt++)
#pragma unroll
                    for (int nt = 0; nt < 4; nt++) {
                        const uint32_t* bhp = &bh[nt >> 1][(nt & 1) * 2];
                        const uint32_t* blp = &bl[nt >> 1][(nt & 1) * 2];
                        mma_bf16(acc[mt][nt], ah[mt], bhp);
                        mma_bf16(acc[mt][nt], ah[mt], blp);
                        mma_bf16(acc[mt][nt], al[mt], bhp);
                    }
            }
        }
        __syncthreads();

        // ---- wr/ws cp.async + register gate ----
        {
            const uint32_t dwrh = smaddr(s_wrh), dwrl = smaddr(s_wrl);
            const uint32_t dwsh = smaddr(s_wsh), dwsl = smaddr(s_wsl);
            for (int e = tid; e < 512; e += 256) {
                int row = e >> 3, q = e & 7;
                cp16(dwrh + (row * PW + q * 4) * 4, &wrh[row * 32 + q * 4]);
                cp16(dwrl + (row * PW + q * 4) * 4, &wrl[row * 32 + q * 4]);
            }
            for (int e = tid; e < 1024; e += 256) {
                int row = e >> 3, q = e & 7;
                cp16(dwsh + (row * PW + q * 4) * 4, &wsh[row * 32 + q * 4]);
                cp16(dwsl + (row * PW + q * 4) * 4, &wsl[row * 32 + q * 4]);
            }
            cp_commit();
        }
        {
            uint16_t* gh16 = (uint16_t*)s_gh;
            uint16_t* gl16 = (uint16_t*)s_gl;
#pragma unroll
            for (int nt = 0; nt < 4; nt++) {
                int j = (nb >> 1) + nt * 4 + lc;
                float bt = bd[j], bsg = bd[64 + j];
#pragma unroll
                for (int mt = 0; mt < 4; mt++)
#pragma unroll
                    for (int rh = 0; rh < 2; rh++) {
                        float tv = acc[mt][nt][rh * 2 + 0] + bt;
                        float sv = acc[mt][nt][rh * 2 + 1] + bsg;
                        float g = fast_gate(tv, sv);
                        int pos = posb + mt * 16 + lr + rh * 8;
                        uint16_t hi, lo; bfsplit1(g, hi, lo);
                        int wi = (pos * PW + (j >> 1)) * 2 + (j & 1);
                        gh16[wi] = hi; gl16[wi] = lo;
                    }
            }
        }
        cp_wait0();
        __syncthreads();

        const uint32_t aGh = smaddr(s_gh) + ((posb + arow8) * PW + acol4) * 4;
        const uint32_t aGl = aGh + 128 * PW * 4;

        // ---- res GEMM -> h_out ----
        {
            const int rnb = (w & 3) * 16;
            const uint32_t bRh = smaddr(s_wrh) + ((rnb + brow8) * PW + bcol4) * 4;
            const uint32_t bRl = bRh + 64 * PW * 4;
            float racc[4][2][4];
#pragma unroll
            for (int mt = 0; mt < 4; mt++)
#pragma unroll
                for (int nt = 0; nt < 2; nt++)
#pragma unroll
                    for (int rr = 0; rr < 4; rr++) racc[mt][nt][rr] = 0.f;
#pragma unroll 1
            for (int ks = 0; ks < 4; ks++) {
                const uint32_t off = (uint32_t)(ks * 32);
                uint32_t ah[4][4], al[4][4], bh[4], bl[4];
#pragma unroll
                for (int mt = 0; mt < 4; mt++) {
                    ldm_x4(ah[mt], aGh + (uint32_t)(mt * 16 * PW * 4) + off);
                    ldm_x4(al[mt], aGl + (uint32_t)(mt * 16 * PW * 4) + off);
                }
                ldm_x4(bh, bRh + off);
                ldm_x4(bl, bRl + off);
#pragma unroll
                for (int mt = 0; mt < 4; mt++)
#pragma unroll
                    for (int nt = 0; nt < 2; nt++) {
                        mma_bf16(racc[mt][nt], ah[mt], &bh[nt * 2]);
                        mma_bf16(racc[mt][nt], ah[mt], &bl[nt * 2]);
                        mma_bf16(racc[mt][nt], al[mt], &bh[nt * 2]);
                    }
            }
            const float* hb = h_in + (size_t)b * LL * 64;
            float* ho = h_out + (size_t)b * LL * 64;
#pragma unroll
            for (int nt = 0; nt < 2; nt++) {
                int c = rnb + nt * 8 + 2 * lc;
                float2 brv = *(const float2*)&br[c];
#pragma unroll
                for (int mt = 0; mt < 4; mt++)
#pragma unroll
                    for (int rh = 0; rh < 2; rh++) {
                        int pos = posb + mt * 16 + lr + rh * 8;
                        size_t gi = (size_t)(l0 + pos) * 64 + c;
                        float2 hv = *(const float2*)&hb[gi];
                        float2 o;
                        o.x = racc[mt][nt][rh * 2 + 0] + brv.x + hv.x;
                        o.y = racc[mt][nt][rh * 2 + 1] + brv.y + hv.y;
                        *(float2*)&ho[gi] = o;
                    }
            }
        }

        // ---- skip GEMM -> RMW ----
        {
            const int snb = (w & 3) * 32;
            const uint32_t bSh = smaddr(s_wsh) + ((snb + brow8) * PW + bcol4) * 4;
            const uint32_t bSl = smaddr(s_wsl) + ((snb + brow8) * PW + bcol4) * 4;
            float sacc[4][4][4];
#pragma unroll
            for (int mt = 0; mt < 4; mt++)
#pragma unroll
                for (int nt = 0; nt < 4; nt++)
#pragma unroll
                    for (int rr = 0; rr < 4; rr++) sacc[mt][nt][rr] = 0.f;
#pragma unroll 1
            for (int ks = 0; ks < 4; ks++) {
                const uint32_t off = (uint32_t)(ks * 32);
                uint32_t ah[4][4], al[4][4], bh[2][4], bl[2][4];
#pragma unroll
                for (int mt = 0; mt < 4; mt++) {
                    ldm_x4(ah[mt], aGh + (uint32_t)(mt * 16 * PW * 4) + off);
                    ldm_x4(al[mt], aGl + (uint32_t)(mt * 16 * PW * 4) + off);
                }
#pragma unroll
                for (int tt = 0; tt < 2; tt++) {
                    ldm_x4(bh[tt], bSh + (uint32_t)(tt * 16 * PW * 4) + off);
                    ldm_x4(bl[tt], bSl + (uint32_t)(tt * 16 * PW * 4) + off);
                }
#pragma unroll
                for (int mt = 0; mt < 4; mt++)
#pragma unroll
                    for (int nt = 0; nt < 4; nt++) {
                        const uint32_t* bhp = &bh[nt >> 1][(nt & 1) * 2];
                        const uint32_t* blp = &bl[nt >> 1][(nt & 1) * 2];
                        mma_bf16(sacc[mt][nt], ah[mt], bhp);
                        mma_bf16(sacc[mt][nt], ah[mt], blp);
                        mma_bf16(sacc[mt][nt], al[mt], bhp);
                    }
            }
            float* sk = g_skip + (size_t)b * LL * 128;
#pragma unroll
            for (int nt = 0; nt < 4; nt++) {
                int s = snb + nt * 8 + 2 * lc;
                float2 bsv = *(const float2*)&bs[s];
#pragma unroll
                for (int mt = 0; mt < 4; mt++)
#pragma unroll
                    for (int rh = 0; rh < 2; rh++) {
                        int pos = posb + mt * 16 + lr + rh * 8;
                        size_t gi = (size_t)(l0 + pos) * 128 + s;
                        float2 v;
                        v.x = sacc[mt][nt][rh * 2 + 0] + bsv.x;
                        v.y = sacc[mt][nt][rh * 2 + 1] + bsv.y;
                        if (!first) {
                            float2 old = *(const float2*)&sk[gi];
                            v.x += old.x; v.y += old.y;
                        }
                        *(float2*)&sk[gi] = v;
                    }
            }
        }

        __syncthreads();
        if (tid == 0) st_rel(&g_flags[i * 2048 + b * 32 + t], 1);

    } else {
        // =================== POST TILE ===================
        if (tid == 0) {
            const int* f = &g_flags[(NBLK - 1) * 2048 + b * 32 + t];
            while (ld_acq(f) == 0) { __nanosleep(64); }
        }
        __syncthreads();

        // ---- stage relu(skip) split ----
        {
            int cp = tid & 63, p0 = tid >> 6;
            const float* sk = g_skip + (size_t)b * LL * 128;
#pragma unroll
            for (int p = p0; p < 128; p += 4) {
                float2 v = *(const float2*)(sk + (size_t)(l0 + p) * 128 + 2 * cp);
                v.x = fmaxf(v.x, 0.f); v.y = fmaxf(v.y, 0.f);
                uint32_t hi, lo; bfsplit2(v.x, v.y, hi, lo);
                s_xh[p * PX + cp] = hi; s_xl[p * PX + cp] = lo;
            }
        }
        cp_wait0();
        __syncthreads();

        const uint32_t aXh = smaddr(s_xh) + ((posb + arow8) * PX + acol4) * 4;
        const uint32_t aXl = aXh + 128 * PX * 4;
        const uint32_t bCh = smaddr(s_cwh) + ((nb + brow8) * PW + bcol4) * 4;
        const uint32_t bCl = bCh + 128 * PW * 4;

        // ---- GEMM1: D1[pos][o1] = act * w1, K-halved ----
        float acc[4][4][4];
#pragma unroll
        for (int mt = 0; mt < 4; mt++)
#pragma unroll
            for (int nt = 0; nt < 4; nt++)
#pragma unroll
                for (int rr = 0; rr < 4; rr++) acc[mt][nt][rr] = 0.f;

#pragma unroll 1
        for (int half = 0; half < 2; half++) {
            if (half == 1) {
                __syncthreads();
                const uint32_t dh = smaddr(s_cwh), dl = smaddr(s_cwl);
                for (int e = tid; e < 1024; e += 256) {
                    int row = e >> 3, q = e & 7;
                    cp16(dh + (row * PW + q * 4) * 4, &g_w1h[row * 64 + 32 + q * 4]);
                    cp16(dl + (row * PW + q * 4) * 4, &g_w1l[row * 64 + 32 + q * 4]);
                }
                cp_commit();
                cp_wait0();
                __syncthreads();
            }
#pragma unroll 1
            for (int ksl = 0; ksl < 4; ksl++) {
                const uint32_t offX = (uint32_t)((half * 4 + ksl) * 32);
                const uint32_t offW = (uint32_t)(ksl * 32);
                uint32_t ah[4][4], al[4][4], bh[2][4], bl[2][4];
#pragma unroll
                for (int mt = 0; mt < 4; mt++) {
                    ldm_x4(ah[mt], aXh + (uint32_t)(mt * 16 * PX * 4) + offX);
                    ldm_x4(al[mt], aXl + (uint32_t)(mt * 16 * PX * 4) + offX);
                }
#pragma unroll
                for (int tt = 0; tt < 2; tt++) {
                    ldm_x4(bh[tt], bCh + (uint32_t)(tt * 16 * PW * 4) + offW);
                    ldm_x4(bl[tt], bCl + (uint32_t)(tt * 16 * PW * 4) + offW);
                }
#pragma unroll
                for (int mt = 0; mt < 4; mt++)
#pragma unroll
                    for (int nt = 0; nt < 4; nt++) {
                        const uint32_t* bhp = &bh[nt >> 1][(nt & 1) * 2];
                        const uint32_t* blp = &bl[nt >> 1][(nt & 1) * 2];
                        mma_bf16(acc[mt][nt], ah[mt], bhp);
                        mma_bf16(acc[mt][nt], ah[mt], blp);
                        mma_bf16(acc[mt][nt], al[mt], bhp);
                    }
            }
        }
        __syncthreads();   // all GEMM1 act reads done

        // ---- issue w2 half-0; relu+bias scatter back into act arrays ----
        {
            const uint32_t dh = smaddr(s_cwh), dl = smaddr(s_cwl);
            for (int e = tid; e < 1024; e += 256) {
                int row = e >> 3, q = e & 7;
                cp16(dh + (row * PW + q * 4) * 4, &g_w2h[row * 64 + q * 4]);
                cp16(dl + (row * PW + q * 4) * 4, &g_w2l[row * 64 + q * 4]);
            }
            cp_commit();
        }
        {
            uint16_t* xh16 = (uint16_t*)s_xh;
            uint16_t* xl16 = (uint16_t*)s_xl;
#pragma unroll
            for (int nt = 0; nt < 4; nt++) {
                int o1 = nb + nt * 8 + 2 * lc;
                float bv0 = b1g[o1], bv1 = b1g[o1 + 1];
#pragma unroll
                for (int mt = 0; mt < 4; mt++)
#pragma unroll
                    for (int rh = 0; rh < 2; rh++) {
                        int pos = posb + mt * 16 + lr + rh * 8;
                        float v0 = fmaxf(acc[mt][nt][rh * 2 + 0] + bv0, 0.f);
                        float v1 = fmaxf(acc[mt][nt][rh * 2 + 1] + bv1, 0.f);
                        uint16_t h0, l0w, h1, l1w;
                        bfsplit1(v0, h0, l0w); bfsplit1(v1, h1, l1w);
                        int wi = (pos * PX + (nb >> 1) + nt * 4 + lc) * 2;
                        xh16[wi] = h0; xh16[wi + 1] = h1;
                        xl16[wi] = l0w; xl16[wi + 1] = l1w;
                    }
            }
        }
        cp_wait0();
        __syncthreads();

        // ---- GEMM2: D2[pos][o2] = relu(D1) * w2, K-halved ----
        float acc2[4][4][4];
#pragma unroll
        for (int mt = 0; mt < 4; mt++)
#pragma unroll
            for (int nt = 0; nt < 4; nt++)
#pragma unroll
                for (int rr = 0; rr < 4; rr++) acc2[mt][nt][rr] = 0.f;

#pragma unroll 1
        for (int half = 0; half < 2; half++) {
            if (half == 1) {
                __syncthreads();
                const uint32_t dh = smaddr(s_cwh), dl = smaddr(s_cwl);
                for (int e = tid; e < 1024; e += 256) {
                    int row = e >> 3, q = e & 7;
                    cp16(dh + (row * PW + q * 4) * 4, &g_w2h[row * 64 + 32 + q * 4]);
                    cp16(dl + (row * PW + q * 4) * 4, &g_w2l[row * 64 + 32 + q * 4]);
                }
                cp_commit();
                cp_wait0();
                __syncthreads();
            }
#pragma unroll 1
            for (int ksl = 0; ksl < 4; ksl++) {
                const uint32_t offX = (uint32_t)((half * 4 + ksl) * 32);
                const uint32_t offW = (uint32_t)(ksl * 32);
                uint32_t ah[4][4], al[4][4], bh[2][4], bl[2][4];
#pragma unroll
                for (int mt = 0; mt < 4; mt++) {
                    ldm_x4(ah[mt], aXh + (uint32_t)(mt * 16 * PX * 4) + offX);
                    ldm_x4(al[mt], aXl + (uint32_t)(mt * 16 * PX * 4) + offX);
                }
#pragma unroll
                for (int tt = 0; tt < 2; tt++) {
                    ldm_x4(bh[tt], bCh + (uint32_t)(tt * 16 * PW * 4) + offW);
                    ldm_x4(bl[tt], bCl + (uint32_t)(tt * 16 * PW * 4) + offW);
                }
#pragma unroll
                for (int mt = 0; mt < 4; mt++)
#pragma unroll
                    for (int nt = 0; nt < 4; nt++) {
                        const uint32_t* bhp = &bh[nt >> 1][(nt & 1) * 2];
                        const uint32_t* blp = &bl[nt >> 1][(nt & 1) * 2];
                        mma_bf16(acc2[mt][nt], ah[mt], bhp);
                        mma_bf16(acc2[mt][nt], ah[mt], blp);
                        mma_bf16(acc2[mt][nt], al[mt], bhp);
                    }
            }
        }

        // ---- register column sums (sum over 128 positions per channel) ----
        float s8[4][2];
#pragma unroll
        for (int nt = 0; nt < 4; nt++)
#pragma unroll
            for (int co = 0; co < 2; co++) {
                float s = 0.f;
#pragma unroll
                for (int mt = 0; mt < 4; mt++)
#pragma unroll
                    for (int rh = 0; rh < 2; rh++) s += acc2[mt][nt][rh * 2 + co];
                s8[nt][co] = s;
            }
#pragma unroll
        for (int m = 4; m <= 16; m <<= 1)
#pragma unroll
            for (int nt = 0; nt < 4; nt++)
#pragma unroll
                for (int co = 0; co < 2; co++)
                    s8[nt][co] += __shfl_xor_sync(0xffffffff, s8[nt][co], m);

        __syncthreads();   // all GEMM2 weight reads done -> reuse region B
        float* sred = (float*)s_cwh;   // [2][128]
        if (lr == 0) {
#pragma unroll
            for (int nt = 0; nt < 4; nt++)
#pragma unroll
                for (int co = 0; co < 2; co++)
                    sred[(w >> 2) * 128 + nb + nt * 8 + 2 * lc + co] = s8[nt][co];
        }
        __syncthreads();
        if (tid < 128)
            g_partial[((size_t)b * 32 + t) * 128 + tid] =
                sred[tid] + sred[128 + tid] + 128.f * b2g[tid];

        __syncthreads();
        if (tid == 0) st_rel(&g_flags[NBLK * 2048 + b * 32 + t], 1);
    }
}

// ---------------------------------------------------------------------------
extern "C" void kernel_launch(void* const* d_in, const int* in_sizes, int n_in,
                              void* d_out, int out_size)
{
    const float* x      = (const float*)d_in[0];
    const float* w_in   = (const float*)d_in[1];
    const float* b_in   = (const float*)d_in[2];
    const float* w_dil  = (const float*)d_in[3];
    const float* b_dil  = (const float*)d_in[4];
    const float* w_res  = (const float*)d_in[5];
    const float* b_res  = (const float*)d_in[6];
    const float* w_skip = (const float*)d_in[7];
    const float* b_skip = (const float*)d_in[8];
    const float* w_out1 = (const float*)d_in[9];
    const float* b_out1 = (const float*)d_in[10];
    const float* w_out2 = (const float*)d_in[11];
    const float* b_out2 = (const float*)d_in[12];
    const float* w_fc1  = (const float*)d_in[13];
    const float* b_fc1  = (const float*)d_in[14];
    const float* w_fc2  = (const float*)d_in[15];
    const float* b_fc2  = (const float*)d_in[16];
    const float* w_fc3  = (const float*)d_in[17];
    const float* b_fc3  = (const float*)d_in[18];
    float* out = (float*)d_out;

    int* flags;
    cudaGetSymbolAddress((void**)&flags, g_flags);

    const int BLOCK_SMEM = (2 * 128 * PX + 2 * 128 * PW + 8 * 132) * 4;  // 110,720 B
    cudaFuncSetAttribute(mega_kernel, cudaFuncAttributeMaxDynamicSharedMemorySize, BLOCK_SMEM);

    cudaMemsetAsync(flags, 0, (NBLK + 1) * BB * 32 * sizeof(int));
    split_kernel<<<(NBLK * 14336 + 16384 + 255) / 256, 256>>>(w_dil, w_res, w_skip, w_out1, w_out2);

    mega_kernel<<<(NBLK + 1) * 2048 + BB, 256, BLOCK_SMEM>>>(
        x, w_in, b_in, b_dil, b_res, b_skip, b_out1, b_out2,
        w_fc1, b_fc1, w_fc2, b_fc2, w_fc3, b_fc3, out);
}